// round 1
// baseline (speedup 1.0000x reference)
#include <cuda_runtime.h>
#include <math.h>

#define BDIM 2
#define LDIM 2048
#define EDIM 1024
#define HDIM 16
#define DDIM 64
#define MDIM (BDIM * LDIM)   // 4096

// Scratch (device globals; no allocation allowed)
__device__ float g_q[BDIM * HDIM * LDIM * DDIM];    // [B,H,L,D]
__device__ float g_k[BDIM * HDIM * LDIM * DDIM];
__device__ float g_v[BDIM * HDIM * LDIM * DDIM];
__device__ float g_ctx[BDIM * LDIM * EDIM];         // [B,L,E]

// ---------------------------------------------------------------------------
// NT SGEMM: C[m,n] = (sum_k A[m,k] * W[n,k] + bias[n]) * alpha
// A: [M,K] row-major, W: [N,K] row-major. M=4096, N=K=1024.
// mapQKV=1 -> scatter to [B,H,L,D]; mapQKV=0 -> row-major [M,N].
// 128x128 tile, BK=8, 256 threads, 8x8 microtile.
// ---------------------------------------------------------------------------
__global__ __launch_bounds__(256)
void sgemm_nt(const float* __restrict__ A, const float* __restrict__ W,
              const float* __restrict__ bias, float alpha,
              float* __restrict__ out, int mapQKV)
{
    const int K = EDIM;
    __shared__ float As[8][128];
    __shared__ float Bs[8][128];

    const int bm = blockIdx.y * 128;
    const int bn = blockIdx.x * 128;
    const int tid = threadIdx.x;
    const int tx = tid & 15;
    const int ty = tid >> 4;
    const int lrow = tid >> 1;          // 0..127
    const int lcol = (tid & 1) * 4;     // 0 or 4

    const float* Ap = A + (size_t)(bm + lrow) * K + lcol;
    const float* Bp = W + (size_t)(bn + lrow) * K + lcol;

    float acc[8][8];
#pragma unroll
    for (int i = 0; i < 8; i++)
#pragma unroll
        for (int j = 0; j < 8; j++) acc[i][j] = 0.f;

    for (int k0 = 0; k0 < K; k0 += 8) {
        float4 av = *(const float4*)(Ap + k0);
        float4 bv = *(const float4*)(Bp + k0);
        __syncthreads();
        As[lcol + 0][lrow] = av.x; As[lcol + 1][lrow] = av.y;
        As[lcol + 2][lrow] = av.z; As[lcol + 3][lrow] = av.w;
        Bs[lcol + 0][lrow] = bv.x; Bs[lcol + 1][lrow] = bv.y;
        Bs[lcol + 2][lrow] = bv.z; Bs[lcol + 3][lrow] = bv.w;
        __syncthreads();
#pragma unroll
        for (int kk = 0; kk < 8; kk++) {
            float4 a0 = *(const float4*)&As[kk][ty * 8];
            float4 a1 = *(const float4*)&As[kk][ty * 8 + 4];
            float4 b0 = *(const float4*)&Bs[kk][tx * 8];
            float4 b1 = *(const float4*)&Bs[kk][tx * 8 + 4];
            float a[8] = {a0.x, a0.y, a0.z, a0.w, a1.x, a1.y, a1.z, a1.w};
            float b[8] = {b0.x, b0.y, b0.z, b0.w, b1.x, b1.y, b1.z, b1.w};
#pragma unroll
            for (int i = 0; i < 8; i++)
#pragma unroll
                for (int j = 0; j < 8; j++)
                    acc[i][j] = fmaf(a[i], b[j], acc[i][j]);
        }
    }

#pragma unroll
    for (int i = 0; i < 8; i++) {
        const int row = bm + ty * 8 + i;
        const int b = row >> 11;           // /L (L=2048)
        const int l = row & (LDIM - 1);
#pragma unroll
        for (int j = 0; j < 8; j++) {
            const int col = bn + tx * 8 + j;
            float v = acc[i][j];
            if (bias) v += bias[col];
            v *= alpha;
            if (mapQKV) {
                const int h = col >> 6;    // /D
                const int d = col & (DDIM - 1);
                out[(((size_t)b * HDIM + h) * LDIM + l) * DDIM + d] = v;
            } else {
                out[(size_t)row * EDIM + col] = v;
            }
        }
    }
}

// ---------------------------------------------------------------------------
// Flash-style causal attention, fp32.
// Block = (b,h, 128 queries), 128 threads, 1 query/thread (Q in regs).
// K/V tiles 64x64 in smem. Invalid queries (q >= seq_len) -> uniform 1/L
// weights over ALL keys (matches reference mask semantics exactly).
// ---------------------------------------------------------------------------
__global__ __launch_bounds__(128)
void attn_kernel(const int* __restrict__ seq_len, float* __restrict__ ctx)
{
    const int bh = blockIdx.y;          // 0..31
    const int b = bh >> 4;              // /H
    const int h = bh & (HDIM - 1);
    const int q0 = blockIdx.x * 128;
    const int tid = threadIdx.x;
    const int qi = q0 + tid;
    const int sl = seq_len[b];

    const float* qb = g_q + (size_t)bh * LDIM * DDIM;
    const float* kb = g_k + (size_t)bh * LDIM * DDIM;
    const float* vb = g_v + (size_t)bh * LDIM * DDIM;

    float qr[DDIM];
#pragma unroll
    for (int d = 0; d < DDIM; d += 4) {
        float4 t = *(const float4*)(qb + (size_t)qi * DDIM + d);
        qr[d] = t.x; qr[d + 1] = t.y; qr[d + 2] = t.z; qr[d + 3] = t.w;
    }

    const bool valid = qi < sl;
    float m = -3.4e38f, lsum = 0.f;
    float acc[DDIM];
#pragma unroll
    for (int d = 0; d < DDIM; d++) acc[d] = 0.f;

    __shared__ float ks[64][DDIM];
    __shared__ float vs[64][DDIM];

    const bool anyInvalid = (q0 + 127 >= sl);
    const int lastKey = anyInvalid ? (LDIM - 1) : (q0 + 127);
    const int ntiles = (lastKey >> 6) + 1;

    for (int t = 0; t < ntiles; t++) {
        const int kbase = t << 6;
        __syncthreads();
        const float4* ksrc = (const float4*)(kb + (size_t)kbase * DDIM);
        const float4* vsrc = (const float4*)(vb + (size_t)kbase * DDIM);
#pragma unroll
        for (int it = 0; it < 8; it++) {
            const int i = tid + it * 128;     // 1024 float4 per tile
            ((float4*)ks)[i] = ksrc[i];
            ((float4*)vs)[i] = vsrc[i];
        }
        __syncthreads();

        if (valid) {
            int jmax = qi - kbase;
            if (jmax > 63) jmax = 63;
            for (int j = 0; j <= jmax; j++) {
                float s = 0.f;
#pragma unroll
                for (int d = 0; d < DDIM; d++) s = fmaf(qr[d], ks[j][d], s);
                if (s > m) {                 // rare (~ln n per row)
                    const float sc = __expf(m - s);
                    lsum *= sc;
#pragma unroll
                    for (int d = 0; d < DDIM; d++) acc[d] *= sc;
                    m = s;
                }
                const float p = __expf(s - m);
                lsum += p;
#pragma unroll
                for (int d = 0; d < DDIM; d++)
                    acc[d] = fmaf(p, vs[j][d], acc[d]);
            }
        } else {
            for (int j = 0; j < 64; j++) {
#pragma unroll
                for (int d = 0; d < DDIM; d++) acc[d] += vs[j][d];
            }
            lsum += 64.f;
        }
    }

    const float inv = 1.f / lsum;
    float* op = ctx + (((size_t)b * LDIM + qi) * HDIM + h) * DDIM;
#pragma unroll
    for (int d = 0; d < DDIM; d += 4) {
        float4 t;
        t.x = acc[d] * inv; t.y = acc[d + 1] * inv;
        t.z = acc[d + 2] * inv; t.w = acc[d + 3] * inv;
        *(float4*)(op + d) = t;
    }
}

// ---------------------------------------------------------------------------
extern "C" void kernel_launch(void* const* d_in, const int* in_sizes, int n_in,
                              void* d_out, int out_size)
{
    const float* hs = (const float*)d_in[0];
    const int* sl   = (const int*)d_in[1];
    const float* Wq = (const float*)d_in[2];
    const float* bq = (const float*)d_in[3];
    const float* Wk = (const float*)d_in[4];
    const float* Wv = (const float*)d_in[5];
    const float* bv = (const float*)d_in[6];
    const float* Wo = (const float*)d_in[7];
    const float* bo = (const float*)d_in[8];
    float* out = (float*)d_out;

    float *q, *k, *v, *ctx;
    cudaGetSymbolAddress((void**)&q, g_q);
    cudaGetSymbolAddress((void**)&k, g_k);
    cudaGetSymbolAddress((void**)&v, g_v);
    cudaGetSymbolAddress((void**)&ctx, g_ctx);

    dim3 gg(EDIM / 128, MDIM / 128);   // (8, 32)
    const float scaling = 0.125f;       // D^-0.5 = 64^-0.5

    sgemm_nt<<<gg, 256>>>(hs, Wq, bq, scaling, q, 1);
    sgemm_nt<<<gg, 256>>>(hs, Wk, nullptr, 1.0f, k, 1);
    sgemm_nt<<<gg, 256>>>(hs, Wv, bv, 1.0f, v, 1);

    dim3 ga(LDIM / 128, BDIM * HDIM);  // (16, 32)
    attn_kernel<<<ga, 128>>>(sl, ctx);

    sgemm_nt<<<gg, 256>>>(ctx, Wo, bo, 1.0f, out, 0);
}

// round 3
// speedup vs baseline: 1.5478x; 1.5478x over previous
#include <cuda_runtime.h>
#include <cuda_bf16.h>
#include <cstdint>
#include <math.h>

typedef unsigned int u32;

#define BDIM 2
#define LDIM 2048
#define EDIM 1024
#define HDIM 16
#define DDIM 64
#define MDIM (BDIM * LDIM)   // 4096

// ---------------- scratch (device globals; allocation is forbidden) --------
__device__ float g_q[BDIM * HDIM * LDIM * DDIM];    // [B,H,L,D]
__device__ float g_k[BDIM * HDIM * LDIM * DDIM];
__device__ float g_v[BDIM * HDIM * LDIM * DDIM];
__device__ float g_ctx[BDIM * LDIM * EDIM];         // [B,L,E]

__device__ __nv_bfloat16 g_hs_h[MDIM * EDIM];
__device__ __nv_bfloat16 g_hs_l[MDIM * EDIM];
__device__ __nv_bfloat16 g_ctx_h[MDIM * EDIM];
__device__ __nv_bfloat16 g_ctx_l[MDIM * EDIM];
__device__ __nv_bfloat16 g_w_h[4 * EDIM * EDIM];    // Wq,Wk,Wv,Wo
__device__ __nv_bfloat16 g_w_l[4 * EDIM * EDIM];

// ---------------------------------------------------------------------------
// Split fp32 -> bf16 hi + bf16 lo (residual)
// ---------------------------------------------------------------------------
__global__ __launch_bounds__(256)
void split_f32(const float* __restrict__ x, __nv_bfloat16* __restrict__ hi,
               __nv_bfloat16* __restrict__ lo, int n4)
{
    int i = blockIdx.x * blockDim.x + threadIdx.x;
    if (i >= n4) return;
    float4 v = ((const float4*)x)[i];
    __nv_bfloat16 h0 = __float2bfloat16(v.x);
    __nv_bfloat16 h1 = __float2bfloat16(v.y);
    __nv_bfloat16 h2 = __float2bfloat16(v.z);
    __nv_bfloat16 h3 = __float2bfloat16(v.w);
    __nv_bfloat16 l0 = __float2bfloat16(v.x - __bfloat162float(h0));
    __nv_bfloat16 l1 = __float2bfloat16(v.y - __bfloat162float(h1));
    __nv_bfloat16 l2 = __float2bfloat16(v.z - __bfloat162float(h2));
    __nv_bfloat16 l3 = __float2bfloat16(v.w - __bfloat162float(h3));
    __nv_bfloat162 hp0; hp0.x = h0; hp0.y = h1;
    __nv_bfloat162 hp1; hp1.x = h2; hp1.y = h3;
    __nv_bfloat162 lp0; lp0.x = l0; lp0.y = l1;
    __nv_bfloat162 lp1; lp1.x = l2; lp1.y = l3;
    uint2 hv, lv;
    hv.x = *(u32*)&hp0; hv.y = *(u32*)&hp1;
    lv.x = *(u32*)&lp0; lv.y = *(u32*)&lp1;
    ((uint2*)hi)[i] = hv;
    ((uint2*)lo)[i] = lv;
}

// ---------------------------------------------------------------------------
// PTX helpers (inline functions, no macros)
// ---------------------------------------------------------------------------
__device__ __forceinline__ void cpasync16(u32 dst, const void* src) {
    asm volatile("cp.async.cg.shared.global [%0], [%1], 16;\n" :: "r"(dst), "l"(src));
}
__device__ __forceinline__ void cp_commit() {
    asm volatile("cp.async.commit_group;\n");
}
__device__ __forceinline__ void cp_wait1() {
    asm volatile("cp.async.wait_group 1;\n");
}
__device__ __forceinline__ void cp_wait0() {
    asm volatile("cp.async.wait_group 0;\n");
}
__device__ __forceinline__ void ldsm4(u32& r0, u32& r1, u32& r2, u32& r3, u32 addr) {
    asm volatile("ldmatrix.sync.aligned.m8n8.x4.shared.b16 {%0,%1,%2,%3}, [%4];"
        : "=r"(r0), "=r"(r1), "=r"(r2), "=r"(r3) : "r"(addr));
}
__device__ __forceinline__ void mma16816(float* acc, const u32* a, const u32* b) {
    asm volatile("mma.sync.aligned.m16n8k16.row.col.f32.bf16.bf16.f32 "
        "{%0,%1,%2,%3}, {%4,%5,%6,%7}, {%8,%9}, {%0,%1,%2,%3};"
        : "+f"(acc[0]), "+f"(acc[1]), "+f"(acc[2]), "+f"(acc[3])
        : "r"(a[0]), "r"(a[1]), "r"(a[2]), "r"(a[3]), "r"(b[0]), "r"(b[1]));
}

// ---------------------------------------------------------------------------
// bf16x3 tensor-core NT GEMM: C[m,n] = (sum_k A[m,k]*W[n,k] + bias[n]) * alpha
// 128x128x32 block tile, 256 thr, 8 warps (4 M x 2 N), warp tile 32x64,
// mma.m16n8k16, cp.async double-buffered.
// ---------------------------------------------------------------------------
#define BK 32
#define SSTR 40                          // smem row stride in bf16 (80 B)
#define ARR_B (128 * SSTR * 2)           // 10240 bytes per array
#define STAGE_B (4 * ARR_B)              // 40960 bytes per stage

__device__ __forceinline__ void issue_stage(
    u32 sb, int k0, int ldc0, u32 sOff,
    const __nv_bfloat16* Ah, const __nv_bfloat16* Al,
    const __nv_bfloat16* Bh, const __nv_bfloat16* Bl,
    size_t gArow, size_t gBrow)
{
#pragma unroll
    for (int c = 0; c < 2; c++) {
        int col = k0 + (ldc0 + c) * 8;
        u32 so = sOff + (u32)(ldc0 + c) * 16;
        cpasync16(sb + 0u * ARR_B + so, Ah + gArow + col);
        cpasync16(sb + 1u * ARR_B + so, Al + gArow + col);
        cpasync16(sb + 2u * ARR_B + so, Bh + gBrow + col);
        cpasync16(sb + 3u * ARR_B + so, Bl + gBrow + col);
    }
    cp_commit();
}

extern "C" __global__ __launch_bounds__(256, 1)
void gemm_bf16x3(const __nv_bfloat16* __restrict__ Ahg, const __nv_bfloat16* __restrict__ Alg,
                 const __nv_bfloat16* __restrict__ Bhg, const __nv_bfloat16* __restrict__ Blg,
                 const float* __restrict__ bias, float alpha,
                 float* __restrict__ out, int mapQKV)
{
    extern __shared__ __align__(16) char dynsmem[];
    const u32 sbase = (u32)__cvta_generic_to_shared(dynsmem);
    const int K = EDIM;
    const int bm = blockIdx.y * 128;
    const int bn = blockIdx.x * 128;
    const int tid = threadIdx.x;
    const int lane = tid & 31;
    const int wid = tid >> 5;
    const int wm = (wid & 3) * 32;       // warp M offset
    const int wn = (wid >> 2) * 64;      // warp N offset

    const int ldrow = tid >> 1;
    const int ldc0 = (tid & 1) * 2;
    const size_t gArow = (size_t)(bm + ldrow) * K;
    const size_t gBrow = (size_t)(bn + ldrow) * K;
    const u32 sOff = (u32)(ldrow * SSTR * 2);

    float acc[2][8][4];
#pragma unroll
    for (int i = 0; i < 2; i++)
#pragma unroll
        for (int j = 0; j < 8; j++)
#pragma unroll
            for (int c = 0; c < 4; c++) acc[i][j][c] = 0.f;

    const int lrowA = wm + (lane & 15);
    const int lcol = (lane >> 4) * 8;
    const int lrowB = wn + (lane & 15);

    const int NIT = K / BK;              // 32
    issue_stage(sbase, 0, ldc0, sOff, Ahg, Alg, Bhg, Blg, gArow, gBrow);

    for (int it = 0; it < NIT; it++) {
        if (it + 1 < NIT) {
            issue_stage(sbase + (u32)((it + 1) & 1) * STAGE_B, (it + 1) * BK,
                        ldc0, sOff, Ahg, Alg, Bhg, Blg, gArow, gBrow);
            cp_wait1();
        } else {
            cp_wait0();
        }
        __syncthreads();

        const u32 sb = sbase + (u32)(it & 1) * STAGE_B;
#pragma unroll
        for (int ks = 0; ks < 2; ks++) {
            const int kb = ks * 16;
            u32 af[2][2][4];             // [split][mt][4]
            u32 bfr[2][8][2];            // [split][nt][2]
#pragma unroll
            for (int mt = 0; mt < 2; mt++) {
                u32 ad = sb + (u32)((lrowA + mt * 16) * SSTR + kb + lcol) * 2;
                ldsm4(af[0][mt][0], af[0][mt][1], af[0][mt][2], af[0][mt][3], ad + 0u * ARR_B);
                ldsm4(af[1][mt][0], af[1][mt][1], af[1][mt][2], af[1][mt][3], ad + 1u * ARR_B);
            }
#pragma unroll
            for (int p = 0; p < 4; p++) {
                u32 bd = sb + (u32)((lrowB + p * 16) * SSTR + kb + lcol) * 2;
                u32 t0, t1, t2, t3;
                ldsm4(t0, t1, t2, t3, bd + 2u * ARR_B);
                bfr[0][2 * p][0] = t0; bfr[0][2 * p][1] = t2;
                bfr[0][2 * p + 1][0] = t1; bfr[0][2 * p + 1][1] = t3;
                ldsm4(t0, t1, t2, t3, bd + 3u * ARR_B);
                bfr[1][2 * p][0] = t0; bfr[1][2 * p][1] = t2;
                bfr[1][2 * p + 1][0] = t1; bfr[1][2 * p + 1][1] = t3;
            }
#pragma unroll
            for (int mt = 0; mt < 2; mt++)
#pragma unroll
                for (int nt = 0; nt < 8; nt++) {
                    mma16816(acc[mt][nt], af[0][mt], bfr[0][nt]);   // hi*hi
                    mma16816(acc[mt][nt], af[0][mt], bfr[1][nt]);   // hi*lo
                    mma16816(acc[mt][nt], af[1][mt], bfr[0][nt]);   // lo*hi
                }
        }
        __syncthreads();
    }

    // ----- epilogue -----
#pragma unroll
    for (int mt = 0; mt < 2; mt++) {
        const int row0 = bm + wm + mt * 16 + (lane >> 2);
#pragma unroll
        for (int nt = 0; nt < 8; nt++) {
            const int col0 = bn + wn + nt * 8 + (lane & 3) * 2;
#pragma unroll
            for (int c = 0; c < 4; c++) {
                const int row = row0 + (c >> 1) * 8;
                const int col = col0 + (c & 1);
                float v = acc[mt][nt][c];
                if (bias) v += bias[col];
                v *= alpha;
                const int b = row >> 11;
                const int l = row & (LDIM - 1);
                if (mapQKV) {
                    const int h = col >> 6;
                    const int d = col & (DDIM - 1);
                    out[(((size_t)b * HDIM + h) * LDIM + l) * DDIM + d] = v;
                } else {
                    out[(size_t)row * EDIM + col] = v;
                }
            }
        }
    }
}

// ---------------------------------------------------------------------------
// Flash-style causal attention, fp32 (unchanged — round-1 validated).
// ---------------------------------------------------------------------------
__global__ __launch_bounds__(128)
void attn_kernel(const int* __restrict__ seq_len, float* __restrict__ ctx)
{
    const int bh = blockIdx.y;
    const int b = bh >> 4;
    const int h = bh & (HDIM - 1);
    const int q0 = blockIdx.x * 128;
    const int tid = threadIdx.x;
    const int qi = q0 + tid;
    const int sl = seq_len[b];

    const float* qb = g_q + (size_t)bh * LDIM * DDIM;
    const float* kb = g_k + (size_t)bh * LDIM * DDIM;
    const float* vb = g_v + (size_t)bh * LDIM * DDIM;

    float qr[DDIM];
#pragma unroll
    for (int d = 0; d < DDIM; d += 4) {
        float4 t = *(const float4*)(qb + (size_t)qi * DDIM + d);
        qr[d] = t.x; qr[d + 1] = t.y; qr[d + 2] = t.z; qr[d + 3] = t.w;
    }

    const bool valid = qi < sl;
    float m = -3.4e38f, lsum = 0.f;
    float acc[DDIM];
#pragma unroll
    for (int d = 0; d < DDIM; d++) acc[d] = 0.f;

    __shared__ float ks[64][DDIM];
    __shared__ float vs[64][DDIM];

    const bool anyInvalid = (q0 + 127 >= sl);
    const int lastKey = anyInvalid ? (LDIM - 1) : (q0 + 127);
    const int ntiles = (lastKey >> 6) + 1;

    for (int t = 0; t < ntiles; t++) {
        const int kbase = t << 6;
        __syncthreads();
        const float4* ksrc = (const float4*)(kb + (size_t)kbase * DDIM);
        const float4* vsrc = (const float4*)(vb + (size_t)kbase * DDIM);
#pragma unroll
        for (int it = 0; it < 8; it++) {
            const int i = tid + it * 128;
            ((float4*)ks)[i] = ksrc[i];
            ((float4*)vs)[i] = vsrc[i];
        }
        __syncthreads();

        if (valid) {
            int jmax = qi - kbase;
            if (jmax > 63) jmax = 63;
            for (int j = 0; j <= jmax; j++) {
                float s = 0.f;
#pragma unroll
                for (int d = 0; d < DDIM; d++) s = fmaf(qr[d], ks[j][d], s);
                if (s > m) {
                    const float sc = __expf(m - s);
                    lsum *= sc;
#pragma unroll
                    for (int d = 0; d < DDIM; d++) acc[d] *= sc;
                    m = s;
                }
                const float p = __expf(s - m);
                lsum += p;
#pragma unroll
                for (int d = 0; d < DDIM; d++)
                    acc[d] = fmaf(p, vs[j][d], acc[d]);
            }
        } else {
            for (int j = 0; j < 64; j++) {
#pragma unroll
                for (int d = 0; d < DDIM; d++) acc[d] += vs[j][d];
            }
            lsum += 64.f;
        }
    }

    const float inv = 1.f / lsum;
    float* op = ctx + (((size_t)b * LDIM + qi) * HDIM + h) * DDIM;
#pragma unroll
    for (int d = 0; d < DDIM; d += 4) {
        float4 t;
        t.x = acc[d] * inv; t.y = acc[d + 1] * inv;
        t.z = acc[d + 2] * inv; t.w = acc[d + 3] * inv;
        *(float4*)(op + d) = t;
    }
}

// ---------------------------------------------------------------------------
extern "C" void kernel_launch(void* const* d_in, const int* in_sizes, int n_in,
                              void* d_out, int out_size)
{
    const float* hs = (const float*)d_in[0];
    const int* sl   = (const int*)d_in[1];
    const float* Wq = (const float*)d_in[2];
    const float* bq = (const float*)d_in[3];
    const float* Wk = (const float*)d_in[4];
    const float* Wv = (const float*)d_in[5];
    const float* bv = (const float*)d_in[6];
    const float* Wo = (const float*)d_in[7];
    const float* bo = (const float*)d_in[8];
    float* out = (float*)d_out;

    float *q, *k, *v, *ctx;
    __nv_bfloat16 *hsh, *hsl, *ctxh, *ctxl, *wh, *wl;
    cudaGetSymbolAddress((void**)&q, g_q);
    cudaGetSymbolAddress((void**)&k, g_k);
    cudaGetSymbolAddress((void**)&v, g_v);
    cudaGetSymbolAddress((void**)&ctx, g_ctx);
    cudaGetSymbolAddress((void**)&hsh, g_hs_h);
    cudaGetSymbolAddress((void**)&hsl, g_hs_l);
    cudaGetSymbolAddress((void**)&ctxh, g_ctx_h);
    cudaGetSymbolAddress((void**)&ctxl, g_ctx_l);
    cudaGetSymbolAddress((void**)&wh, g_w_h);
    cudaGetSymbolAddress((void**)&wl, g_w_l);

    cudaFuncSetAttribute(gemm_bf16x3, cudaFuncAttributeMaxDynamicSharedMemorySize,
                         2 * STAGE_B);

    const int WSZ = EDIM * EDIM;
    split_f32<<<(MDIM * EDIM / 4 + 255) / 256, 256>>>(hs, hsh, hsl, MDIM * EDIM / 4);
    split_f32<<<(WSZ / 4 + 255) / 256, 256>>>(Wq, wh + 0 * WSZ, wl + 0 * WSZ, WSZ / 4);
    split_f32<<<(WSZ / 4 + 255) / 256, 256>>>(Wk, wh + 1 * WSZ, wl + 1 * WSZ, WSZ / 4);
    split_f32<<<(WSZ / 4 + 255) / 256, 256>>>(Wv, wh + 2 * WSZ, wl + 2 * WSZ, WSZ / 4);
    split_f32<<<(WSZ / 4 + 255) / 256, 256>>>(Wo, wh + 3 * WSZ, wl + 3 * WSZ, WSZ / 4);

    dim3 gg(EDIM / 128, MDIM / 128);    // (8, 32)
    const int dsm = 2 * STAGE_B;
    gemm_bf16x3<<<gg, 256, dsm>>>(hsh, hsl, wh + 0 * WSZ, wl + 0 * WSZ, bq, 0.125f, q, 1);
    gemm_bf16x3<<<gg, 256, dsm>>>(hsh, hsl, wh + 1 * WSZ, wl + 1 * WSZ, nullptr, 1.0f, k, 1);
    gemm_bf16x3<<<gg, 256, dsm>>>(hsh, hsl, wh + 2 * WSZ, wl + 2 * WSZ, bv, 1.0f, v, 1);

    dim3 ga(LDIM / 128, BDIM * HDIM);   // (16, 32)
    attn_kernel<<<ga, 128>>>(sl, ctx);

    split_f32<<<(MDIM * EDIM / 4 + 255) / 256, 256>>>(ctx, ctxh, ctxl, MDIM * EDIM / 4);
    gemm_bf16x3<<<gg, 256, dsm>>>(ctxh, ctxl, wh + 3 * WSZ, wl + 3 * WSZ, bo, 1.0f, out, 0);
}

// round 4
// speedup vs baseline: 2.6589x; 1.7179x over previous
#include <cuda_runtime.h>
#include <cuda_bf16.h>
#include <cstdint>
#include <math.h>

typedef unsigned int u32;

#define BDIM 2
#define LDIM 2048
#define EDIM 1024
#define HDIM 16
#define DDIM 64
#define MDIM (BDIM * LDIM)   // 4096

// ---------------- scratch (device globals; allocation is forbidden) --------
__device__ __nv_bfloat16 g_qh[BDIM * HDIM * LDIM * DDIM];   // [B,H,L,D]
__device__ __nv_bfloat16 g_ql[BDIM * HDIM * LDIM * DDIM];
__device__ __nv_bfloat16 g_kh[BDIM * HDIM * LDIM * DDIM];
__device__ __nv_bfloat16 g_kl[BDIM * HDIM * LDIM * DDIM];
__device__ __nv_bfloat16 g_vh[BDIM * HDIM * LDIM * DDIM];
__device__ __nv_bfloat16 g_vl[BDIM * HDIM * LDIM * DDIM];
__device__ __nv_bfloat16 g_hs_h[MDIM * EDIM];
__device__ __nv_bfloat16 g_hs_l[MDIM * EDIM];
__device__ __nv_bfloat16 g_ctx_h[MDIM * EDIM];              // [B,L,E]
__device__ __nv_bfloat16 g_ctx_l[MDIM * EDIM];
__device__ __nv_bfloat16 g_w_h[4 * EDIM * EDIM];            // Wq,Wk,Wv,Wo
__device__ __nv_bfloat16 g_w_l[4 * EDIM * EDIM];

// ---------------------------------------------------------------------------
// helpers
// ---------------------------------------------------------------------------
__device__ __forceinline__ u32 packbf(float lo, float hi) {
    u32 d;
    asm("cvt.rn.bf16x2.f32 %0, %1, %2;" : "=r"(d) : "f"(hi), "f"(lo));
    return d;
}
__device__ __forceinline__ float unlo(u32 u) { return __uint_as_float(u << 16); }
__device__ __forceinline__ float unhi(u32 u) { return __uint_as_float(u & 0xffff0000u); }

__device__ __forceinline__ void cpasync16(u32 dst, const void* src) {
    asm volatile("cp.async.cg.shared.global [%0], [%1], 16;\n" :: "r"(dst), "l"(src));
}
__device__ __forceinline__ void cp_commit() { asm volatile("cp.async.commit_group;\n"); }
__device__ __forceinline__ void cp_wait1() { asm volatile("cp.async.wait_group 1;\n"); }
__device__ __forceinline__ void cp_wait0() { asm volatile("cp.async.wait_group 0;\n"); }

__device__ __forceinline__ void ldsm4(u32& r0, u32& r1, u32& r2, u32& r3, u32 addr) {
    asm volatile("ldmatrix.sync.aligned.m8n8.x4.shared.b16 {%0,%1,%2,%3}, [%4];"
        : "=r"(r0), "=r"(r1), "=r"(r2), "=r"(r3) : "r"(addr));
}
__device__ __forceinline__ void ldsm4t(u32& r0, u32& r1, u32& r2, u32& r3, u32 addr) {
    asm volatile("ldmatrix.sync.aligned.m8n8.x4.trans.shared.b16 {%0,%1,%2,%3}, [%4];"
        : "=r"(r0), "=r"(r1), "=r"(r2), "=r"(r3) : "r"(addr));
}
__device__ __forceinline__ void mma16816(float* acc, const u32* a, const u32* b) {
    asm volatile("mma.sync.aligned.m16n8k16.row.col.f32.bf16.bf16.f32 "
        "{%0,%1,%2,%3}, {%4,%5,%6,%7}, {%8,%9}, {%0,%1,%2,%3};"
        : "+f"(acc[0]), "+f"(acc[1]), "+f"(acc[2]), "+f"(acc[3])
        : "r"(a[0]), "r"(a[1]), "r"(a[2]), "r"(a[3]), "r"(b[0]), "r"(b[1]));
}

// ---------------------------------------------------------------------------
// Split fp32 -> bf16 hi + bf16 lo
// ---------------------------------------------------------------------------
__global__ __launch_bounds__(256)
void split_f32(const float* __restrict__ x, __nv_bfloat16* __restrict__ hi,
               __nv_bfloat16* __restrict__ lo, int n4)
{
    int i = blockIdx.x * blockDim.x + threadIdx.x;
    if (i >= n4) return;
    float4 v = ((const float4*)x)[i];
    u32 h0 = packbf(v.x, v.y), h1 = packbf(v.z, v.w);
    u32 l0 = packbf(v.x - unlo(h0), v.y - unhi(h0));
    u32 l1 = packbf(v.z - unlo(h1), v.w - unhi(h1));
    uint2 hv; hv.x = h0; hv.y = h1;
    uint2 lv; lv.x = l0; lv.y = l1;
    ((uint2*)hi)[i] = hv;
    ((uint2*)lo)[i] = lv;
}

// ---------------------------------------------------------------------------
// bf16x3 tensor-core NT GEMM (round-3 validated core; epilogue now emits
// bf16 hi/lo scatter for QKV mode, fp32 for final mode)
// ---------------------------------------------------------------------------
#define BK 32
#define SSTR 40
#define ARR_B (128 * SSTR * 2)
#define STAGE_B (4 * ARR_B)

__device__ __forceinline__ void issue_stage(
    u32 sb, int k0, int ldc0, u32 sOff,
    const __nv_bfloat16* Ah, const __nv_bfloat16* Al,
    const __nv_bfloat16* Bh, const __nv_bfloat16* Bl,
    size_t gArow, size_t gBrow)
{
#pragma unroll
    for (int c = 0; c < 2; c++) {
        int col = k0 + (ldc0 + c) * 8;
        u32 so = sOff + (u32)(ldc0 + c) * 16;
        cpasync16(sb + 0u * ARR_B + so, Ah + gArow + col);
        cpasync16(sb + 1u * ARR_B + so, Al + gArow + col);
        cpasync16(sb + 2u * ARR_B + so, Bh + gBrow + col);
        cpasync16(sb + 3u * ARR_B + so, Bl + gBrow + col);
    }
    cp_commit();
}

extern "C" __global__ __launch_bounds__(256, 1)
void gemm_bf16x3(const __nv_bfloat16* __restrict__ Ahg, const __nv_bfloat16* __restrict__ Alg,
                 const __nv_bfloat16* __restrict__ Bhg, const __nv_bfloat16* __restrict__ Blg,
                 const float* __restrict__ bias, float alpha,
                 float* __restrict__ out,
                 u32* __restrict__ outh, u32* __restrict__ outl, int mapQKV)
{
    extern __shared__ __align__(16) char dynsmem[];
    const u32 sbase = (u32)__cvta_generic_to_shared(dynsmem);
    const int K = EDIM;
    const int bm = blockIdx.y * 128;
    const int bn = blockIdx.x * 128;
    const int tid = threadIdx.x;
    const int lane = tid & 31;
    const int wid = tid >> 5;
    const int wm = (wid & 3) * 32;
    const int wn = (wid >> 2) * 64;

    const int ldrow = tid >> 1;
    const int ldc0 = (tid & 1) * 2;
    const size_t gArow = (size_t)(bm + ldrow) * K;
    const size_t gBrow = (size_t)(bn + ldrow) * K;
    const u32 sOff = (u32)(ldrow * SSTR * 2);

    float acc[2][8][4];
#pragma unroll
    for (int i = 0; i < 2; i++)
#pragma unroll
        for (int j = 0; j < 8; j++)
#pragma unroll
            for (int c = 0; c < 4; c++) acc[i][j][c] = 0.f;

    const int lrowA = wm + (lane & 15);
    const int lcol = (lane >> 4) * 8;
    const int lrowB = wn + (lane & 15);

    const int NIT = K / BK;
    issue_stage(sbase, 0, ldc0, sOff, Ahg, Alg, Bhg, Blg, gArow, gBrow);

    for (int it = 0; it < NIT; it++) {
        if (it + 1 < NIT) {
            issue_stage(sbase + (u32)((it + 1) & 1) * STAGE_B, (it + 1) * BK,
                        ldc0, sOff, Ahg, Alg, Bhg, Blg, gArow, gBrow);
            cp_wait1();
        } else {
            cp_wait0();
        }
        __syncthreads();

        const u32 sb = sbase + (u32)(it & 1) * STAGE_B;
#pragma unroll
        for (int ks = 0; ks < 2; ks++) {
            const int kb = ks * 16;
            u32 af[2][2][4];
            u32 bfr[2][8][2];
#pragma unroll
            for (int mt = 0; mt < 2; mt++) {
                u32 ad = sb + (u32)((lrowA + mt * 16) * SSTR + kb + lcol) * 2;
                ldsm4(af[0][mt][0], af[0][mt][1], af[0][mt][2], af[0][mt][3], ad + 0u * ARR_B);
                ldsm4(af[1][mt][0], af[1][mt][1], af[1][mt][2], af[1][mt][3], ad + 1u * ARR_B);
            }
#pragma unroll
            for (int p = 0; p < 4; p++) {
                u32 bd = sb + (u32)((lrowB + p * 16) * SSTR + kb + lcol) * 2;
                u32 t0, t1, t2, t3;
                ldsm4(t0, t1, t2, t3, bd + 2u * ARR_B);
                bfr[0][2 * p][0] = t0; bfr[0][2 * p][1] = t2;
                bfr[0][2 * p + 1][0] = t1; bfr[0][2 * p + 1][1] = t3;
                ldsm4(t0, t1, t2, t3, bd + 3u * ARR_B);
                bfr[1][2 * p][0] = t0; bfr[1][2 * p][1] = t2;
                bfr[1][2 * p + 1][0] = t1; bfr[1][2 * p + 1][1] = t3;
            }
#pragma unroll
            for (int mt = 0; mt < 2; mt++)
#pragma unroll
                for (int nt = 0; nt < 8; nt++) {
                    mma16816(acc[mt][nt], af[0][mt], bfr[0][nt]);
                    mma16816(acc[mt][nt], af[0][mt], bfr[1][nt]);
                    mma16816(acc[mt][nt], af[1][mt], bfr[0][nt]);
                }
        }
        __syncthreads();
    }

    // ----- epilogue -----
#pragma unroll
    for (int mt = 0; mt < 2; mt++) {
#pragma unroll
        for (int nt = 0; nt < 8; nt++) {
#pragma unroll
            for (int r = 0; r < 2; r++) {
                const int row = bm + wm + mt * 16 + (lane >> 2) + r * 8;
                const int col0 = bn + wn + nt * 8 + (lane & 3) * 2;
                float v0 = acc[mt][nt][r * 2 + 0];
                float v1 = acc[mt][nt][r * 2 + 1];
                if (bias) { v0 += bias[col0]; v1 += bias[col0 + 1]; }
                v0 *= alpha; v1 *= alpha;
                const int b = row >> 11;
                const int l = row & (LDIM - 1);
                if (mapQKV) {
                    const int h = col0 >> 6;
                    const int d = col0 & (DDIM - 1);
                    const size_t e = (((size_t)(b * HDIM + h) * LDIM) + l) * DDIM + d;
                    u32 hv = packbf(v0, v1);
                    u32 lv = packbf(v0 - unlo(hv), v1 - unhi(hv));
                    outh[e >> 1] = hv;
                    outl[e >> 1] = lv;
                } else {
                    out[(size_t)row * EDIM + col0] = v0;
                    out[(size_t)row * EDIM + col0 + 1] = v1;
                }
            }
        }
    }
}

// ---------------------------------------------------------------------------
// Tensor-core flash attention (bf16x3 on QK^T and PV, fp32 softmax).
// Block: 128 queries x (b,h). 4 warps, warp = 32 query rows.
// K/V tiles of 64 keys, cp.async double-buffered.
// Invalid rows (q >= seq_len): s=0 over ALL keys -> uniform 1/2048 (ref match).
// ---------------------------------------------------------------------------
#define STR 72
#define QH_OFF 0
#define QL_OFF (128 * STR * 2)          // 18432
#define ST_BASE (2 * (128 * STR * 2))   // 36864
#define KT_B (64 * STR * 2)             // 9216
#define KH_O 0
#define KL_O KT_B
#define VH_O (2 * KT_B)
#define VL_O (3 * KT_B)
#define ST_SZ (4 * KT_B)                // 36864
#define ATT_SMEM (ST_BASE + 2 * ST_SZ)  // 110592

__device__ __forceinline__ void attn_issue_kv(u32 base, int kbase, int tid,
                                              const __nv_bfloat16* khg, const __nv_bfloat16* klg,
                                              const __nv_bfloat16* vhg, const __nv_bfloat16* vlg)
{
    const int row = tid >> 1;
    const int c0 = (tid & 1) * 4;
#pragma unroll
    for (int c = 0; c < 4; c++) {
        const int ch = c0 + c;
        const u32 off = (u32)((row * STR + ch * 8) * 2);
        const size_t src = (size_t)(kbase + row) * DDIM + ch * 8;
        cpasync16(base + KH_O + off, khg + src);
        cpasync16(base + KL_O + off, klg + src);
        cpasync16(base + VH_O + off, vhg + src);
        cpasync16(base + VL_O + off, vlg + src);
    }
}

__global__ __launch_bounds__(128)
void attn_mma(const int* __restrict__ seq_len,
              u32* __restrict__ ctxh, u32* __restrict__ ctxl)
{
    extern __shared__ __align__(16) char sm[];
    const u32 sb = (u32)__cvta_generic_to_shared(sm);
    const int bh = blockIdx.y;
    const int b = bh >> 4;
    const int h = bh & (HDIM - 1);
    const int qt = (int)gridDim.x - 1 - (int)blockIdx.x;   // heavy blocks first
    const int q0 = qt * 128;
    const int tid = threadIdx.x;
    const int lane = tid & 31;
    const int w = tid >> 5;
    const int wm = w * 32;
    const int g = lane >> 2;
    const int qd = lane & 3;
    const int sl = seq_len[b];

    const size_t hoff = (size_t)bh * LDIM * DDIM;
    const __nv_bfloat16* qhg = g_qh + hoff;
    const __nv_bfloat16* qlg = g_ql + hoff;
    const __nv_bfloat16* khg = g_kh + hoff;
    const __nv_bfloat16* klg = g_kl + hoff;
    const __nv_bfloat16* vhg = g_vh + hoff;
    const __nv_bfloat16* vlg = g_vl + hoff;

    // prologue: Q tile + KV tile 0 (one cp.async group)
    {
        const int row = tid;
        const size_t src = (size_t)(q0 + row) * DDIM;
#pragma unroll
        for (int c = 0; c < 8; c++) {
            const u32 off = (u32)((row * STR + c * 8) * 2);
            cpasync16(sb + QH_OFF + off, qhg + src + c * 8);
            cpasync16(sb + QL_OFF + off, qlg + src + c * 8);
        }
    }
    attn_issue_kv(sb + ST_BASE, 0, tid, khg, klg, vhg, vlg);
    cp_commit();

    const bool anyInvalid = (q0 + 127 >= sl);
    const int lastKey = anyInvalid ? (LDIM - 1) : (q0 + 127);
    const int ntiles = (lastKey >> 6) + 1;

    float o[2][8][4];
    float mrow[4], lrow[4];
#pragma unroll
    for (int i = 0; i < 2; i++)
#pragma unroll
        for (int j = 0; j < 8; j++)
#pragma unroll
            for (int c = 0; c < 4; c++) o[i][j][c] = 0.f;
#pragma unroll
    for (int i = 0; i < 4; i++) { mrow[i] = -1e30f; lrow[i] = 0.f; }

    for (int t = 0; t < ntiles; t++) {
        if (t + 1 < ntiles) {
            attn_issue_kv(sb + ST_BASE + (u32)((t + 1) & 1) * ST_SZ, (t + 1) << 6,
                          tid, khg, klg, vhg, vlg);
            cp_commit();
            cp_wait1();
        } else {
            cp_wait0();
        }
        __syncthreads();

        const u32 kb_ = sb + ST_BASE + (u32)(t & 1) * ST_SZ;

        // ----- S = Q K^T (bf16x3) -----
        float s[2][8][4];
#pragma unroll
        for (int i = 0; i < 2; i++)
#pragma unroll
            for (int j = 0; j < 8; j++)
#pragma unroll
                for (int c = 0; c < 4; c++) s[i][j][c] = 0.f;

#pragma unroll
        for (int kf = 0; kf < 4; kf++) {
            u32 aqh[2][4], aql[2][4];
#pragma unroll
            for (int mf = 0; mf < 2; mf++) {
                const u32 ad = (u32)(((wm + mf * 16 + (lane & 15)) * STR
                                      + kf * 16 + (lane >> 4) * 8) * 2);
                ldsm4(aqh[mf][0], aqh[mf][1], aqh[mf][2], aqh[mf][3], sb + QH_OFF + ad);
                ldsm4(aql[mf][0], aql[mf][1], aql[mf][2], aql[mf][3], sb + QL_OFF + ad);
            }
#pragma unroll
            for (int p = 0; p < 4; p++) {
                const u32 kd = (u32)(((p * 16 + (lane & 15)) * STR
                                      + kf * 16 + (lane >> 4) * 8) * 2);
                u32 t0, t1, t2, t3;
                u32 bkh0[2], bkh1[2], bkl0[2], bkl1[2];
                ldsm4(t0, t1, t2, t3, kb_ + KH_O + kd);
                bkh0[0] = t0; bkh0[1] = t2; bkh1[0] = t1; bkh1[1] = t3;
                ldsm4(t0, t1, t2, t3, kb_ + KL_O + kd);
                bkl0[0] = t0; bkl0[1] = t2; bkl1[0] = t1; bkl1[1] = t3;
#pragma unroll
                for (int mf = 0; mf < 2; mf++) {
                    mma16816(s[mf][2 * p], aqh[mf], bkh0);
                    mma16816(s[mf][2 * p], aqh[mf], bkl0);
                    mma16816(s[mf][2 * p], aql[mf], bkh0);
                    mma16816(s[mf][2 * p + 1], aqh[mf], bkh1);
                    mma16816(s[mf][2 * p + 1], aqh[mf], bkl1);
                    mma16816(s[mf][2 * p + 1], aql[mf], bkh1);
                }
            }
        }

        // ----- mask + online softmax -----
        const int kbase = t << 6;
#pragma unroll
        for (int mf = 0; mf < 2; mf++) {
#pragma unroll
            for (int hl = 0; hl < 2; hl++) {
                const int qi = q0 + wm + mf * 16 + g + hl * 8;
                const bool vr = qi < sl;
                const int idx = mf * 2 + hl;
                float mx = -1e30f;
#pragma unroll
                for (int nf = 0; nf < 8; nf++) {
                    const int c0 = kbase + nf * 8 + qd * 2;
                    float s0 = s[mf][nf][hl * 2];
                    float s1 = s[mf][nf][hl * 2 + 1];
                    if (!vr) { s0 = 0.f; s1 = 0.f; }
                    else {
                        if (c0 > qi) s0 = -1e30f;
                        if (c0 + 1 > qi) s1 = -1e30f;
                    }
                    s[mf][nf][hl * 2] = s0;
                    s[mf][nf][hl * 2 + 1] = s1;
                    mx = fmaxf(mx, fmaxf(s0, s1));
                }
                mx = fmaxf(mx, __shfl_xor_sync(0xffffffffu, mx, 1));
                mx = fmaxf(mx, __shfl_xor_sync(0xffffffffu, mx, 2));
                const float mnew = fmaxf(mrow[idx], mx);
                const float sc = __expf(mrow[idx] - mnew);
                mrow[idx] = mnew;
                float ps = 0.f;
#pragma unroll
                for (int nf = 0; nf < 8; nf++) {
                    float p0 = __expf(s[mf][nf][hl * 2] - mnew);
                    float p1 = __expf(s[mf][nf][hl * 2 + 1] - mnew);
                    s[mf][nf][hl * 2] = p0;
                    s[mf][nf][hl * 2 + 1] = p1;
                    ps += p0 + p1;
                    o[mf][nf][hl * 2] *= sc;
                    o[mf][nf][hl * 2 + 1] *= sc;
                }
                ps += __shfl_xor_sync(0xffffffffu, ps, 1);
                ps += __shfl_xor_sync(0xffffffffu, ps, 2);
                lrow[idx] = lrow[idx] * sc + ps;
            }
        }

        // ----- O += P V (bf16x3) -----
#pragma unroll
        for (int kg = 0; kg < 4; kg++) {
            u32 aph[2][4], apl[2][4];
#pragma unroll
            for (int mf = 0; mf < 2; mf++) {
                aph[mf][0] = packbf(s[mf][2 * kg][0], s[mf][2 * kg][1]);
                aph[mf][1] = packbf(s[mf][2 * kg][2], s[mf][2 * kg][3]);
                aph[mf][2] = packbf(s[mf][2 * kg + 1][0], s[mf][2 * kg + 1][1]);
                aph[mf][3] = packbf(s[mf][2 * kg + 1][2], s[mf][2 * kg + 1][3]);
#pragma unroll
                for (int r = 0; r < 4; r++) {
                    const int nf = 2 * kg + (r >> 1);
                    const int cb = (r & 1) * 2;
                    apl[mf][r] = packbf(s[mf][nf][cb] - unlo(aph[mf][r]),
                                        s[mf][nf][cb + 1] - unhi(aph[mf][r]));
                }
            }
#pragma unroll
            for (int dp = 0; dp < 4; dp++) {
                const u32 vrow = (u32)(((kg * 16 + (lane & 7) + ((lane >> 3) & 1) * 8) * STR
                                        + dp * 16 + (lane >> 4) * 8) * 2);
                u32 t0, t1, t2, t3;
                u32 bvh0[2], bvh1[2], bvl0[2], bvl1[2];
                ldsm4t(t0, t1, t2, t3, kb_ + VH_O + vrow);
                bvh0[0] = t0; bvh0[1] = t1; bvh1[0] = t2; bvh1[1] = t3;
                ldsm4t(t0, t1, t2, t3, kb_ + VL_O + vrow);
                bvl0[0] = t0; bvl0[1] = t1; bvl1[0] = t2; bvl1[1] = t3;
#pragma unroll
                for (int mf = 0; mf < 2; mf++) {
                    mma16816(o[mf][2 * dp], aph[mf], bvh0);
                    mma16816(o[mf][2 * dp], aph[mf], bvl0);
                    mma16816(o[mf][2 * dp], apl[mf], bvh0);
                    mma16816(o[mf][2 * dp + 1], aph[mf], bvh1);
                    mma16816(o[mf][2 * dp + 1], aph[mf], bvl1);
                    mma16816(o[mf][2 * dp + 1], apl[mf], bvh1);
                }
            }
        }
        __syncthreads();
    }

    // ----- epilogue: normalize, split to bf16 hi/lo, write ctx [B,L,E] -----
#pragma unroll
    for (int mf = 0; mf < 2; mf++) {
#pragma unroll
        for (int hl = 0; hl < 2; hl++) {
            const int idx = mf * 2 + hl;
            const float inv = 1.f / lrow[idx];
            const int qi = q0 + wm + mf * 16 + g + hl * 8;
#pragma unroll
            for (int nf = 0; nf < 8; nf++) {
                const float o0 = o[mf][nf][hl * 2] * inv;
                const float o1 = o[mf][nf][hl * 2 + 1] * inv;
                const u32 hv = packbf(o0, o1);
                const u32 lv = packbf(o0 - unlo(hv), o1 - unhi(hv));
                const size_t e = ((size_t)(b * LDIM + qi) * EDIM)
                               + h * DDIM + nf * 8 + qd * 2;
                ctxh[e >> 1] = hv;
                ctxl[e >> 1] = lv;
            }
        }
    }
}

// ---------------------------------------------------------------------------
extern "C" void kernel_launch(void* const* d_in, const int* in_sizes, int n_in,
                              void* d_out, int out_size)
{
    const float* hs = (const float*)d_in[0];
    const int* sl   = (const int*)d_in[1];
    const float* Wq = (const float*)d_in[2];
    const float* bq = (const float*)d_in[3];
    const float* Wk = (const float*)d_in[4];
    const float* Wv = (const float*)d_in[5];
    const float* bv = (const float*)d_in[6];
    const float* Wo = (const float*)d_in[7];
    const float* bo = (const float*)d_in[8];
    float* out = (float*)d_out;

    __nv_bfloat16 *qh, *ql, *kh, *kl, *vh, *vl, *hsh, *hsl, *ctxh, *ctxl, *wh, *wl;
    cudaGetSymbolAddress((void**)&qh, g_qh);
    cudaGetSymbolAddress((void**)&ql, g_ql);
    cudaGetSymbolAddress((void**)&kh, g_kh);
    cudaGetSymbolAddress((void**)&kl, g_kl);
    cudaGetSymbolAddress((void**)&vh, g_vh);
    cudaGetSymbolAddress((void**)&vl, g_vl);
    cudaGetSymbolAddress((void**)&hsh, g_hs_h);
    cudaGetSymbolAddress((void**)&hsl, g_hs_l);
    cudaGetSymbolAddress((void**)&ctxh, g_ctx_h);
    cudaGetSymbolAddress((void**)&ctxl, g_ctx_l);
    cudaGetSymbolAddress((void**)&wh, g_w_h);
    cudaGetSymbolAddress((void**)&wl, g_w_l);

    cudaFuncSetAttribute(gemm_bf16x3, cudaFuncAttributeMaxDynamicSharedMemorySize,
                         2 * STAGE_B);
    cudaFuncSetAttribute(attn_mma, cudaFuncAttributeMaxDynamicSharedMemorySize,
                         ATT_SMEM);

    const int WSZ = EDIM * EDIM;
    split_f32<<<(MDIM * EDIM / 4 + 255) / 256, 256>>>(hs, hsh, hsl, MDIM * EDIM / 4);
    split_f32<<<(WSZ / 4 + 255) / 256, 256>>>(Wq, wh + 0 * WSZ, wl + 0 * WSZ, WSZ / 4);
    split_f32<<<(WSZ / 4 + 255) / 256, 256>>>(Wk, wh + 1 * WSZ, wl + 1 * WSZ, WSZ / 4);
    split_f32<<<(WSZ / 4 + 255) / 256, 256>>>(Wv, wh + 2 * WSZ, wl + 2 * WSZ, WSZ / 4);
    split_f32<<<(WSZ / 4 + 255) / 256, 256>>>(Wo, wh + 3 * WSZ, wl + 3 * WSZ, WSZ / 4);

    dim3 gg(EDIM / 128, MDIM / 128);    // (8, 32)
    const int dsm = 2 * STAGE_B;
    gemm_bf16x3<<<gg, 256, dsm>>>(hsh, hsl, wh + 0 * WSZ, wl + 0 * WSZ, bq, 0.125f,
                                  nullptr, (u32*)qh, (u32*)ql, 1);
    gemm_bf16x3<<<gg, 256, dsm>>>(hsh, hsl, wh + 1 * WSZ, wl + 1 * WSZ, nullptr, 1.0f,
                                  nullptr, (u32*)kh, (u32*)kl, 1);
    gemm_bf16x3<<<gg, 256, dsm>>>(hsh, hsl, wh + 2 * WSZ, wl + 2 * WSZ, bv, 1.0f,
                                  nullptr, (u32*)vh, (u32*)vl, 1);

    dim3 ga(LDIM / 128, BDIM * HDIM);   // (16, 32)
    attn_mma<<<ga, 128, ATT_SMEM>>>(sl, (u32*)ctxh, (u32*)ctxl);

    gemm_bf16x3<<<gg, 256, dsm>>>(ctxh, ctxl, wh + 3 * WSZ, wl + 3 * WSZ, bo, 1.0f,
                                  out, nullptr, nullptr, 0);
}

// round 6
// speedup vs baseline: 2.9538x; 1.1109x over previous
#include <cuda_runtime.h>
#include <cuda_bf16.h>
#include <cstdint>
#include <math.h>

typedef unsigned int u32;

#define BDIM 2
#define LDIM 2048
#define EDIM 1024
#define HDIM 16
#define DDIM 64
#define MDIM (BDIM * LDIM)   // 4096

// ---------------- scratch (device globals; allocation is forbidden) --------
__device__ __nv_bfloat16 g_qh[BDIM * HDIM * LDIM * DDIM];   // [B,H,L,D]
__device__ __nv_bfloat16 g_ql[BDIM * HDIM * LDIM * DDIM];
__device__ __nv_bfloat16 g_kh[BDIM * HDIM * LDIM * DDIM];
__device__ __nv_bfloat16 g_kl[BDIM * HDIM * LDIM * DDIM];
__device__ __nv_bfloat16 g_vh[BDIM * HDIM * LDIM * DDIM];
__device__ __nv_bfloat16 g_vl[BDIM * HDIM * LDIM * DDIM];
__device__ __nv_bfloat16 g_hs_h[MDIM * EDIM];
__device__ __nv_bfloat16 g_hs_l[MDIM * EDIM];
__device__ __nv_bfloat16 g_ctx_h[MDIM * EDIM];              // [B,L,E]
__device__ __nv_bfloat16 g_ctx_l[MDIM * EDIM];
__device__ __nv_bfloat16 g_w_h[4 * EDIM * EDIM];            // Wq,Wk,Wv,Wo
__device__ __nv_bfloat16 g_w_l[4 * EDIM * EDIM];
__device__ float g_meanv[BDIM * HDIM * DDIM];               // [B,H,D]

// ---------------------------------------------------------------------------
// helpers
// ---------------------------------------------------------------------------
__device__ __forceinline__ u32 packbf(float lo, float hi) {
    u32 d;
    asm("cvt.rn.bf16x2.f32 %0, %1, %2;" : "=r"(d) : "f"(hi), "f"(lo));
    return d;
}
__device__ __forceinline__ float unlo(u32 u) { return __uint_as_float(u << 16); }
__device__ __forceinline__ float unhi(u32 u) { return __uint_as_float(u & 0xffff0000u); }

__device__ __forceinline__ void cpasync16(u32 dst, const void* src) {
    asm volatile("cp.async.cg.shared.global [%0], [%1], 16;\n" :: "r"(dst), "l"(src));
}
__device__ __forceinline__ void cp_commit() { asm volatile("cp.async.commit_group;\n"); }
__device__ __forceinline__ void cp_wait1() { asm volatile("cp.async.wait_group 1;\n"); }
__device__ __forceinline__ void cp_wait0() { asm volatile("cp.async.wait_group 0;\n"); }

__device__ __forceinline__ void ldsm4(u32& r0, u32& r1, u32& r2, u32& r3, u32 addr) {
    asm volatile("ldmatrix.sync.aligned.m8n8.x4.shared.b16 {%0,%1,%2,%3}, [%4];"
        : "=r"(r0), "=r"(r1), "=r"(r2), "=r"(r3) : "r"(addr));
}
__device__ __forceinline__ void ldsm4t(u32& r0, u32& r1, u32& r2, u32& r3, u32 addr) {
    asm volatile("ldmatrix.sync.aligned.m8n8.x4.trans.shared.b16 {%0,%1,%2,%3}, [%4];"
        : "=r"(r0), "=r"(r1), "=r"(r2), "=r"(r3) : "r"(addr));
}
__device__ __forceinline__ void mma16816(float* acc, const u32* a, const u32* b) {
    asm volatile("mma.sync.aligned.m16n8k16.row.col.f32.bf16.bf16.f32 "
        "{%0,%1,%2,%3}, {%4,%5,%6,%7}, {%8,%9}, {%0,%1,%2,%3};"
        : "+f"(acc[0]), "+f"(acc[1]), "+f"(acc[2]), "+f"(acc[3])
        : "r"(a[0]), "r"(a[1]), "r"(a[2]), "r"(a[3]), "r"(b[0]), "r"(b[1]));
}

// ---------------------------------------------------------------------------
// Split fp32 -> bf16 hi + bf16 lo
// ---------------------------------------------------------------------------
__global__ __launch_bounds__(256)
void split_f32(const float* __restrict__ x, __nv_bfloat16* __restrict__ hi,
               __nv_bfloat16* __restrict__ lo, int n4)
{
    int i = blockIdx.x * blockDim.x + threadIdx.x;
    if (i >= n4) return;
    float4 v = ((const float4*)x)[i];
    u32 h0 = packbf(v.x, v.y), h1 = packbf(v.z, v.w);
    u32 l0 = packbf(v.x - unlo(h0), v.y - unhi(h0));
    u32 l1 = packbf(v.z - unlo(h1), v.w - unhi(h1));
    uint2 hv; hv.x = h0; hv.y = h1;
    uint2 lv; lv.x = l0; lv.y = l1;
    ((uint2*)hi)[i] = hv;
    ((uint2*)lo)[i] = lv;
}

// ---------------------------------------------------------------------------
// mean(V) over all L rows per (b,h,d)  -> g_meanv
// ---------------------------------------------------------------------------
__global__ __launch_bounds__(256)
void meanv_kernel(float* __restrict__ mv)
{
    __shared__ float red[256];
    const int bh = blockIdx.x;           // 0..31
    const int tid = threadIdx.x;
    const int d = tid & 63;
    const int seg = tid >> 6;            // 0..3
    const __nv_bfloat16* vh = g_vh + (size_t)bh * LDIM * DDIM;
    const __nv_bfloat16* vl = g_vl + (size_t)bh * LDIM * DDIM;
    float s = 0.f;
    for (int l = seg * 512; l < (seg + 1) * 512; l++) {
        const size_t e = (size_t)l * DDIM + d;
        s += __bfloat162float(vh[e]) + __bfloat162float(vl[e]);
    }
    red[tid] = s;
    __syncthreads();
    if (tid < 64)
        mv[bh * 64 + d] = (red[d] + red[64 + d] + red[128 + d] + red[192 + d])
                          * (1.0f / 2048.0f);
}

// ---------------------------------------------------------------------------
// Fill ctx rows for invalid queries (l >= seq_len[b]) with mean(V)
// ---------------------------------------------------------------------------
__global__ __launch_bounds__(256)
void fill_invalid(const int* __restrict__ seq_len, const float* __restrict__ mv,
                  u32* __restrict__ ctxh, u32* __restrict__ ctxl)
{
    const int r = blockIdx.x;            // 0..4095 row (b,l)
    const int b = r >> 11;
    const int l = r & (LDIM - 1);
    if (l < seq_len[b]) return;
    const int tid = threadIdx.x;
#pragma unroll
    for (int it = 0; it < 2; it++) {
        const int idx = tid + it * 256;  // pair index 0..511
        const int col = idx * 2;
        const float v0 = mv[b * 1024 + col];
        const float v1 = mv[b * 1024 + col + 1];
        const u32 hv = packbf(v0, v1);
        const u32 lv = packbf(v0 - unlo(hv), v1 - unhi(hv));
        const size_t e = (size_t)r * 512 + idx;
        ctxh[e] = hv;
        ctxl[e] = lv;
    }
}

// ---------------------------------------------------------------------------
// bf16x3 tensor-core NT GEMM (round-4 validated, unchanged)
// ---------------------------------------------------------------------------
#define BK 32
#define SSTR 40
#define ARR_B (128 * SSTR * 2)
#define STAGE_B (4 * ARR_B)

__device__ __forceinline__ void issue_stage(
    u32 sb, int k0, int ldc0, u32 sOff,
    const __nv_bfloat16* Ah, const __nv_bfloat16* Al,
    const __nv_bfloat16* Bh, const __nv_bfloat16* Bl,
    size_t gArow, size_t gBrow)
{
#pragma unroll
    for (int c = 0; c < 2; c++) {
        int col = k0 + (ldc0 + c) * 8;
        u32 so = sOff + (u32)(ldc0 + c) * 16;
        cpasync16(sb + 0u * ARR_B + so, Ah + gArow + col);
        cpasync16(sb + 1u * ARR_B + so, Al + gArow + col);
        cpasync16(sb + 2u * ARR_B + so, Bh + gBrow + col);
        cpasync16(sb + 3u * ARR_B + so, Bl + gBrow + col);
    }
    cp_commit();
}

extern "C" __global__ __launch_bounds__(256, 1)
void gemm_bf16x3(const __nv_bfloat16* __restrict__ Ahg, const __nv_bfloat16* __restrict__ Alg,
                 const __nv_bfloat16* __restrict__ Bhg, const __nv_bfloat16* __restrict__ Blg,
                 const float* __restrict__ bias, float alpha,
                 float* __restrict__ out,
                 u32* __restrict__ outh, u32* __restrict__ outl, int mapQKV)
{
    extern __shared__ __align__(16) char dynsmem[];
    const u32 sbase = (u32)__cvta_generic_to_shared(dynsmem);
    const int K = EDIM;
    const int bm = blockIdx.y * 128;
    const int bn = blockIdx.x * 128;
    const int tid = threadIdx.x;
    const int lane = tid & 31;
    const int wid = tid >> 5;
    const int wm = (wid & 3) * 32;
    const int wn = (wid >> 2) * 64;

    const int ldrow = tid >> 1;
    const int ldc0 = (tid & 1) * 2;
    const size_t gArow = (size_t)(bm + ldrow) * K;
    const size_t gBrow = (size_t)(bn + ldrow) * K;
    const u32 sOff = (u32)(ldrow * SSTR * 2);

    float acc[2][8][4];
#pragma unroll
    for (int i = 0; i < 2; i++)
#pragma unroll
        for (int j = 0; j < 8; j++)
#pragma unroll
            for (int c = 0; c < 4; c++) acc[i][j][c] = 0.f;

    const int lrowA = wm + (lane & 15);
    const int lcol = (lane >> 4) * 8;
    const int lrowB = wn + (lane & 15);

    const int NIT = K / BK;
    issue_stage(sbase, 0, ldc0, sOff, Ahg, Alg, Bhg, Blg, gArow, gBrow);

    for (int it = 0; it < NIT; it++) {
        if (it + 1 < NIT) {
            issue_stage(sbase + (u32)((it + 1) & 1) * STAGE_B, (it + 1) * BK,
                        ldc0, sOff, Ahg, Alg, Bhg, Blg, gArow, gBrow);
            cp_wait1();
        } else {
            cp_wait0();
        }
        __syncthreads();

        const u32 sb = sbase + (u32)(it & 1) * STAGE_B;
#pragma unroll
        for (int ks = 0; ks < 2; ks++) {
            const int kb = ks * 16;
            u32 af[2][2][4];
            u32 bfr[2][8][2];
#pragma unroll
            for (int mt = 0; mt < 2; mt++) {
                u32 ad = sb + (u32)((lrowA + mt * 16) * SSTR + kb + lcol) * 2;
                ldsm4(af[0][mt][0], af[0][mt][1], af[0][mt][2], af[0][mt][3], ad + 0u * ARR_B);
                ldsm4(af[1][mt][0], af[1][mt][1], af[1][mt][2], af[1][mt][3], ad + 1u * ARR_B);
            }
#pragma unroll
            for (int p = 0; p < 4; p++) {
                u32 bd = sb + (u32)((lrowB + p * 16) * SSTR + kb + lcol) * 2;
                u32 t0, t1, t2, t3;
                ldsm4(t0, t1, t2, t3, bd + 2u * ARR_B);
                bfr[0][2 * p][0] = t0; bfr[0][2 * p][1] = t2;
                bfr[0][2 * p + 1][0] = t1; bfr[0][2 * p + 1][1] = t3;
                ldsm4(t0, t1, t2, t3, bd + 3u * ARR_B);
                bfr[1][2 * p][0] = t0; bfr[1][2 * p][1] = t2;
                bfr[1][2 * p + 1][0] = t1; bfr[1][2 * p + 1][1] = t3;
            }
#pragma unroll
            for (int mt = 0; mt < 2; mt++)
#pragma unroll
                for (int nt = 0; nt < 8; nt++) {
                    mma16816(acc[mt][nt], af[0][mt], bfr[0][nt]);
                    mma16816(acc[mt][nt], af[0][mt], bfr[1][nt]);
                    mma16816(acc[mt][nt], af[1][mt], bfr[0][nt]);
                }
        }
        __syncthreads();
    }

#pragma unroll
    for (int mt = 0; mt < 2; mt++) {
#pragma unroll
        for (int nt = 0; nt < 8; nt++) {
#pragma unroll
            for (int r = 0; r < 2; r++) {
                const int row = bm + wm + mt * 16 + (lane >> 2) + r * 8;
                const int col0 = bn + wn + nt * 8 + (lane & 3) * 2;
                float v0 = acc[mt][nt][r * 2 + 0];
                float v1 = acc[mt][nt][r * 2 + 1];
                if (bias) { v0 += bias[col0]; v1 += bias[col0 + 1]; }
                v0 *= alpha; v1 *= alpha;
                const int b = row >> 11;
                const int l = row & (LDIM - 1);
                if (mapQKV) {
                    const int h = col0 >> 6;
                    const int d = col0 & (DDIM - 1);
                    const size_t e = (((size_t)(b * HDIM + h) * LDIM) + l) * DDIM + d;
                    u32 hv = packbf(v0, v1);
                    u32 lv = packbf(v0 - unlo(hv), v1 - unhi(hv));
                    outh[e >> 1] = hv;
                    outl[e >> 1] = lv;
                } else {
                    out[(size_t)row * EDIM + col0] = v0;
                    out[(size_t)row * EDIM + col0 + 1] = v1;
                }
            }
        }
    }
}

// ---------------------------------------------------------------------------
// Tensor-core flash attention, VALID ROWS ONLY (invalid rows handled by
// fill_invalid). Blocks fully beyond seq_len exit immediately; tile loop
// runs causally to min(q0+127, sl-1).
// ---------------------------------------------------------------------------
#define STR 72
#define QH_OFF 0
#define QL_OFF (128 * STR * 2)
#define ST_BASE (2 * (128 * STR * 2))
#define KT_B (64 * STR * 2)
#define KH_O 0
#define KL_O KT_B
#define VH_O (2 * KT_B)
#define VL_O (3 * KT_B)
#define ST_SZ (4 * KT_B)
#define ATT_SMEM (ST_BASE + 2 * ST_SZ)

__device__ __forceinline__ void attn_issue_kv(u32 base, int kbase, int tid,
                                              const __nv_bfloat16* khg, const __nv_bfloat16* klg,
                                              const __nv_bfloat16* vhg, const __nv_bfloat16* vlg)
{
    const int row = tid >> 1;
    const int c0 = (tid & 1) * 4;
#pragma unroll
    for (int c = 0; c < 4; c++) {
        const int ch = c0 + c;
        const u32 off = (u32)((row * STR + ch * 8) * 2);
        const size_t src = (size_t)(kbase + row) * DDIM + ch * 8;
        cpasync16(base + KH_O + off, khg + src);
        cpasync16(base + KL_O + off, klg + src);
        cpasync16(base + VH_O + off, vhg + src);
        cpasync16(base + VL_O + off, vlg + src);
    }
}

__global__ __launch_bounds__(128)
void attn_mma(const int* __restrict__ seq_len,
              u32* __restrict__ ctxh, u32* __restrict__ ctxl)
{
    extern __shared__ __align__(16) char sm[];
    const u32 sb = (u32)__cvta_generic_to_shared(sm);
    const int bh = blockIdx.y;
    const int b = bh >> 4;
    const int h = bh & (HDIM - 1);
    const int qt = (int)gridDim.x - 1 - (int)blockIdx.x;   // heavy blocks first
    const int q0 = qt * 128;
    const int sl = seq_len[b];
    if (q0 >= sl) return;                 // fully invalid block

    const int tid = threadIdx.x;
    const int lane = tid & 31;
    const int w = tid >> 5;
    const int wm = w * 32;
    const int g = lane >> 2;
    const int qd = lane & 3;

    const size_t hoff = (size_t)bh * LDIM * DDIM;
    const __nv_bfloat16* qhg = g_qh + hoff;
    const __nv_bfloat16* qlg = g_ql + hoff;
    const __nv_bfloat16* khg = g_kh + hoff;
    const __nv_bfloat16* klg = g_kl + hoff;
    const __nv_bfloat16* vhg = g_vh + hoff;
    const __nv_bfloat16* vlg = g_vl + hoff;

    {
        const int row = tid;
        const size_t src = (size_t)(q0 + row) * DDIM;
#pragma unroll
        for (int c = 0; c < 8; c++) {
            const u32 off = (u32)((row * STR + c * 8) * 2);
            cpasync16(sb + QH_OFF + off, qhg + src + c * 8);
            cpasync16(sb + QL_OFF + off, qlg + src + c * 8);
        }
    }
    attn_issue_kv(sb + ST_BASE, 0, tid, khg, klg, vhg, vlg);
    cp_commit();

    const int qend = min(q0 + 127, sl - 1);
    const int ntiles = (qend >> 6) + 1;

    float o[2][8][4];
    float mrow[4], lrow[4];
#pragma unroll
    for (int i = 0; i < 2; i++)
#pragma unroll
        for (int j = 0; j < 8; j++)
#pragma unroll
            for (int c = 0; c < 4; c++) o[i][j][c] = 0.f;
#pragma unroll
    for (int i = 0; i < 4; i++) { mrow[i] = -1e30f; lrow[i] = 0.f; }

    for (int t = 0; t < ntiles; t++) {
        if (t + 1 < ntiles) {
            attn_issue_kv(sb + ST_BASE + (u32)((t + 1) & 1) * ST_SZ, (t + 1) << 6,
                          tid, khg, klg, vhg, vlg);
            cp_commit();
            cp_wait1();
        } else {
            cp_wait0();
        }
        __syncthreads();

        const u32 kb_ = sb + ST_BASE + (u32)(t & 1) * ST_SZ;

        // ----- S = Q K^T (bf16x3) -----
        float s[2][8][4];
#pragma unroll
        for (int i = 0; i < 2; i++)
#pragma unroll
            for (int j = 0; j < 8; j++)
#pragma unroll
                for (int c = 0; c < 4; c++) s[i][j][c] = 0.f;

#pragma unroll
        for (int kf = 0; kf < 4; kf++) {
            u32 aqh[2][4], aql[2][4];
#pragma unroll
            for (int mf = 0; mf < 2; mf++) {
                const u32 ad = (u32)(((wm + mf * 16 + (lane & 15)) * STR
                                      + kf * 16 + (lane >> 4) * 8) * 2);
                ldsm4(aqh[mf][0], aqh[mf][1], aqh[mf][2], aqh[mf][3], sb + QH_OFF + ad);
                ldsm4(aql[mf][0], aql[mf][1], aql[mf][2], aql[mf][3], sb + QL_OFF + ad);
            }
#pragma unroll
            for (int p = 0; p < 4; p++) {
                const u32 kd = (u32)(((p * 16 + (lane & 15)) * STR
                                      + kf * 16 + (lane >> 4) * 8) * 2);
                u32 t0, t1, t2, t3;
                u32 bkh0[2], bkh1[2], bkl0[2], bkl1[2];
                ldsm4(t0, t1, t2, t3, kb_ + KH_O + kd);
                bkh0[0] = t0; bkh0[1] = t2; bkh1[0] = t1; bkh1[1] = t3;
                ldsm4(t0, t1, t2, t3, kb_ + KL_O + kd);
                bkl0[0] = t0; bkl0[1] = t2; bkl1[0] = t1; bkl1[1] = t3;
#pragma unroll
                for (int mf = 0; mf < 2; mf++) {
                    mma16816(s[mf][2 * p], aqh[mf], bkh0);
                    mma16816(s[mf][2 * p], aqh[mf], bkl0);
                    mma16816(s[mf][2 * p], aql[mf], bkh0);
                    mma16816(s[mf][2 * p + 1], aqh[mf], bkh1);
                    mma16816(s[mf][2 * p + 1], aqh[mf], bkl1);
                    mma16816(s[mf][2 * p + 1], aql[mf], bkh1);
                }
            }
        }

        // ----- causal mask + online softmax -----
        const int kbase = t << 6;
#pragma unroll
        for (int mf = 0; mf < 2; mf++) {
#pragma unroll
            for (int hl = 0; hl < 2; hl++) {
                const int qi = q0 + wm + mf * 16 + g + hl * 8;
                const int idx = mf * 2 + hl;
                float mx = -1e30f;
#pragma unroll
                for (int nf = 0; nf < 8; nf++) {
                    const int c0 = kbase + nf * 8 + qd * 2;
                    float s0 = s[mf][nf][hl * 2];
                    float s1 = s[mf][nf][hl * 2 + 1];
                    if (c0 > qi) s0 = -1e30f;
                    if (c0 + 1 > qi) s1 = -1e30f;
                    s[mf][nf][hl * 2] = s0;
                    s[mf][nf][hl * 2 + 1] = s1;
                    mx = fmaxf(mx, fmaxf(s0, s1));
                }
                mx = fmaxf(mx, __shfl_xor_sync(0xffffffffu, mx, 1));
                mx = fmaxf(mx, __shfl_xor_sync(0xffffffffu, mx, 2));
                const float mnew = fmaxf(mrow[idx], mx);
                const float sc = __expf(mrow[idx] - mnew);
                mrow[idx] = mnew;
                float ps = 0.f;
#pragma unroll
                for (int nf = 0; nf < 8; nf++) {
                    float p0 = __expf(s[mf][nf][hl * 2] - mnew);
                    float p1 = __expf(s[mf][nf][hl * 2 + 1] - mnew);
                    s[mf][nf][hl * 2] = p0;
                    s[mf][nf][hl * 2 + 1] = p1;
                    ps += p0 + p1;
                    o[mf][nf][hl * 2] *= sc;
                    o[mf][nf][hl * 2 + 1] *= sc;
                }
                ps += __shfl_xor_sync(0xffffffffu, ps, 1);
                ps += __shfl_xor_sync(0xffffffffu, ps, 2);
                lrow[idx] = lrow[idx] * sc + ps;
            }
        }

        // ----- O += P V (bf16x3) -----
#pragma unroll
        for (int kg = 0; kg < 4; kg++) {
            u32 aph[2][4], apl[2][4];
#pragma unroll
            for (int mf = 0; mf < 2; mf++) {
                aph[mf][0] = packbf(s[mf][2 * kg][0], s[mf][2 * kg][1]);
                aph[mf][1] = packbf(s[mf][2 * kg][2], s[mf][2 * kg][3]);
                aph[mf][2] = packbf(s[mf][2 * kg + 1][0], s[mf][2 * kg + 1][1]);
                aph[mf][3] = packbf(s[mf][2 * kg + 1][2], s[mf][2 * kg + 1][3]);
#pragma unroll
                for (int r = 0; r < 4; r++) {
                    const int nf = 2 * kg + (r >> 1);
                    const int cb = (r & 1) * 2;
                    apl[mf][r] = packbf(s[mf][nf][cb] - unlo(aph[mf][r]),
                                        s[mf][nf][cb + 1] - unhi(aph[mf][r]));
                }
            }
#pragma unroll
            for (int dp = 0; dp < 4; dp++) {
                const u32 vrow = (u32)(((kg * 16 + (lane & 7) + ((lane >> 3) & 1) * 8) * STR
                                        + dp * 16 + (lane >> 4) * 8) * 2);
                u32 t0, t1, t2, t3;
                u32 bvh0[2], bvh1[2], bvl0[2], bvl1[2];
                ldsm4t(t0, t1, t2, t3, kb_ + VH_O + vrow);
                bvh0[0] = t0; bvh0[1] = t1; bvh1[0] = t2; bvh1[1] = t3;
                ldsm4t(t0, t1, t2, t3, kb_ + VL_O + vrow);
                bvl0[0] = t0; bvl0[1] = t1; bvl1[0] = t2; bvl1[1] = t3;
#pragma unroll
                for (int mf = 0; mf < 2; mf++) {
                    mma16816(o[mf][2 * dp], aph[mf], bvh0);
                    mma16816(o[mf][2 * dp], aph[mf], bvl0);
                    mma16816(o[mf][2 * dp], apl[mf], bvh0);
                    mma16816(o[mf][2 * dp + 1], aph[mf], bvh1);
                    mma16816(o[mf][2 * dp + 1], aph[mf], bvl1);
                    mma16816(o[mf][2 * dp + 1], apl[mf], bvh1);
                }
            }
        }
        __syncthreads();
    }

    // ----- epilogue: write VALID rows only -----
#pragma unroll
    for (int mf = 0; mf < 2; mf++) {
#pragma unroll
        for (int hl = 0; hl < 2; hl++) {
            const int idx = mf * 2 + hl;
            const int qi = q0 + wm + mf * 16 + g + hl * 8;
            if (qi >= sl) continue;
            const float inv = 1.f / lrow[idx];
#pragma unroll
            for (int nf = 0; nf < 8; nf++) {
                const float o0 = o[mf][nf][hl * 2] * inv;
                const float o1 = o[mf][nf][hl * 2 + 1] * inv;
                const u32 hv = packbf(o0, o1);
                const u32 lv = packbf(o0 - unlo(hv), o1 - unhi(hv));
                const size_t e = ((size_t)(b * LDIM + qi) * EDIM)
                               + h * DDIM + nf * 8 + qd * 2;
                ctxh[e >> 1] = hv;
                ctxl[e >> 1] = lv;
            }
        }
    }
}

// ---------------------------------------------------------------------------
extern "C" void kernel_launch(void* const* d_in, const int* in_sizes, int n_in,
                              void* d_out, int out_size)
{
    const float* hs = (const float*)d_in[0];
    const int* sl   = (const int*)d_in[1];
    const float* Wq = (const float*)d_in[2];
    const float* bq = (const float*)d_in[3];
    const float* Wk = (const float*)d_in[4];
    const float* Wv = (const float*)d_in[5];
    const float* bv = (const float*)d_in[6];
    const float* Wo = (const float*)d_in[7];
    const float* bo = (const float*)d_in[8];
    float* out = (float*)d_out;

    __nv_bfloat16 *qh, *ql, *kh, *kl, *vh, *vl, *hsh, *hsl, *ctxh, *ctxl, *wh, *wl;
    float* mv;
    cudaGetSymbolAddress((void**)&qh, g_qh);
    cudaGetSymbolAddress((void**)&ql, g_ql);
    cudaGetSymbolAddress((void**)&kh, g_kh);
    cudaGetSymbolAddress((void**)&kl, g_kl);
    cudaGetSymbolAddress((void**)&vh, g_vh);
    cudaGetSymbolAddress((void**)&vl, g_vl);
    cudaGetSymbolAddress((void**)&hsh, g_hs_h);
    cudaGetSymbolAddress((void**)&hsl, g_hs_l);
    cudaGetSymbolAddress((void**)&ctxh, g_ctx_h);
    cudaGetSymbolAddress((void**)&ctxl, g_ctx_l);
    cudaGetSymbolAddress((void**)&wh, g_w_h);
    cudaGetSymbolAddress((void**)&wl, g_w_l);
    cudaGetSymbolAddress((void**)&mv, g_meanv);

    cudaFuncSetAttribute(gemm_bf16x3, cudaFuncAttributeMaxDynamicSharedMemorySize,
                         2 * STAGE_B);
    cudaFuncSetAttribute(attn_mma, cudaFuncAttributeMaxDynamicSharedMemorySize, ATT_SMEM);

    const int WSZ = EDIM * EDIM;
    split_f32<<<(MDIM * EDIM / 4 + 255) / 256, 256>>>(hs, hsh, hsl, MDIM * EDIM / 4);
    split_f32<<<(WSZ / 4 + 255) / 256, 256>>>(Wq, wh + 0 * WSZ, wl + 0 * WSZ, WSZ / 4);
    split_f32<<<(WSZ / 4 + 255) / 256, 256>>>(Wk, wh + 1 * WSZ, wl + 1 * WSZ, WSZ / 4);
    split_f32<<<(WSZ / 4 + 255) / 256, 256>>>(Wv, wh + 2 * WSZ, wl + 2 * WSZ, WSZ / 4);
    split_f32<<<(WSZ / 4 + 255) / 256, 256>>>(Wo, wh + 3 * WSZ, wl + 3 * WSZ, WSZ / 4);

    dim3 gg(EDIM / 128, MDIM / 128);    // (8, 32)
    const int dsm = 2 * STAGE_B;
    gemm_bf16x3<<<gg, 256, dsm>>>(hsh, hsl, wh + 0 * WSZ, wl + 0 * WSZ, bq, 0.125f,
                                  nullptr, (u32*)qh, (u32*)ql, 1);
    gemm_bf16x3<<<gg, 256, dsm>>>(hsh, hsl, wh + 1 * WSZ, wl + 1 * WSZ, nullptr, 1.0f,
                                  nullptr, (u32*)kh, (u32*)kl, 1);
    gemm_bf16x3<<<gg, 256, dsm>>>(hsh, hsl, wh + 2 * WSZ, wl + 2 * WSZ, bv, 1.0f,
                                  nullptr, (u32*)vh, (u32*)vl, 1);

    meanv_kernel<<<BDIM * HDIM, 256>>>(mv);
    fill_invalid<<<MDIM, 256>>>(sl, mv, (u32*)ctxh, (u32*)ctxl);

    dim3 ga(LDIM / 128, BDIM * HDIM);   // (16, 32)
    attn_mma<<<ga, 128, ATT_SMEM>>>(sl, (u32*)ctxh, (u32*)ctxl);

    gemm_bf16x3<<<gg, 256, dsm>>>(ctxh, ctxl, wh + 3 * WSZ, wl + 3 * WSZ, bo, 1.0f,
                                  out, nullptr, nullptr, 0);
}

// round 7
// speedup vs baseline: 3.3345x; 1.1289x over previous
#include <cuda_runtime.h>
#include <cuda_bf16.h>
#include <cstdint>
#include <math.h>

typedef unsigned int u32;

#define BDIM 2
#define LDIM 2048
#define EDIM 1024
#define HDIM 16
#define DDIM 64
#define MDIM (BDIM * LDIM)   // 4096

// ---------------- scratch (device globals; allocation is forbidden) --------
__device__ __nv_bfloat16 g_qh[BDIM * HDIM * LDIM * DDIM];   // [B,H,L,D]
__device__ __nv_bfloat16 g_ql[BDIM * HDIM * LDIM * DDIM];
__device__ __nv_bfloat16 g_kh[BDIM * HDIM * LDIM * DDIM];
__device__ __nv_bfloat16 g_kl[BDIM * HDIM * LDIM * DDIM];
__device__ __nv_bfloat16 g_vh[BDIM * HDIM * LDIM * DDIM];
__device__ __nv_bfloat16 g_vl[BDIM * HDIM * LDIM * DDIM];
__device__ __nv_bfloat16 g_hs_h[MDIM * EDIM];
__device__ __nv_bfloat16 g_hs_l[MDIM * EDIM];
__device__ __nv_bfloat16 g_ctx_h[MDIM * EDIM];              // [B,L,E]
__device__ __nv_bfloat16 g_ctx_l[MDIM * EDIM];
__device__ __nv_bfloat16 g_w_h[4 * EDIM * EDIM];            // Wq,Wk,Wv,Wo
__device__ __nv_bfloat16 g_w_l[4 * EDIM * EDIM];
__device__ float g_meanv[BDIM * HDIM * DDIM];               // [B,H,D]

// ---------------------------------------------------------------------------
// helpers
// ---------------------------------------------------------------------------
__device__ __forceinline__ u32 packbf(float lo, float hi) {
    u32 d;
    asm("cvt.rn.bf16x2.f32 %0, %1, %2;" : "=r"(d) : "f"(hi), "f"(lo));
    return d;
}
__device__ __forceinline__ float unlo(u32 u) { return __uint_as_float(u << 16); }
__device__ __forceinline__ float unhi(u32 u) { return __uint_as_float(u & 0xffff0000u); }

__device__ __forceinline__ void cpasync16(u32 dst, const void* src) {
    asm volatile("cp.async.cg.shared.global [%0], [%1], 16;\n" :: "r"(dst), "l"(src));
}
__device__ __forceinline__ void cp_commit() { asm volatile("cp.async.commit_group;\n"); }
__device__ __forceinline__ void cp_wait1() { asm volatile("cp.async.wait_group 1;\n"); }
__device__ __forceinline__ void cp_wait0() { asm volatile("cp.async.wait_group 0;\n"); }

__device__ __forceinline__ void ldsm4(u32& r0, u32& r1, u32& r2, u32& r3, u32 addr) {
    asm volatile("ldmatrix.sync.aligned.m8n8.x4.shared.b16 {%0,%1,%2,%3}, [%4];"
        : "=r"(r0), "=r"(r1), "=r"(r2), "=r"(r3) : "r"(addr));
}
__device__ __forceinline__ void ldsm4t(u32& r0, u32& r1, u32& r2, u32& r3, u32 addr) {
    asm volatile("ldmatrix.sync.aligned.m8n8.x4.trans.shared.b16 {%0,%1,%2,%3}, [%4];"
        : "=r"(r0), "=r"(r1), "=r"(r2), "=r"(r3) : "r"(addr));
}
__device__ __forceinline__ void mma16816(float* acc, const u32* a, const u32* b) {
    asm volatile("mma.sync.aligned.m16n8k16.row.col.f32.bf16.bf16.f32 "
        "{%0,%1,%2,%3}, {%4,%5,%6,%7}, {%8,%9}, {%0,%1,%2,%3};"
        : "+f"(acc[0]), "+f"(acc[1]), "+f"(acc[2]), "+f"(acc[3])
        : "r"(a[0]), "r"(a[1]), "r"(a[2]), "r"(a[3]), "r"(b[0]), "r"(b[1]));
}

// ---------------------------------------------------------------------------
// Split fp32 -> bf16 hi + bf16 lo
// ---------------------------------------------------------------------------
__global__ __launch_bounds__(256)
void split_f32(const float* __restrict__ x, __nv_bfloat16* __restrict__ hi,
               __nv_bfloat16* __restrict__ lo, int n4)
{
    int i = blockIdx.x * blockDim.x + threadIdx.x;
    if (i >= n4) return;
    float4 v = ((const float4*)x)[i];
    u32 h0 = packbf(v.x, v.y), h1 = packbf(v.z, v.w);
    u32 l0 = packbf(v.x - unlo(h0), v.y - unhi(h0));
    u32 l1 = packbf(v.z - unlo(h1), v.w - unhi(h1));
    uint2 hv; hv.x = h0; hv.y = h1;
    uint2 lv; lv.x = l0; lv.y = l1;
    ((uint2*)hi)[i] = hv;
    ((uint2*)lo)[i] = lv;
}

// Split all four weight matrices in one launch (inputs may not be contiguous)
__global__ __launch_bounds__(256)
void split_w4(const float* __restrict__ w0, const float* __restrict__ w1,
              const float* __restrict__ w2, const float* __restrict__ w3,
              __nv_bfloat16* __restrict__ hi, __nv_bfloat16* __restrict__ lo)
{
    const int n4 = EDIM * EDIM / 4;      // per matrix
    int i = blockIdx.x * blockDim.x + threadIdx.x;
    const int m = i / n4;
    const int j = i - m * n4;
    const float* src = (m == 0) ? w0 : (m == 1) ? w1 : (m == 2) ? w2 : w3;
    float4 v = ((const float4*)src)[j];
    u32 h0 = packbf(v.x, v.y), h1 = packbf(v.z, v.w);
    u32 l0 = packbf(v.x - unlo(h0), v.y - unhi(h0));
    u32 l1 = packbf(v.z - unlo(h1), v.w - unhi(h1));
    uint2 hv; hv.x = h0; hv.y = h1;
    uint2 lv; lv.x = l0; lv.y = l1;
    ((uint2*)hi)[i] = hv;
    ((uint2*)lo)[i] = lv;
}

// ---------------------------------------------------------------------------
// mean(V) over all L rows per (b,h,d)  -> g_meanv
// ---------------------------------------------------------------------------
__global__ __launch_bounds__(256)
void meanv_kernel(float* __restrict__ mv)
{
    __shared__ float red[256];
    const int bh = blockIdx.x;
    const int tid = threadIdx.x;
    const int d = tid & 63;
    const int seg = tid >> 6;
    const __nv_bfloat16* vh = g_vh + (size_t)bh * LDIM * DDIM;
    const __nv_bfloat16* vl = g_vl + (size_t)bh * LDIM * DDIM;
    float s = 0.f;
    for (int l = seg * 512; l < (seg + 1) * 512; l++) {
        const size_t e = (size_t)l * DDIM + d;
        s += __bfloat162float(vh[e]) + __bfloat162float(vl[e]);
    }
    red[tid] = s;
    __syncthreads();
    if (tid < 64)
        mv[bh * 64 + d] = (red[d] + red[64 + d] + red[128 + d] + red[192 + d])
                          * (1.0f / 2048.0f);
}

// ---------------------------------------------------------------------------
// Fill ctx rows for invalid queries (l >= seq_len[b]) with mean(V)
// ---------------------------------------------------------------------------
__global__ __launch_bounds__(256)
void fill_invalid(const int* __restrict__ seq_len, const float* __restrict__ mv,
                  u32* __restrict__ ctxh, u32* __restrict__ ctxl)
{
    const int r = blockIdx.x;
    const int b = r >> 11;
    const int l = r & (LDIM - 1);
    if (l < seq_len[b]) return;
    const int tid = threadIdx.x;
#pragma unroll
    for (int it = 0; it < 2; it++) {
        const int idx = tid + it * 256;
        const int col = idx * 2;
        const float v0 = mv[b * 1024 + col];
        const float v1 = mv[b * 1024 + col + 1];
        const u32 hv = packbf(v0, v1);
        const u32 lv = packbf(v0 - unlo(hv), v1 - unhi(hv));
        const size_t e = (size_t)r * 512 + idx;
        ctxh[e] = hv;
        ctxl[e] = lv;
    }
}

// ---------------------------------------------------------------------------
// bf16x3 tensor-core NT GEMM, single-wave config.
// Tile 128(M) x 256(N), BK=32, 3-stage cp.async pipeline, 256 thr, 8 warps
// (2 M x 4 N), warp tile 64x64. Grid = (N/256, M/128) = 128 CTAs = 1 wave.
// ---------------------------------------------------------------------------
#define SSTR 40                           // smem row stride in bf16 (80 B)
#define A_ARR (128 * SSTR * 2)            // 10240 B
#define B_ARR (256 * SSTR * 2)            // 20480 B
#define O_AH 0
#define O_AL A_ARR
#define O_BH (2 * A_ARR)
#define O_BL (2 * A_ARR + B_ARR)
#define STG2 (2 * A_ARR + 2 * B_ARR)      // 61440 B
#define G_SMEM (3 * STG2)                 // 184320 B

__device__ __forceinline__ void g_issue(
    u32 sbase, int s, int k0, int tid,
    const __nv_bfloat16* Ah, const __nv_bfloat16* Al,
    const __nv_bfloat16* Bh, const __nv_bfloat16* Bl,
    int bm, int bn)
{
    const u32 st = sbase + (u32)(s % 3) * STG2;
    // A: 512 16B-chunks per array (128 rows x 4)
#pragma unroll
    for (int i = 0; i < 2; i++) {
        const int c = tid + i * 256;
        const int row = c >> 2, ch = c & 3;
        const u32 so = (u32)(row * (SSTR * 2) + ch * 16);
        const size_t gs = (size_t)(bm + row) * EDIM + k0 + ch * 8;
        cpasync16(st + O_AH + so, Ah + gs);
        cpasync16(st + O_AL + so, Al + gs);
    }
    // B: 1024 chunks per array (256 rows x 4)
#pragma unroll
    for (int i = 0; i < 4; i++) {
        const int c = tid + i * 256;
        const int row = c >> 2, ch = c & 3;
        const u32 so = (u32)(row * (SSTR * 2) + ch * 16);
        const size_t gs = (size_t)(bn + row) * EDIM + k0 + ch * 8;
        cpasync16(st + O_BH + so, Bh + gs);
        cpasync16(st + O_BL + so, Bl + gs);
    }
    cp_commit();
}

extern "C" __global__ __launch_bounds__(256, 1)
void gemm_bf16x3(const __nv_bfloat16* __restrict__ Ahg, const __nv_bfloat16* __restrict__ Alg,
                 const __nv_bfloat16* __restrict__ Bhg, const __nv_bfloat16* __restrict__ Blg,
                 const float* __restrict__ bias, float alpha,
                 float* __restrict__ out,
                 u32* __restrict__ outh, u32* __restrict__ outl, int mapQKV)
{
    extern __shared__ __align__(16) char dynsmem[];
    const u32 sbase = (u32)__cvta_generic_to_shared(dynsmem);
    const int bm = blockIdx.y * 128;
    const int bn = blockIdx.x * 256;
    const int tid = threadIdx.x;
    const int lane = tid & 31;
    const int wid = tid >> 5;
    const int wm = (wid & 1) * 64;        // warp M offset (2 warps along M)
    const int wn = (wid >> 1) * 64;       // warp N offset (4 warps along N)

    float acc[4][8][4];
#pragma unroll
    for (int i = 0; i < 4; i++)
#pragma unroll
        for (int j = 0; j < 8; j++)
#pragma unroll
            for (int c = 0; c < 4; c++) acc[i][j][c] = 0.f;

    const int lrA = wm + (lane & 15);
    const int lrB = wn + (lane & 15);
    const int lcol = (lane >> 4) * 8;

    const int NIT = EDIM / 32;            // 32
    g_issue(sbase, 0, 0, tid, Ahg, Alg, Bhg, Blg, bm, bn);
    g_issue(sbase, 1, 32, tid, Ahg, Alg, Bhg, Blg, bm, bn);

    for (int it = 0; it < NIT; it++) {
        if (it + 1 < NIT) cp_wait1(); else cp_wait0();
        __syncthreads();
        if (it + 2 < NIT)
            g_issue(sbase, it + 2, (it + 2) * 32, tid, Ahg, Alg, Bhg, Blg, bm, bn);

        const u32 st = sbase + (u32)(it % 3) * STG2;
#pragma unroll
        for (int ks = 0; ks < 2; ks++) {
            const int kb = ks * 16;
            u32 ah[4][4], al[4][4];
#pragma unroll
            for (int mt = 0; mt < 4; mt++) {
                const u32 ad = st + (u32)((lrA + mt * 16) * SSTR + kb + lcol) * 2;
                ldsm4(ah[mt][0], ah[mt][1], ah[mt][2], ah[mt][3], ad + O_AH);
                ldsm4(al[mt][0], al[mt][1], al[mt][2], al[mt][3], ad + O_AL);
            }
#pragma unroll
            for (int p = 0; p < 4; p++) {
                const u32 bd = st + (u32)((lrB + p * 16) * SSTR + kb + lcol) * 2;
                u32 t0, t1, t2, t3;
                u32 bh0[2], bh1[2], bl0[2], bl1[2];
                ldsm4(t0, t1, t2, t3, bd + O_BH);
                bh0[0] = t0; bh0[1] = t2; bh1[0] = t1; bh1[1] = t3;
                ldsm4(t0, t1, t2, t3, bd + O_BL);
                bl0[0] = t0; bl0[1] = t2; bl1[0] = t1; bl1[1] = t3;
#pragma unroll
                for (int mt = 0; mt < 4; mt++) {
                    mma16816(acc[mt][2 * p], ah[mt], bh0);
                    mma16816(acc[mt][2 * p], ah[mt], bl0);
                    mma16816(acc[mt][2 * p], al[mt], bh0);
                    mma16816(acc[mt][2 * p + 1], ah[mt], bh1);
                    mma16816(acc[mt][2 * p + 1], ah[mt], bl1);
                    mma16816(acc[mt][2 * p + 1], al[mt], bh1);
                }
            }
        }
        __syncthreads();
    }

    // ----- epilogue -----
#pragma unroll
    for (int mt = 0; mt < 4; mt++) {
#pragma unroll
        for (int nt = 0; nt < 8; nt++) {
#pragma unroll
            for (int r = 0; r < 2; r++) {
                const int row = bm + wm + mt * 16 + (lane >> 2) + r * 8;
                const int col0 = bn + wn + nt * 8 + (lane & 3) * 2;
                float v0 = acc[mt][nt][r * 2 + 0];
                float v1 = acc[mt][nt][r * 2 + 1];
                if (bias) { v0 += bias[col0]; v1 += bias[col0 + 1]; }
                v0 *= alpha; v1 *= alpha;
                const int b = row >> 11;
                const int l = row & (LDIM - 1);
                if (mapQKV) {
                    const int h = col0 >> 6;
                    const int d = col0 & (DDIM - 1);
                    const size_t e = (((size_t)(b * HDIM + h) * LDIM) + l) * DDIM + d;
                    u32 hv = packbf(v0, v1);
                    u32 lv = packbf(v0 - unlo(hv), v1 - unhi(hv));
                    outh[e >> 1] = hv;
                    outl[e >> 1] = lv;
                } else {
                    out[(size_t)row * EDIM + col0] = v0;
                    out[(size_t)row * EDIM + col0 + 1] = v1;
                }
            }
        }
    }
}

// ---------------------------------------------------------------------------
// Tensor-core flash attention, valid rows only (round-6 validated, unchanged)
// ---------------------------------------------------------------------------
#define STR 72
#define QH_OFF 0
#define QL_OFF (128 * STR * 2)
#define ST_BASE (2 * (128 * STR * 2))
#define KT_B (64 * STR * 2)
#define KH_O 0
#define KL_O KT_B
#define VH_O (2 * KT_B)
#define VL_O (3 * KT_B)
#define ST_SZ (4 * KT_B)
#define ATT_SMEM (ST_BASE + 2 * ST_SZ)

__device__ __forceinline__ void attn_issue_kv(u32 base, int kbase, int tid,
                                              const __nv_bfloat16* khg, const __nv_bfloat16* klg,
                                              const __nv_bfloat16* vhg, const __nv_bfloat16* vlg)
{
    const int row = tid >> 1;
    const int c0 = (tid & 1) * 4;
#pragma unroll
    for (int c = 0; c < 4; c++) {
        const int ch = c0 + c;
        const u32 off = (u32)((row * STR + ch * 8) * 2);
        const size_t src = (size_t)(kbase + row) * DDIM + ch * 8;
        cpasync16(base + KH_O + off, khg + src);
        cpasync16(base + KL_O + off, klg + src);
        cpasync16(base + VH_O + off, vhg + src);
        cpasync16(base + VL_O + off, vlg + src);
    }
}

__global__ __launch_bounds__(128)
void attn_mma(const int* __restrict__ seq_len,
              u32* __restrict__ ctxh, u32* __restrict__ ctxl)
{
    extern __shared__ __align__(16) char sm[];
    const u32 sb = (u32)__cvta_generic_to_shared(sm);
    const int bh = blockIdx.y;
    const int b = bh >> 4;
    const int h = bh & (HDIM - 1);
    const int qt = (int)gridDim.x - 1 - (int)blockIdx.x;
    const int q0 = qt * 128;
    const int sl = seq_len[b];
    if (q0 >= sl) return;

    const int tid = threadIdx.x;
    const int lane = tid & 31;
    const int w = tid >> 5;
    const int wm = w * 32;
    const int g = lane >> 2;
    const int qd = lane & 3;

    const size_t hoff = (size_t)bh * LDIM * DDIM;
    const __nv_bfloat16* qhg = g_qh + hoff;
    const __nv_bfloat16* qlg = g_ql + hoff;
    const __nv_bfloat16* khg = g_kh + hoff;
    const __nv_bfloat16* klg = g_kl + hoff;
    const __nv_bfloat16* vhg = g_vh + hoff;
    const __nv_bfloat16* vlg = g_vl + hoff;

    {
        const int row = tid;
        const size_t src = (size_t)(q0 + row) * DDIM;
#pragma unroll
        for (int c = 0; c < 8; c++) {
            const u32 off = (u32)((row * STR + c * 8) * 2);
            cpasync16(sb + QH_OFF + off, qhg + src + c * 8);
            cpasync16(sb + QL_OFF + off, qlg + src + c * 8);
        }
    }
    attn_issue_kv(sb + ST_BASE, 0, tid, khg, klg, vhg, vlg);
    cp_commit();

    const int qend = min(q0 + 127, sl - 1);
    const int ntiles = (qend >> 6) + 1;

    float o[2][8][4];
    float mrow[4], lrow[4];
#pragma unroll
    for (int i = 0; i < 2; i++)
#pragma unroll
        for (int j = 0; j < 8; j++)
#pragma unroll
            for (int c = 0; c < 4; c++) o[i][j][c] = 0.f;
#pragma unroll
    for (int i = 0; i < 4; i++) { mrow[i] = -1e30f; lrow[i] = 0.f; }

    for (int t = 0; t < ntiles; t++) {
        if (t + 1 < ntiles) {
            attn_issue_kv(sb + ST_BASE + (u32)((t + 1) & 1) * ST_SZ, (t + 1) << 6,
                          tid, khg, klg, vhg, vlg);
            cp_commit();
            cp_wait1();
        } else {
            cp_wait0();
        }
        __syncthreads();

        const u32 kb_ = sb + ST_BASE + (u32)(t & 1) * ST_SZ;

        float s[2][8][4];
#pragma unroll
        for (int i = 0; i < 2; i++)
#pragma unroll
            for (int j = 0; j < 8; j++)
#pragma unroll
                for (int c = 0; c < 4; c++) s[i][j][c] = 0.f;

#pragma unroll
        for (int kf = 0; kf < 4; kf++) {
            u32 aqh[2][4], aql[2][4];
#pragma unroll
            for (int mf = 0; mf < 2; mf++) {
                const u32 ad = (u32)(((wm + mf * 16 + (lane & 15)) * STR
                                      + kf * 16 + (lane >> 4) * 8) * 2);
                ldsm4(aqh[mf][0], aqh[mf][1], aqh[mf][2], aqh[mf][3], sb + QH_OFF + ad);
                ldsm4(aql[mf][0], aql[mf][1], aql[mf][2], aql[mf][3], sb + QL_OFF + ad);
            }
#pragma unroll
            for (int p = 0; p < 4; p++) {
                const u32 kd = (u32)(((p * 16 + (lane & 15)) * STR
                                      + kf * 16 + (lane >> 4) * 8) * 2);
                u32 t0, t1, t2, t3;
                u32 bkh0[2], bkh1[2], bkl0[2], bkl1[2];
                ldsm4(t0, t1, t2, t3, kb_ + KH_O + kd);
                bkh0[0] = t0; bkh0[1] = t2; bkh1[0] = t1; bkh1[1] = t3;
                ldsm4(t0, t1, t2, t3, kb_ + KL_O + kd);
                bkl0[0] = t0; bkl0[1] = t2; bkl1[0] = t1; bkl1[1] = t3;
#pragma unroll
                for (int mf = 0; mf < 2; mf++) {
                    mma16816(s[mf][2 * p], aqh[mf], bkh0);
                    mma16816(s[mf][2 * p], aqh[mf], bkl0);
                    mma16816(s[mf][2 * p], aql[mf], bkh0);
                    mma16816(s[mf][2 * p + 1], aqh[mf], bkh1);
                    mma16816(s[mf][2 * p + 1], aqh[mf], bkl1);
                    mma16816(s[mf][2 * p + 1], aql[mf], bkh1);
                }
            }
        }

        const int kbase = t << 6;
#pragma unroll
        for (int mf = 0; mf < 2; mf++) {
#pragma unroll
            for (int hl = 0; hl < 2; hl++) {
                const int qi = q0 + wm + mf * 16 + g + hl * 8;
                const int idx = mf * 2 + hl;
                float mx = -1e30f;
#pragma unroll
                for (int nf = 0; nf < 8; nf++) {
                    const int c0 = kbase + nf * 8 + qd * 2;
                    float s0 = s[mf][nf][hl * 2];
                    float s1 = s[mf][nf][hl * 2 + 1];
                    if (c0 > qi) s0 = -1e30f;
                    if (c0 + 1 > qi) s1 = -1e30f;
                    s[mf][nf][hl * 2] = s0;
                    s[mf][nf][hl * 2 + 1] = s1;
                    mx = fmaxf(mx, fmaxf(s0, s1));
                }
                mx = fmaxf(mx, __shfl_xor_sync(0xffffffffu, mx, 1));
                mx = fmaxf(mx, __shfl_xor_sync(0xffffffffu, mx, 2));
                const float mnew = fmaxf(mrow[idx], mx);
                const float sc = __expf(mrow[idx] - mnew);
                mrow[idx] = mnew;
                float ps = 0.f;
#pragma unroll
                for (int nf = 0; nf < 8; nf++) {
                    float p0 = __expf(s[mf][nf][hl * 2] - mnew);
                    float p1 = __expf(s[mf][nf][hl * 2 + 1] - mnew);
                    s[mf][nf][hl * 2] = p0;
                    s[mf][nf][hl * 2 + 1] = p1;
                    ps += p0 + p1;
                    o[mf][nf][hl * 2] *= sc;
                    o[mf][nf][hl * 2 + 1] *= sc;
                }
                ps += __shfl_xor_sync(0xffffffffu, ps, 1);
                ps += __shfl_xor_sync(0xffffffffu, ps, 2);
                lrow[idx] = lrow[idx] * sc + ps;
            }
        }

#pragma unroll
        for (int kg = 0; kg < 4; kg++) {
            u32 aph[2][4], apl[2][4];
#pragma unroll
            for (int mf = 0; mf < 2; mf++) {
                aph[mf][0] = packbf(s[mf][2 * kg][0], s[mf][2 * kg][1]);
                aph[mf][1] = packbf(s[mf][2 * kg][2], s[mf][2 * kg][3]);
                aph[mf][2] = packbf(s[mf][2 * kg + 1][0], s[mf][2 * kg + 1][1]);
                aph[mf][3] = packbf(s[mf][2 * kg + 1][2], s[mf][2 * kg + 1][3]);
#pragma unroll
                for (int r = 0; r < 4; r++) {
                    const int nf = 2 * kg + (r >> 1);
                    const int cb = (r & 1) * 2;
                    apl[mf][r] = packbf(s[mf][nf][cb] - unlo(aph[mf][r]),
                                        s[mf][nf][cb + 1] - unhi(aph[mf][r]));
                }
            }
#pragma unroll
            for (int dp = 0; dp < 4; dp++) {
                const u32 vrow = (u32)(((kg * 16 + (lane & 7) + ((lane >> 3) & 1) * 8) * STR
                                        + dp * 16 + (lane >> 4) * 8) * 2);
                u32 t0, t1, t2, t3;
                u32 bvh0[2], bvh1[2], bvl0[2], bvl1[2];
                ldsm4t(t0, t1, t2, t3, kb_ + VH_O + vrow);
                bvh0[0] = t0; bvh0[1] = t1; bvh1[0] = t2; bvh1[1] = t3;
                ldsm4t(t0, t1, t2, t3, kb_ + VL_O + vrow);
                bvl0[0] = t0; bvl0[1] = t1; bvl1[0] = t2; bvl1[1] = t3;
#pragma unroll
                for (int mf = 0; mf < 2; mf++) {
                    mma16816(o[mf][2 * dp], aph[mf], bvh0);
                    mma16816(o[mf][2 * dp], aph[mf], bvl0);
                    mma16816(o[mf][2 * dp], apl[mf], bvh0);
                    mma16816(o[mf][2 * dp + 1], aph[mf], bvh1);
                    mma16816(o[mf][2 * dp + 1], aph[mf], bvl1);
                    mma16816(o[mf][2 * dp + 1], apl[mf], bvh1);
                }
            }
        }
        __syncthreads();
    }

#pragma unroll
    for (int mf = 0; mf < 2; mf++) {
#pragma unroll
        for (int hl = 0; hl < 2; hl++) {
            const int idx = mf * 2 + hl;
            const int qi = q0 + wm + mf * 16 + g + hl * 8;
            if (qi >= sl) continue;
            const float inv = 1.f / lrow[idx];
#pragma unroll
            for (int nf = 0; nf < 8; nf++) {
                const float o0 = o[mf][nf][hl * 2] * inv;
                const float o1 = o[mf][nf][hl * 2 + 1] * inv;
                const u32 hv = packbf(o0, o1);
                const u32 lv = packbf(o0 - unlo(hv), o1 - unhi(hv));
                const size_t e = ((size_t)(b * LDIM + qi) * EDIM)
                               + h * DDIM + nf * 8 + qd * 2;
                ctxh[e >> 1] = hv;
                ctxl[e >> 1] = lv;
            }
        }
    }
}

// ---------------------------------------------------------------------------
extern "C" void kernel_launch(void* const* d_in, const int* in_sizes, int n_in,
                              void* d_out, int out_size)
{
    const float* hs = (const float*)d_in[0];
    const int* sl   = (const int*)d_in[1];
    const float* Wq = (const float*)d_in[2];
    const float* bq = (const float*)d_in[3];
    const float* Wk = (const float*)d_in[4];
    const float* Wv = (const float*)d_in[5];
    const float* bv = (const float*)d_in[6];
    const float* Wo = (const float*)d_in[7];
    const float* bo = (const float*)d_in[8];
    float* out = (float*)d_out;

    __nv_bfloat16 *qh, *ql, *kh, *kl, *vh, *vl, *hsh, *hsl, *ctxh, *ctxl, *wh, *wl;
    float* mv;
    cudaGetSymbolAddress((void**)&qh, g_qh);
    cudaGetSymbolAddress((void**)&ql, g_ql);
    cudaGetSymbolAddress((void**)&kh, g_kh);
    cudaGetSymbolAddress((void**)&kl, g_kl);
    cudaGetSymbolAddress((void**)&vh, g_vh);
    cudaGetSymbolAddress((void**)&vl, g_vl);
    cudaGetSymbolAddress((void**)&hsh, g_hs_h);
    cudaGetSymbolAddress((void**)&hsl, g_hs_l);
    cudaGetSymbolAddress((void**)&ctxh, g_ctx_h);
    cudaGetSymbolAddress((void**)&ctxl, g_ctx_l);
    cudaGetSymbolAddress((void**)&wh, g_w_h);
    cudaGetSymbolAddress((void**)&wl, g_w_l);
    cudaGetSymbolAddress((void**)&mv, g_meanv);

    cudaFuncSetAttribute(gemm_bf16x3, cudaFuncAttributeMaxDynamicSharedMemorySize, G_SMEM);
    cudaFuncSetAttribute(attn_mma, cudaFuncAttributeMaxDynamicSharedMemorySize, ATT_SMEM);

    const int WSZ = EDIM * EDIM;
    split_f32<<<(MDIM * EDIM / 4 + 255) / 256, 256>>>(hs, hsh, hsl, MDIM * EDIM / 4);
    split_w4<<<4 * WSZ / 4 / 256, 256>>>(Wq, Wk, Wv, Wo, wh, wl);

    dim3 gg(EDIM / 256, MDIM / 128);    // (4, 32) = 128 CTAs = 1 wave
    gemm_bf16x3<<<gg, 256, G_SMEM>>>(hsh, hsl, wh + 0 * WSZ, wl + 0 * WSZ, bq, 0.125f,
                                     nullptr, (u32*)qh, (u32*)ql, 1);
    gemm_bf16x3<<<gg, 256, G_SMEM>>>(hsh, hsl, wh + 1 * WSZ, wl + 1 * WSZ, nullptr, 1.0f,
                                     nullptr, (u32*)kh, (u32*)kl, 1);
    gemm_bf16x3<<<gg, 256, G_SMEM>>>(hsh, hsl, wh + 2 * WSZ, wl + 2 * WSZ, bv, 1.0f,
                                     nullptr, (u32*)vh, (u32*)vl, 1);

    meanv_kernel<<<BDIM * HDIM, 256>>>(mv);
    fill_invalid<<<MDIM, 256>>>(sl, mv, (u32*)ctxh, (u32*)ctxl);

    dim3 ga(LDIM / 128, BDIM * HDIM);   // (16, 32)
    attn_mma<<<ga, 128, ATT_SMEM>>>(sl, (u32*)ctxh, (u32*)ctxl);

    gemm_bf16x3<<<gg, 256, G_SMEM>>>(ctxh, ctxl, wh + 3 * WSZ, wl + 3 * WSZ, bo, 1.0f,
                                     out, nullptr, nullptr, 0);
}

// round 8
// speedup vs baseline: 3.4469x; 1.0337x over previous
#include <cuda_runtime.h>
#include <cuda_bf16.h>
#include <cstdint>
#include <math.h>

typedef unsigned int u32;

#define BDIM 2
#define LDIM 2048
#define EDIM 1024
#define HDIM 16
#define DDIM 64
#define MDIM (BDIM * LDIM)   // 4096

// ---------------- scratch (device globals; allocation is forbidden) --------
__device__ __nv_bfloat16 g_qh[BDIM * HDIM * LDIM * DDIM];   // [B,H,L,D]
__device__ __nv_bfloat16 g_ql[BDIM * HDIM * LDIM * DDIM];
__device__ __nv_bfloat16 g_kh[BDIM * HDIM * LDIM * DDIM];
__device__ __nv_bfloat16 g_kl[BDIM * HDIM * LDIM * DDIM];
__device__ __nv_bfloat16 g_vh[BDIM * HDIM * LDIM * DDIM];
__device__ __nv_bfloat16 g_vl[BDIM * HDIM * LDIM * DDIM];
__device__ __nv_bfloat16 g_hs_h[MDIM * EDIM];
__device__ __nv_bfloat16 g_hs_l[MDIM * EDIM];
__device__ __nv_bfloat16 g_ctx_h[MDIM * EDIM];              // [B,L,E]
__device__ __nv_bfloat16 g_ctx_l[MDIM * EDIM];
__device__ __nv_bfloat16 g_w_h[4 * EDIM * EDIM];            // Wq,Wk,Wv,Wo
__device__ __nv_bfloat16 g_w_l[4 * EDIM * EDIM];
__device__ float g_meanv[BDIM * HDIM * DDIM];               // [B,H,D]

// ---------------------------------------------------------------------------
// helpers
// ---------------------------------------------------------------------------
__device__ __forceinline__ u32 packbf(float lo, float hi) {
    u32 d;
    asm("cvt.rn.bf16x2.f32 %0, %1, %2;" : "=r"(d) : "f"(hi), "f"(lo));
    return d;
}
__device__ __forceinline__ float unlo(u32 u) { return __uint_as_float(u << 16); }
__device__ __forceinline__ float unhi(u32 u) { return __uint_as_float(u & 0xffff0000u); }

__device__ __forceinline__ void cpasync16(u32 dst, const void* src) {
    asm volatile("cp.async.cg.shared.global [%0], [%1], 16;\n" :: "r"(dst), "l"(src));
}
__device__ __forceinline__ void cp_commit() { asm volatile("cp.async.commit_group;\n"); }
__device__ __forceinline__ void cp_wait1() { asm volatile("cp.async.wait_group 1;\n"); }
__device__ __forceinline__ void cp_wait0() { asm volatile("cp.async.wait_group 0;\n"); }

__device__ __forceinline__ void ldsm4(u32& r0, u32& r1, u32& r2, u32& r3, u32 addr) {
    asm volatile("ldmatrix.sync.aligned.m8n8.x4.shared.b16 {%0,%1,%2,%3}, [%4];"
        : "=r"(r0), "=r"(r1), "=r"(r2), "=r"(r3) : "r"(addr));
}
__device__ __forceinline__ void ldsm4t(u32& r0, u32& r1, u32& r2, u32& r3, u32 addr) {
    asm volatile("ldmatrix.sync.aligned.m8n8.x4.trans.shared.b16 {%0,%1,%2,%3}, [%4];"
        : "=r"(r0), "=r"(r1), "=r"(r2), "=r"(r3) : "r"(addr));
}
__device__ __forceinline__ void mma16816(float* acc, const u32* a, const u32* b) {
    asm volatile("mma.sync.aligned.m16n8k16.row.col.f32.bf16.bf16.f32 "
        "{%0,%1,%2,%3}, {%4,%5,%6,%7}, {%8,%9}, {%0,%1,%2,%3};"
        : "+f"(acc[0]), "+f"(acc[1]), "+f"(acc[2]), "+f"(acc[3])
        : "r"(a[0]), "r"(a[1]), "r"(a[2]), "r"(a[3]), "r"(b[0]), "r"(b[1]));
}

// ---------------------------------------------------------------------------
// Split fp32 -> bf16 hi + bf16 lo
// ---------------------------------------------------------------------------
__global__ __launch_bounds__(256)
void split_f32(const float* __restrict__ x, __nv_bfloat16* __restrict__ hi,
               __nv_bfloat16* __restrict__ lo, int n4)
{
    int i = blockIdx.x * blockDim.x + threadIdx.x;
    if (i >= n4) return;
    float4 v = ((const float4*)x)[i];
    u32 h0 = packbf(v.x, v.y), h1 = packbf(v.z, v.w);
    u32 l0 = packbf(v.x - unlo(h0), v.y - unhi(h0));
    u32 l1 = packbf(v.z - unlo(h1), v.w - unhi(h1));
    uint2 hv; hv.x = h0; hv.y = h1;
    uint2 lv; lv.x = l0; lv.y = l1;
    ((uint2*)hi)[i] = hv;
    ((uint2*)lo)[i] = lv;
}

// Split all four weight matrices in one launch
__global__ __launch_bounds__(256)
void split_w4(const float* __restrict__ w0, const float* __restrict__ w1,
              const float* __restrict__ w2, const float* __restrict__ w3,
              __nv_bfloat16* __restrict__ hi, __nv_bfloat16* __restrict__ lo)
{
    const int n4 = EDIM * EDIM / 4;
    int i = blockIdx.x * blockDim.x + threadIdx.x;
    const int m = i / n4;
    const int j = i - m * n4;
    const float* src = (m == 0) ? w0 : (m == 1) ? w1 : (m == 2) ? w2 : w3;
    float4 v = ((const float4*)src)[j];
    u32 h0 = packbf(v.x, v.y), h1 = packbf(v.z, v.w);
    u32 l0 = packbf(v.x - unlo(h0), v.y - unhi(h0));
    u32 l1 = packbf(v.z - unlo(h1), v.w - unhi(h1));
    uint2 hv; hv.x = h0; hv.y = h1;
    uint2 lv; lv.x = l0; lv.y = l1;
    ((uint2*)hi)[i] = hv;
    ((uint2*)lo)[i] = lv;
}

// ---------------------------------------------------------------------------
// mean(V) over all L rows per (b,h,d)  -> g_meanv
// ---------------------------------------------------------------------------
__global__ __launch_bounds__(256)
void meanv_kernel(float* __restrict__ mv)
{
    __shared__ float red[256];
    const int bh = blockIdx.x;
    const int tid = threadIdx.x;
    const int d = tid & 63;
    const int seg = tid >> 6;
    const __nv_bfloat16* vh = g_vh + (size_t)bh * LDIM * DDIM;
    const __nv_bfloat16* vl = g_vl + (size_t)bh * LDIM * DDIM;
    float s = 0.f;
    for (int l = seg * 512; l < (seg + 1) * 512; l++) {
        const size_t e = (size_t)l * DDIM + d;
        s += __bfloat162float(vh[e]) + __bfloat162float(vl[e]);
    }
    red[tid] = s;
    __syncthreads();
    if (tid < 64)
        mv[bh * 64 + d] = (red[d] + red[64 + d] + red[128 + d] + red[192 + d])
                          * (1.0f / 2048.0f);
}

// ---------------------------------------------------------------------------
// Fill ctx rows for invalid queries (l >= seq_len[b]) with mean(V)
// ---------------------------------------------------------------------------
__global__ __launch_bounds__(256)
void fill_invalid(const int* __restrict__ seq_len, const float* __restrict__ mv,
                  u32* __restrict__ ctxh, u32* __restrict__ ctxl)
{
    const int r = blockIdx.x;
    const int b = r >> 11;
    const int l = r & (LDIM - 1);
    if (l < seq_len[b]) return;
    const int tid = threadIdx.x;
#pragma unroll
    for (int it = 0; it < 2; it++) {
        const int idx = tid + it * 256;
        const int col = idx * 2;
        const float v0 = mv[b * 1024 + col];
        const float v1 = mv[b * 1024 + col + 1];
        const u32 hv = packbf(v0, v1);
        const u32 lv = packbf(v0 - unlo(hv), v1 - unhi(hv));
        const size_t e = (size_t)r * 512 + idx;
        ctxh[e] = hv;
        ctxl[e] = lv;
    }
}

// ---------------------------------------------------------------------------
// bf16x3 tensor-core NT GEMM, single-wave, 512 threads / 16 warps.
// Tile 128(M) x 256(N), BK=32, 3-stage cp.async, warp grid 4M x 4N,
// warp tile 32x64. Grid = 128 CTAs = 1 wave.
// ---------------------------------------------------------------------------
#define SSTR 40                           // smem row stride in bf16 (80 B)
#define A_ARR (128 * SSTR * 2)            // 10240 B
#define B_ARR (256 * SSTR * 2)            // 20480 B
#define O_AH 0
#define O_AL A_ARR
#define O_BH (2 * A_ARR)
#define O_BL (2 * A_ARR + B_ARR)
#define STG2 (2 * A_ARR + 2 * B_ARR)      // 61440 B
#define G_SMEM (3 * STG2)                 // 184320 B

__device__ __forceinline__ void g_issue(
    u32 sbase, int s, int k0, int tid,
    const __nv_bfloat16* Ah, const __nv_bfloat16* Al,
    const __nv_bfloat16* Bh, const __nv_bfloat16* Bl,
    int bm, int bn)
{
    const u32 st = sbase + (u32)(s % 3) * STG2;
    // A: 512 16B-chunks per array (128 rows x 4), one per thread
    {
        const int row = tid >> 2, ch = tid & 3;
        const u32 so = (u32)(row * (SSTR * 2) + ch * 16);
        const size_t gs = (size_t)(bm + row) * EDIM + k0 + ch * 8;
        cpasync16(st + O_AH + so, Ah + gs);
        cpasync16(st + O_AL + so, Al + gs);
    }
    // B: 1024 chunks per array (256 rows x 4), two per thread
#pragma unroll
    for (int i = 0; i < 2; i++) {
        const int c = tid + i * 512;
        const int row = c >> 2, ch = c & 3;
        const u32 so = (u32)(row * (SSTR * 2) + ch * 16);
        const size_t gs = (size_t)(bn + row) * EDIM + k0 + ch * 8;
        cpasync16(st + O_BH + so, Bh + gs);
        cpasync16(st + O_BL + so, Bl + gs);
    }
    cp_commit();
}

extern "C" __global__ __launch_bounds__(512, 1)
void gemm_bf16x3(const __nv_bfloat16* __restrict__ Ahg, const __nv_bfloat16* __restrict__ Alg,
                 const __nv_bfloat16* __restrict__ Bhg, const __nv_bfloat16* __restrict__ Blg,
                 const float* __restrict__ bias, float alpha,
                 float* __restrict__ out,
                 u32* __restrict__ outh, u32* __restrict__ outl, int mapQKV)
{
    extern __shared__ __align__(16) char dynsmem[];
    const u32 sbase = (u32)__cvta_generic_to_shared(dynsmem);
    const int bm = blockIdx.y * 128;
    const int bn = blockIdx.x * 256;
    const int tid = threadIdx.x;
    const int lane = tid & 31;
    const int wid = tid >> 5;
    const int wm = (wid & 3) * 32;        // 4 warps along M
    const int wn = (wid >> 2) * 64;       // 4 warps along N

    float acc[2][8][4];
#pragma unroll
    for (int i = 0; i < 2; i++)
#pragma unroll
        for (int j = 0; j < 8; j++)
#pragma unroll
            for (int c = 0; c < 4; c++) acc[i][j][c] = 0.f;

    const int lrA = wm + (lane & 15);
    const int lrB = wn + (lane & 15);
    const int lcol = (lane >> 4) * 8;

    const int NIT = EDIM / 32;            // 32
    g_issue(sbase, 0, 0, tid, Ahg, Alg, Bhg, Blg, bm, bn);
    g_issue(sbase, 1, 32, tid, Ahg, Alg, Bhg, Blg, bm, bn);

    for (int it = 0; it < NIT; it++) {
        if (it + 1 < NIT) cp_wait1(); else cp_wait0();
        __syncthreads();
        if (it + 2 < NIT)
            g_issue(sbase, it + 2, (it + 2) * 32, tid, Ahg, Alg, Bhg, Blg, bm, bn);

        const u32 st = sbase + (u32)(it % 3) * STG2;
#pragma unroll
        for (int ks = 0; ks < 2; ks++) {
            const int kb = ks * 16;
            u32 ah[2][4], al[2][4];
#pragma unroll
            for (int mt = 0; mt < 2; mt++) {
                const u32 ad = st + (u32)((lrA + mt * 16) * SSTR + kb + lcol) * 2;
                ldsm4(ah[mt][0], ah[mt][1], ah[mt][2], ah[mt][3], ad + O_AH);
                ldsm4(al[mt][0], al[mt][1], al[mt][2], al[mt][3], ad + O_AL);
            }
#pragma unroll
            for (int p = 0; p < 4; p++) {
                const u32 bd = st + (u32)((lrB + p * 16) * SSTR + kb + lcol) * 2;
                u32 t0, t1, t2, t3;
                u32 bh0[2], bh1[2], bl0[2], bl1[2];
                ldsm4(t0, t1, t2, t3, bd + O_BH);
                bh0[0] = t0; bh0[1] = t2; bh1[0] = t1; bh1[1] = t3;
                ldsm4(t0, t1, t2, t3, bd + O_BL);
                bl0[0] = t0; bl0[1] = t2; bl1[0] = t1; bl1[1] = t3;
#pragma unroll
                for (int mt = 0; mt < 2; mt++) {
                    mma16816(acc[mt][2 * p], ah[mt], bh0);
                    mma16816(acc[mt][2 * p], ah[mt], bl0);
                    mma16816(acc[mt][2 * p], al[mt], bh0);
                    mma16816(acc[mt][2 * p + 1], ah[mt], bh1);
                    mma16816(acc[mt][2 * p + 1], ah[mt], bl1);
                    mma16816(acc[mt][2 * p + 1], al[mt], bh1);
                }
            }
        }
        __syncthreads();
    }

    // ----- epilogue -----
#pragma unroll
    for (int mt = 0; mt < 2; mt++) {
#pragma unroll
        for (int nt = 0; nt < 8; nt++) {
#pragma unroll
            for (int r = 0; r < 2; r++) {
                const int row = bm + wm + mt * 16 + (lane >> 2) + r * 8;
                const int col0 = bn + wn + nt * 8 + (lane & 3) * 2;
                float v0 = acc[mt][nt][r * 2 + 0];
                float v1 = acc[mt][nt][r * 2 + 1];
                if (bias) { v0 += bias[col0]; v1 += bias[col0 + 1]; }
                v0 *= alpha; v1 *= alpha;
                const int b = row >> 11;
                const int l = row & (LDIM - 1);
                if (mapQKV) {
                    const int h = col0 >> 6;
                    const int d = col0 & (DDIM - 1);
                    const size_t e = (((size_t)(b * HDIM + h) * LDIM) + l) * DDIM + d;
                    u32 hv = packbf(v0, v1);
                    u32 lv = packbf(v0 - unlo(hv), v1 - unhi(hv));
                    outh[e >> 1] = hv;
                    outl[e >> 1] = lv;
                } else {
                    out[(size_t)row * EDIM + col0] = v0;
                    out[(size_t)row * EDIM + col0 + 1] = v1;
                }
            }
        }
    }
}

// ---------------------------------------------------------------------------
// Tensor-core flash attention, valid rows only (round-6 validated, unchanged)
// ---------------------------------------------------------------------------
#define STR 72
#define QH_OFF 0
#define QL_OFF (128 * STR * 2)
#define ST_BASE (2 * (128 * STR * 2))
#define KT_B (64 * STR * 2)
#define KH_O 0
#define KL_O KT_B
#define VH_O (2 * KT_B)
#define VL_O (3 * KT_B)
#define ST_SZ (4 * KT_B)
#define ATT_SMEM (ST_BASE + 2 * ST_SZ)

__device__ __forceinline__ void attn_issue_kv(u32 base, int kbase, int tid,
                                              const __nv_bfloat16* khg, const __nv_bfloat16* klg,
                                              const __nv_bfloat16* vhg, const __nv_bfloat16* vlg)
{
    const int row = tid >> 1;
    const int c0 = (tid & 1) * 4;
#pragma unroll
    for (int c = 0; c < 4; c++) {
        const int ch = c0 + c;
        const u32 off = (u32)((row * STR + ch * 8) * 2);
        const size_t src = (size_t)(kbase + row) * DDIM + ch * 8;
        cpasync16(base + KH_O + off, khg + src);
        cpasync16(base + KL_O + off, klg + src);
        cpasync16(base + VH_O + off, vhg + src);
        cpasync16(base + VL_O + off, vlg + src);
    }
}

__global__ __launch_bounds__(128)
void attn_mma(const int* __restrict__ seq_len,
              u32* __restrict__ ctxh, u32* __restrict__ ctxl)
{
    extern __shared__ __align__(16) char sm[];
    const u32 sb = (u32)__cvta_generic_to_shared(sm);
    const int bh = blockIdx.y;
    const int b = bh >> 4;
    const int h = bh & (HDIM - 1);
    const int qt = (int)gridDim.x - 1 - (int)blockIdx.x;
    const int q0 = qt * 128;
    const int sl = seq_len[b];
    if (q0 >= sl) return;

    const int tid = threadIdx.x;
    const int lane = tid & 31;
    const int w = tid >> 5;
    const int wm = w * 32;
    const int g = lane >> 2;
    const int qd = lane & 3;

    const size_t hoff = (size_t)bh * LDIM * DDIM;
    const __nv_bfloat16* qhg = g_qh + hoff;
    const __nv_bfloat16* qlg = g_ql + hoff;
    const __nv_bfloat16* khg = g_kh + hoff;
    const __nv_bfloat16* klg = g_kl + hoff;
    const __nv_bfloat16* vhg = g_vh + hoff;
    const __nv_bfloat16* vlg = g_vl + hoff;

    {
        const int row = tid;
        const size_t src = (size_t)(q0 + row) * DDIM;
#pragma unroll
        for (int c = 0; c < 8; c++) {
            const u32 off = (u32)((row * STR + c * 8) * 2);
            cpasync16(sb + QH_OFF + off, qhg + src + c * 8);
            cpasync16(sb + QL_OFF + off, qlg + src + c * 8);
        }
    }
    attn_issue_kv(sb + ST_BASE, 0, tid, khg, klg, vhg, vlg);
    cp_commit();

    const int qend = min(q0 + 127, sl - 1);
    const int ntiles = (qend >> 6) + 1;

    float o[2][8][4];
    float mrow[4], lrow[4];
#pragma unroll
    for (int i = 0; i < 2; i++)
#pragma unroll
        for (int j = 0; j < 8; j++)
#pragma unroll
            for (int c = 0; c < 4; c++) o[i][j][c] = 0.f;
#pragma unroll
    for (int i = 0; i < 4; i++) { mrow[i] = -1e30f; lrow[i] = 0.f; }

    for (int t = 0; t < ntiles; t++) {
        if (t + 1 < ntiles) {
            attn_issue_kv(sb + ST_BASE + (u32)((t + 1) & 1) * ST_SZ, (t + 1) << 6,
                          tid, khg, klg, vhg, vlg);
            cp_commit();
            cp_wait1();
        } else {
            cp_wait0();
        }
        __syncthreads();

        const u32 kb_ = sb + ST_BASE + (u32)(t & 1) * ST_SZ;

        float s[2][8][4];
#pragma unroll
        for (int i = 0; i < 2; i++)
#pragma unroll
            for (int j = 0; j < 8; j++)
#pragma unroll
                for (int c = 0; c < 4; c++) s[i][j][c] = 0.f;

#pragma unroll
        for (int kf = 0; kf < 4; kf++) {
            u32 aqh[2][4], aql[2][4];
#pragma unroll
            for (int mf = 0; mf < 2; mf++) {
                const u32 ad = (u32)(((wm + mf * 16 + (lane & 15)) * STR
                                      + kf * 16 + (lane >> 4) * 8) * 2);
                ldsm4(aqh[mf][0], aqh[mf][1], aqh[mf][2], aqh[mf][3], sb + QH_OFF + ad);
                ldsm4(aql[mf][0], aql[mf][1], aql[mf][2], aql[mf][3], sb + QL_OFF + ad);
            }
#pragma unroll
            for (int p = 0; p < 4; p++) {
                const u32 kd = (u32)(((p * 16 + (lane & 15)) * STR
                                      + kf * 16 + (lane >> 4) * 8) * 2);
                u32 t0, t1, t2, t3;
                u32 bkh0[2], bkh1[2], bkl0[2], bkl1[2];
                ldsm4(t0, t1, t2, t3, kb_ + KH_O + kd);
                bkh0[0] = t0; bkh0[1] = t2; bkh1[0] = t1; bkh1[1] = t3;
                ldsm4(t0, t1, t2, t3, kb_ + KL_O + kd);
                bkl0[0] = t0; bkl0[1] = t2; bkl1[0] = t1; bkl1[1] = t3;
#pragma unroll
                for (int mf = 0; mf < 2; mf++) {
                    mma16816(s[mf][2 * p], aqh[mf], bkh0);
                    mma16816(s[mf][2 * p], aqh[mf], bkl0);
                    mma16816(s[mf][2 * p], aql[mf], bkh0);
                    mma16816(s[mf][2 * p + 1], aqh[mf], bkh1);
                    mma16816(s[mf][2 * p + 1], aqh[mf], bkl1);
                    mma16816(s[mf][2 * p + 1], aql[mf], bkh1);
                }
            }
        }

        const int kbase = t << 6;
#pragma unroll
        for (int mf = 0; mf < 2; mf++) {
#pragma unroll
            for (int hl = 0; hl < 2; hl++) {
                const int qi = q0 + wm + mf * 16 + g + hl * 8;
                const int idx = mf * 2 + hl;
                float mx = -1e30f;
#pragma unroll
                for (int nf = 0; nf < 8; nf++) {
                    const int c0 = kbase + nf * 8 + qd * 2;
                    float s0 = s[mf][nf][hl * 2];
                    float s1 = s[mf][nf][hl * 2 + 1];
                    if (c0 > qi) s0 = -1e30f;
                    if (c0 + 1 > qi) s1 = -1e30f;
                    s[mf][nf][hl * 2] = s0;
                    s[mf][nf][hl * 2 + 1] = s1;
                    mx = fmaxf(mx, fmaxf(s0, s1));
                }
                mx = fmaxf(mx, __shfl_xor_sync(0xffffffffu, mx, 1));
                mx = fmaxf(mx, __shfl_xor_sync(0xffffffffu, mx, 2));
                const float mnew = fmaxf(mrow[idx], mx);
                const float sc = __expf(mrow[idx] - mnew);
                mrow[idx] = mnew;
                float ps = 0.f;
#pragma unroll
                for (int nf = 0; nf < 8; nf++) {
                    float p0 = __expf(s[mf][nf][hl * 2] - mnew);
                    float p1 = __expf(s[mf][nf][hl * 2 + 1] - mnew);
                    s[mf][nf][hl * 2] = p0;
                    s[mf][nf][hl * 2 + 1] = p1;
                    ps += p0 + p1;
                    o[mf][nf][hl * 2] *= sc;
                    o[mf][nf][hl * 2 + 1] *= sc;
                }
                ps += __shfl_xor_sync(0xffffffffu, ps, 1);
                ps += __shfl_xor_sync(0xffffffffu, ps, 2);
                lrow[idx] = lrow[idx] * sc + ps;
            }
        }

#pragma unroll
        for (int kg = 0; kg < 4; kg++) {
            u32 aph[2][4], apl[2][4];
#pragma unroll
            for (int mf = 0; mf < 2; mf++) {
                aph[mf][0] = packbf(s[mf][2 * kg][0], s[mf][2 * kg][1]);
                aph[mf][1] = packbf(s[mf][2 * kg][2], s[mf][2 * kg][3]);
                aph[mf][2] = packbf(s[mf][2 * kg + 1][0], s[mf][2 * kg + 1][1]);
                aph[mf][3] = packbf(s[mf][2 * kg + 1][2], s[mf][2 * kg + 1][3]);
#pragma unroll
                for (int r = 0; r < 4; r++) {
                    const int nf = 2 * kg + (r >> 1);
                    const int cb = (r & 1) * 2;
                    apl[mf][r] = packbf(s[mf][nf][cb] - unlo(aph[mf][r]),
                                        s[mf][nf][cb + 1] - unhi(aph[mf][r]));
                }
            }
#pragma unroll
            for (int dp = 0; dp < 4; dp++) {
                const u32 vrow = (u32)(((kg * 16 + (lane & 7) + ((lane >> 3) & 1) * 8) * STR
                                        + dp * 16 + (lane >> 4) * 8) * 2);
                u32 t0, t1, t2, t3;
                u32 bvh0[2], bvh1[2], bvl0[2], bvl1[2];
                ldsm4t(t0, t1, t2, t3, kb_ + VH_O + vrow);
                bvh0[0] = t0; bvh0[1] = t1; bvh1[0] = t2; bvh1[1] = t3;
                ldsm4t(t0, t1, t2, t3, kb_ + VL_O + vrow);
                bvl0[0] = t0; bvl0[1] = t1; bvl1[0] = t2; bvl1[1] = t3;
#pragma unroll
                for (int mf = 0; mf < 2; mf++) {
                    mma16816(o[mf][2 * dp], aph[mf], bvh0);
                    mma16816(o[mf][2 * dp], aph[mf], bvl0);
                    mma16816(o[mf][2 * dp], apl[mf], bvh0);
                    mma16816(o[mf][2 * dp + 1], aph[mf], bvh1);
                    mma16816(o[mf][2 * dp + 1], aph[mf], bvl1);
                    mma16816(o[mf][2 * dp + 1], apl[mf], bvh1);
                }
            }
        }
        __syncthreads();
    }

#pragma unroll
    for (int mf = 0; mf < 2; mf++) {
#pragma unroll
        for (int hl = 0; hl < 2; hl++) {
            const int idx = mf * 2 + hl;
            const int qi = q0 + wm + mf * 16 + g + hl * 8;
            if (qi >= sl) continue;
            const float inv = 1.f / lrow[idx];
#pragma unroll
            for (int nf = 0; nf < 8; nf++) {
                const float o0 = o[mf][nf][hl * 2] * inv;
                const float o1 = o[mf][nf][hl * 2 + 1] * inv;
                const u32 hv = packbf(o0, o1);
                const u32 lv = packbf(o0 - unlo(hv), o1 - unhi(hv));
                const size_t e = ((size_t)(b * LDIM + qi) * EDIM)
                               + h * DDIM + nf * 8 + qd * 2;
                ctxh[e >> 1] = hv;
                ctxl[e >> 1] = lv;
            }
        }
    }
}

// ---------------------------------------------------------------------------
extern "C" void kernel_launch(void* const* d_in, const int* in_sizes, int n_in,
                              void* d_out, int out_size)
{
    const float* hs = (const float*)d_in[0];
    const int* sl   = (const int*)d_in[1];
    const float* Wq = (const float*)d_in[2];
    const float* bq = (const float*)d_in[3];
    const float* Wk = (const float*)d_in[4];
    const float* Wv = (const float*)d_in[5];
    const float* bv = (const float*)d_in[6];
    const float* Wo = (const float*)d_in[7];
    const float* bo = (const float*)d_in[8];
    float* out = (float*)d_out;

    __nv_bfloat16 *qh, *ql, *kh, *kl, *vh, *vl, *hsh, *hsl, *ctxh, *ctxl, *wh, *wl;
    float* mv;
    cudaGetSymbolAddress((void**)&qh, g_qh);
    cudaGetSymbolAddress((void**)&ql, g_ql);
    cudaGetSymbolAddress((void**)&kh, g_kh);
    cudaGetSymbolAddress((void**)&kl, g_kl);
    cudaGetSymbolAddress((void**)&vh, g_vh);
    cudaGetSymbolAddress((void**)&vl, g_vl);
    cudaGetSymbolAddress((void**)&hsh, g_hs_h);
    cudaGetSymbolAddress((void**)&hsl, g_hs_l);
    cudaGetSymbolAddress((void**)&ctxh, g_ctx_h);
    cudaGetSymbolAddress((void**)&ctxl, g_ctx_l);
    cudaGetSymbolAddress((void**)&wh, g_w_h);
    cudaGetSymbolAddress((void**)&wl, g_w_l);
    cudaGetSymbolAddress((void**)&mv, g_meanv);

    cudaFuncSetAttribute(gemm_bf16x3, cudaFuncAttributeMaxDynamicSharedMemorySize, G_SMEM);
    cudaFuncSetAttribute(attn_mma, cudaFuncAttributeMaxDynamicSharedMemorySize, ATT_SMEM);

    const int WSZ = EDIM * EDIM;
    split_f32<<<(MDIM * EDIM / 4 + 255) / 256, 256>>>(hs, hsh, hsl, MDIM * EDIM / 4);
    split_w4<<<4 * WSZ / 4 / 256, 256>>>(Wq, Wk, Wv, Wo, wh, wl);

    dim3 gg(EDIM / 256, MDIM / 128);    // (4, 32) = 128 CTAs = 1 wave
    gemm_bf16x3<<<gg, 512, G_SMEM>>>(hsh, hsl, wh + 0 * WSZ, wl + 0 * WSZ, bq, 0.125f,
                                     nullptr, (u32*)qh, (u32*)ql, 1);
    gemm_bf16x3<<<gg, 512, G_SMEM>>>(hsh, hsl, wh + 1 * WSZ, wl + 1 * WSZ, nullptr, 1.0f,
                                     nullptr, (u32*)kh, (u32*)kl, 1);
    gemm_bf16x3<<<gg, 512, G_SMEM>>>(hsh, hsl, wh + 2 * WSZ, wl + 2 * WSZ, bv, 1.0f,
                                     nullptr, (u32*)vh, (u32*)vl, 1);

    meanv_kernel<<<BDIM * HDIM, 256>>>(mv);
    fill_invalid<<<MDIM, 256>>>(sl, mv, (u32*)ctxh, (u32*)ctxl);

    dim3 ga(LDIM / 128, BDIM * HDIM);   // (16, 32)
    attn_mma<<<ga, 128, ATT_SMEM>>>(sl, (u32*)ctxh, (u32*)ctxl);

    gemm_bf16x3<<<gg, 512, G_SMEM>>>(ctxh, ctxl, wh + 3 * WSZ, wl + 3 * WSZ, bo, 1.0f,
                                     out, nullptr, nullptr, 0);
}

// round 9
// speedup vs baseline: 7.4566x; 2.1632x over previous
#include <cuda_runtime.h>
#include <cuda_fp16.h>
#include <cstdint>
#include <math.h>

typedef unsigned int u32;

#define BDIM 2
#define LDIM 2048
#define EDIM 1024
#define HDIM 16
#define DDIM 64
#define MDIM (BDIM * LDIM)   // 4096

// ---------------- scratch (device globals; allocation is forbidden) --------
__device__ __half g_q[BDIM * HDIM * LDIM * DDIM];   // [B,H,L,D]
__device__ __half g_k[BDIM * HDIM * LDIM * DDIM];
__device__ __half g_v[BDIM * HDIM * LDIM * DDIM];
__device__ __half g_hs[MDIM * EDIM];
__device__ __half g_ctx[MDIM * EDIM];               // [B,L,E]
__device__ __half g_w[4 * EDIM * EDIM];             // Wq,Wk,Wv,Wo
__device__ float g_meanv[BDIM * HDIM * DDIM];       // [B,H,D]

// ---------------------------------------------------------------------------
// helpers
// ---------------------------------------------------------------------------
__device__ __forceinline__ u32 packh(float lo, float hi) {
    u32 d;
    asm("cvt.rn.f16x2.f32 %0, %1, %2;" : "=r"(d) : "f"(hi), "f"(lo));
    return d;
}

__device__ __forceinline__ void cpasync16(u32 dst, const void* src) {
    asm volatile("cp.async.cg.shared.global [%0], [%1], 16;\n" :: "r"(dst), "l"(src));
}
__device__ __forceinline__ void cp_commit() { asm volatile("cp.async.commit_group;\n"); }
__device__ __forceinline__ void cp_wait1() { asm volatile("cp.async.wait_group 1;\n"); }
__device__ __forceinline__ void cp_wait0() { asm volatile("cp.async.wait_group 0;\n"); }

__device__ __forceinline__ void ldsm4(u32& r0, u32& r1, u32& r2, u32& r3, u32 addr) {
    asm volatile("ldmatrix.sync.aligned.m8n8.x4.shared.b16 {%0,%1,%2,%3}, [%4];"
        : "=r"(r0), "=r"(r1), "=r"(r2), "=r"(r3) : "r"(addr));
}
__device__ __forceinline__ void ldsm4t(u32& r0, u32& r1, u32& r2, u32& r3, u32 addr) {
    asm volatile("ldmatrix.sync.aligned.m8n8.x4.trans.shared.b16 {%0,%1,%2,%3}, [%4];"
        : "=r"(r0), "=r"(r1), "=r"(r2), "=r"(r3) : "r"(addr));
}
__device__ __forceinline__ void mma16816(float* acc, const u32* a, const u32* b) {
    asm volatile("mma.sync.aligned.m16n8k16.row.col.f32.f16.f16.f32 "
        "{%0,%1,%2,%3}, {%4,%5,%6,%7}, {%8,%9}, {%0,%1,%2,%3};"
        : "+f"(acc[0]), "+f"(acc[1]), "+f"(acc[2]), "+f"(acc[3])
        : "r"(a[0]), "r"(a[1]), "r"(a[2]), "r"(a[3]), "r"(b[0]), "r"(b[1]));
}

// ---------------------------------------------------------------------------
// Convert fp32 -> fp16
// ---------------------------------------------------------------------------
__global__ __launch_bounds__(256)
void conv_f32(const float* __restrict__ x, __half* __restrict__ o, int n4)
{
    int i = blockIdx.x * blockDim.x + threadIdx.x;
    if (i >= n4) return;
    float4 v = ((const float4*)x)[i];
    uint2 hv;
    hv.x = packh(v.x, v.y);
    hv.y = packh(v.z, v.w);
    ((uint2*)o)[i] = hv;
}

__global__ __launch_bounds__(256)
void conv_w4(const float* __restrict__ w0, const float* __restrict__ w1,
             const float* __restrict__ w2, const float* __restrict__ w3,
             __half* __restrict__ o)
{
    const int n4 = EDIM * EDIM / 4;
    int i = blockIdx.x * blockDim.x + threadIdx.x;
    const int m = i / n4;
    const int j = i - m * n4;
    const float* src = (m == 0) ? w0 : (m == 1) ? w1 : (m == 2) ? w2 : w3;
    float4 v = ((const float4*)src)[j];
    uint2 hv;
    hv.x = packh(v.x, v.y);
    hv.y = packh(v.z, v.w);
    ((uint2*)o)[i] = hv;
}

// ---------------------------------------------------------------------------
// mean(V) over all L rows per (b,h,d)  -> g_meanv
// ---------------------------------------------------------------------------
__global__ __launch_bounds__(256)
void meanv_kernel(float* __restrict__ mv)
{
    __shared__ float red[256];
    const int bh = blockIdx.x;
    const int tid = threadIdx.x;
    const int d = tid & 63;
    const int seg = tid >> 6;
    const __half* vb = g_v + (size_t)bh * LDIM * DDIM;
    float s = 0.f;
    for (int l = seg * 512; l < (seg + 1) * 512; l++)
        s += __half2float(vb[(size_t)l * DDIM + d]);
    red[tid] = s;
    __syncthreads();
    if (tid < 64)
        mv[bh * 64 + d] = (red[d] + red[64 + d] + red[128 + d] + red[192 + d])
                          * (1.0f / 2048.0f);
}

// ---------------------------------------------------------------------------
// Fill ctx rows for invalid queries (l >= seq_len[b]) with mean(V)
// ---------------------------------------------------------------------------
__global__ __launch_bounds__(256)
void fill_invalid(const int* __restrict__ seq_len, const float* __restrict__ mv,
                  u32* __restrict__ ctx)
{
    const int r = blockIdx.x;
    const int b = r >> 11;
    const int l = r & (LDIM - 1);
    if (l < seq_len[b]) return;
    const int tid = threadIdx.x;
#pragma unroll
    for (int it = 0; it < 2; it++) {
        const int idx = tid + it * 256;          // pair index 0..511
        const int col = idx * 2;
        ctx[(size_t)r * 512 + idx] = packh(mv[b * 1024 + col], mv[b * 1024 + col + 1]);
    }
}

// ---------------------------------------------------------------------------
// fp16 single-pass tensor-core NT GEMM.
// Tile 128(M) x 256(N), BK=32, 3-stage cp.async, 512 thr / 16 warps (4Mx4N),
// warp tile 32x64. Grid = 128 CTAs = 1 wave.
// ---------------------------------------------------------------------------
#define SSTR 40                           // smem row stride in fp16 (80 B)
#define A_ARR (128 * SSTR * 2)            // 10240 B
#define B_ARR (256 * SSTR * 2)            // 20480 B
#define O_A 0
#define O_B A_ARR
#define STG (A_ARR + B_ARR)               // 30720 B
#define G_SMEM (3 * STG)                  // 92160 B

__device__ __forceinline__ void g_issue(
    u32 sbase, int s, int k0, int tid,
    const __half* A, const __half* B, int bm, int bn)
{
    const u32 st = sbase + (u32)(s % 3) * STG;
    // A: 512 16B-chunks (128 rows x 4), one per thread
    {
        const int row = tid >> 2, ch = tid & 3;
        const u32 so = (u32)(row * (SSTR * 2) + ch * 16);
        cpasync16(st + O_A + so, A + (size_t)(bm + row) * EDIM + k0 + ch * 8);
    }
    // B: 1024 chunks (256 rows x 4), two per thread
#pragma unroll
    for (int i = 0; i < 2; i++) {
        const int c = tid + i * 512;
        const int row = c >> 2, ch = c & 3;
        const u32 so = (u32)(row * (SSTR * 2) + ch * 16);
        cpasync16(st + O_B + so, B + (size_t)(bn + row) * EDIM + k0 + ch * 8);
    }
    cp_commit();
}

extern "C" __global__ __launch_bounds__(512, 1)
void gemm_h(const __half* __restrict__ Ag, const __half* __restrict__ Bg,
            const float* __restrict__ bias, float alpha,
            float* __restrict__ out, u32* __restrict__ outq, int mapQKV)
{
    extern __shared__ __align__(16) char dynsmem[];
    const u32 sbase = (u32)__cvta_generic_to_shared(dynsmem);
    const int bm = blockIdx.y * 128;
    const int bn = blockIdx.x * 256;
    const int tid = threadIdx.x;
    const int lane = tid & 31;
    const int wid = tid >> 5;
    const int wm = (wid & 3) * 32;        // 4 warps along M
    const int wn = (wid >> 2) * 64;       // 4 warps along N

    float acc[2][8][4];
#pragma unroll
    for (int i = 0; i < 2; i++)
#pragma unroll
        for (int j = 0; j < 8; j++)
#pragma unroll
            for (int c = 0; c < 4; c++) acc[i][j][c] = 0.f;

    const int lrA = wm + (lane & 15);
    const int lrB = wn + (lane & 15);
    const int lcol = (lane >> 4) * 8;

    const int NIT = EDIM / 32;            // 32
    g_issue(sbase, 0, 0, tid, Ag, Bg, bm, bn);
    g_issue(sbase, 1, 32, tid, Ag, Bg, bm, bn);

    for (int it = 0; it < NIT; it++) {
        if (it + 1 < NIT) cp_wait1(); else cp_wait0();
        __syncthreads();
        if (it + 2 < NIT)
            g_issue(sbase, it + 2, (it + 2) * 32, tid, Ag, Bg, bm, bn);

        const u32 st = sbase + (u32)(it % 3) * STG;
#pragma unroll
        for (int ks = 0; ks < 2; ks++) {
            const int kb = ks * 16;
            u32 ah[2][4];
#pragma unroll
            for (int mt = 0; mt < 2; mt++) {
                const u32 ad = st + O_A + (u32)((lrA + mt * 16) * SSTR + kb + lcol) * 2;
                ldsm4(ah[mt][0], ah[mt][1], ah[mt][2], ah[mt][3], ad);
            }
#pragma unroll
            for (int p = 0; p < 4; p++) {
                const u32 bd = st + O_B + (u32)((lrB + p * 16) * SSTR + kb + lcol) * 2;
                u32 t0, t1, t2, t3;
                u32 b0[2], b1[2];
                ldsm4(t0, t1, t2, t3, bd);
                b0[0] = t0; b0[1] = t2; b1[0] = t1; b1[1] = t3;
#pragma unroll
                for (int mt = 0; mt < 2; mt++) {
                    mma16816(acc[mt][2 * p], ah[mt], b0);
                    mma16816(acc[mt][2 * p + 1], ah[mt], b1);
                }
            }
        }
        __syncthreads();
    }

    // ----- epilogue -----
#pragma unroll
    for (int mt = 0; mt < 2; mt++) {
#pragma unroll
        for (int nt = 0; nt < 8; nt++) {
#pragma unroll
            for (int r = 0; r < 2; r++) {
                const int row = bm + wm + mt * 16 + (lane >> 2) + r * 8;
                const int col0 = bn + wn + nt * 8 + (lane & 3) * 2;
                float v0 = acc[mt][nt][r * 2 + 0];
                float v1 = acc[mt][nt][r * 2 + 1];
                if (bias) { v0 += bias[col0]; v1 += bias[col0 + 1]; }
                v0 *= alpha; v1 *= alpha;
                const int b = row >> 11;
                const int l = row & (LDIM - 1);
                if (mapQKV) {
                    const int h = col0 >> 6;
                    const int d = col0 & (DDIM - 1);
                    const size_t e = (((size_t)(b * HDIM + h) * LDIM) + l) * DDIM + d;
                    outq[e >> 1] = packh(v0, v1);
                } else {
                    out[(size_t)row * EDIM + col0] = v0;
                    out[(size_t)row * EDIM + col0 + 1] = v1;
                }
            }
        }
    }
}

// ---------------------------------------------------------------------------
// fp16 tensor-core flash attention, valid rows only. Structure identical to
// round-8 validated kernel; single-precision-pass MMAs.
// ---------------------------------------------------------------------------
#define STR 72
#define Q_OFF 0
#define ST_BASE (128 * STR * 2)           // 18432
#define KT_B (64 * STR * 2)               // 9216
#define K_O 0
#define V_O KT_B
#define ST_SZ (2 * KT_B)                  // 18432
#define ATT_SMEM (ST_BASE + 2 * ST_SZ)    // 55296

__device__ __forceinline__ void attn_issue_kv(u32 base, int kbase, int tid,
                                              const __half* kg, const __half* vg)
{
    const int row = tid >> 1;
    const int c0 = (tid & 1) * 4;
#pragma unroll
    for (int c = 0; c < 4; c++) {
        const int ch = c0 + c;
        const u32 off = (u32)((row * STR + ch * 8) * 2);
        const size_t src = (size_t)(kbase + row) * DDIM + ch * 8;
        cpasync16(base + K_O + off, kg + src);
        cpasync16(base + V_O + off, vg + src);
    }
}

__global__ __launch_bounds__(128)
void attn_mma(const int* __restrict__ seq_len, u32* __restrict__ ctx)
{
    extern __shared__ __align__(16) char sm[];
    const u32 sb = (u32)__cvta_generic_to_shared(sm);
    const int bh = blockIdx.y;
    const int b = bh >> 4;
    const int h = bh & (HDIM - 1);
    const int qt = (int)gridDim.x - 1 - (int)blockIdx.x;   // heavy blocks first
    const int q0 = qt * 128;
    const int sl = seq_len[b];
    if (q0 >= sl) return;

    const int tid = threadIdx.x;
    const int lane = tid & 31;
    const int w = tid >> 5;
    const int wm = w * 32;
    const int g = lane >> 2;
    const int qd = lane & 3;

    const size_t hoff = (size_t)bh * LDIM * DDIM;
    const __half* qg = g_q + hoff;
    const __half* kg = g_k + hoff;
    const __half* vg = g_v + hoff;

    {
        const int row = tid;
        const size_t src = (size_t)(q0 + row) * DDIM;
#pragma unroll
        for (int c = 0; c < 8; c++)
            cpasync16(sb + Q_OFF + (u32)((row * STR + c * 8) * 2), qg + src + c * 8);
    }
    attn_issue_kv(sb + ST_BASE, 0, tid, kg, vg);
    cp_commit();

    const int qend = min(q0 + 127, sl - 1);
    const int ntiles = (qend >> 6) + 1;

    float o[2][8][4];
    float mrow[4], lrow[4];
#pragma unroll
    for (int i = 0; i < 2; i++)
#pragma unroll
        for (int j = 0; j < 8; j++)
#pragma unroll
            for (int c = 0; c < 4; c++) o[i][j][c] = 0.f;
#pragma unroll
    for (int i = 0; i < 4; i++) { mrow[i] = -1e30f; lrow[i] = 0.f; }

    for (int t = 0; t < ntiles; t++) {
        if (t + 1 < ntiles) {
            attn_issue_kv(sb + ST_BASE + (u32)((t + 1) & 1) * ST_SZ, (t + 1) << 6,
                          tid, kg, vg);
            cp_commit();
            cp_wait1();
        } else {
            cp_wait0();
        }
        __syncthreads();

        const u32 kb_ = sb + ST_BASE + (u32)(t & 1) * ST_SZ;

        // ----- S = Q K^T (fp16 single pass) -----
        float s[2][8][4];
#pragma unroll
        for (int i = 0; i < 2; i++)
#pragma unroll
            for (int j = 0; j < 8; j++)
#pragma unroll
                for (int c = 0; c < 4; c++) s[i][j][c] = 0.f;

#pragma unroll
        for (int kf = 0; kf < 4; kf++) {
            u32 aq[2][4];
#pragma unroll
            for (int mf = 0; mf < 2; mf++) {
                const u32 ad = sb + Q_OFF + (u32)(((wm + mf * 16 + (lane & 15)) * STR
                                      + kf * 16 + (lane >> 4) * 8) * 2);
                ldsm4(aq[mf][0], aq[mf][1], aq[mf][2], aq[mf][3], ad);
            }
#pragma unroll
            for (int p = 0; p < 4; p++) {
                const u32 kd = kb_ + K_O + (u32)(((p * 16 + (lane & 15)) * STR
                                      + kf * 16 + (lane >> 4) * 8) * 2);
                u32 t0, t1, t2, t3;
                u32 bk0[2], bk1[2];
                ldsm4(t0, t1, t2, t3, kd);
                bk0[0] = t0; bk0[1] = t2; bk1[0] = t1; bk1[1] = t3;
#pragma unroll
                for (int mf = 0; mf < 2; mf++) {
                    mma16816(s[mf][2 * p], aq[mf], bk0);
                    mma16816(s[mf][2 * p + 1], aq[mf], bk1);
                }
            }
        }

        // ----- causal mask + online softmax -----
        const int kbase = t << 6;
#pragma unroll
        for (int mf = 0; mf < 2; mf++) {
#pragma unroll
            for (int hl = 0; hl < 2; hl++) {
                const int qi = q0 + wm + mf * 16 + g + hl * 8;
                const int idx = mf * 2 + hl;
                float mx = -1e30f;
#pragma unroll
                for (int nf = 0; nf < 8; nf++) {
                    const int c0 = kbase + nf * 8 + qd * 2;
                    float s0 = s[mf][nf][hl * 2];
                    float s1 = s[mf][nf][hl * 2 + 1];
                    if (c0 > qi) s0 = -1e30f;
                    if (c0 + 1 > qi) s1 = -1e30f;
                    s[mf][nf][hl * 2] = s0;
                    s[mf][nf][hl * 2 + 1] = s1;
                    mx = fmaxf(mx, fmaxf(s0, s1));
                }
                mx = fmaxf(mx, __shfl_xor_sync(0xffffffffu, mx, 1));
                mx = fmaxf(mx, __shfl_xor_sync(0xffffffffu, mx, 2));
                const float mnew = fmaxf(mrow[idx], mx);
                const float sc = __expf(mrow[idx] - mnew);
                mrow[idx] = mnew;
                float ps = 0.f;
#pragma unroll
                for (int nf = 0; nf < 8; nf++) {
                    float p0 = __expf(s[mf][nf][hl * 2] - mnew);
                    float p1 = __expf(s[mf][nf][hl * 2 + 1] - mnew);
                    s[mf][nf][hl * 2] = p0;
                    s[mf][nf][hl * 2 + 1] = p1;
                    ps += p0 + p1;
                    o[mf][nf][hl * 2] *= sc;
                    o[mf][nf][hl * 2 + 1] *= sc;
                }
                ps += __shfl_xor_sync(0xffffffffu, ps, 1);
                ps += __shfl_xor_sync(0xffffffffu, ps, 2);
                lrow[idx] = lrow[idx] * sc + ps;
            }
        }

        // ----- O += P V (fp16 single pass) -----
#pragma unroll
        for (int kg2 = 0; kg2 < 4; kg2++) {
            u32 ap[2][4];
#pragma unroll
            for (int mf = 0; mf < 2; mf++) {
                ap[mf][0] = packh(s[mf][2 * kg2][0], s[mf][2 * kg2][1]);
                ap[mf][1] = packh(s[mf][2 * kg2][2], s[mf][2 * kg2][3]);
                ap[mf][2] = packh(s[mf][2 * kg2 + 1][0], s[mf][2 * kg2 + 1][1]);
                ap[mf][3] = packh(s[mf][2 * kg2 + 1][2], s[mf][2 * kg2 + 1][3]);
            }
#pragma unroll
            for (int dp = 0; dp < 4; dp++) {
                const u32 vrow = kb_ + V_O
                    + (u32)(((kg2 * 16 + (lane & 7) + ((lane >> 3) & 1) * 8) * STR
                             + dp * 16 + (lane >> 4) * 8) * 2);
                u32 t0, t1, t2, t3;
                u32 bv0[2], bv1[2];
                ldsm4t(t0, t1, t2, t3, vrow);
                bv0[0] = t0; bv0[1] = t1; bv1[0] = t2; bv1[1] = t3;
#pragma unroll
                for (int mf = 0; mf < 2; mf++) {
                    mma16816(o[mf][2 * dp], ap[mf], bv0);
                    mma16816(o[mf][2 * dp + 1], ap[mf], bv1);
                }
            }
        }
        __syncthreads();
    }

    // ----- epilogue: write VALID rows only (fp16 ctx) -----
#pragma unroll
    for (int mf = 0; mf < 2; mf++) {
#pragma unroll
        for (int hl = 0; hl < 2; hl++) {
            const int idx = mf * 2 + hl;
            const int qi = q0 + wm + mf * 16 + g + hl * 8;
            if (qi >= sl) continue;
            const float inv = 1.f / lrow[idx];
#pragma unroll
            for (int nf = 0; nf < 8; nf++) {
                const float o0 = o[mf][nf][hl * 2] * inv;
                const float o1 = o[mf][nf][hl * 2 + 1] * inv;
                const size_t e = ((size_t)(b * LDIM + qi) * EDIM)
                               + h * DDIM + nf * 8 + qd * 2;
                ctx[e >> 1] = packh(o0, o1);
            }
        }
    }
}

// ---------------------------------------------------------------------------
extern "C" void kernel_launch(void* const* d_in, const int* in_sizes, int n_in,
                              void* d_out, int out_size)
{
    const float* hs = (const float*)d_in[0];
    const int* sl   = (const int*)d_in[1];
    const float* Wq = (const float*)d_in[2];
    const float* bq = (const float*)d_in[3];
    const float* Wk = (const float*)d_in[4];
    const float* Wv = (const float*)d_in[5];
    const float* bv = (const float*)d_in[6];
    const float* Wo = (const float*)d_in[7];
    const float* bo = (const float*)d_in[8];
    float* out = (float*)d_out;

    __half *q, *k, *v, *hsx, *ctx, *wx;
    float* mv;
    cudaGetSymbolAddress((void**)&q, g_q);
    cudaGetSymbolAddress((void**)&k, g_k);
    cudaGetSymbolAddress((void**)&v, g_v);
    cudaGetSymbolAddress((void**)&hsx, g_hs);
    cudaGetSymbolAddress((void**)&ctx, g_ctx);
    cudaGetSymbolAddress((void**)&wx, g_w);
    cudaGetSymbolAddress((void**)&mv, g_meanv);

    cudaFuncSetAttribute(gemm_h, cudaFuncAttributeMaxDynamicSharedMemorySize, G_SMEM);
    cudaFuncSetAttribute(attn_mma, cudaFuncAttributeMaxDynamicSharedMemorySize, ATT_SMEM);

    const int WSZ = EDIM * EDIM;
    conv_f32<<<(MDIM * EDIM / 4 + 255) / 256, 256>>>(hs, hsx, MDIM * EDIM / 4);
    conv_w4<<<4 * WSZ / 4 / 256, 256>>>(Wq, Wk, Wv, Wo, wx);

    dim3 gg(EDIM / 256, MDIM / 128);    // (4, 32) = 128 CTAs = 1 wave
    gemm_h<<<gg, 512, G_SMEM>>>(hsx, wx + 0 * WSZ, bq, 0.125f, nullptr, (u32*)q, 1);
    gemm_h<<<gg, 512, G_SMEM>>>(hsx, wx + 1 * WSZ, nullptr, 1.0f, nullptr, (u32*)k, 1);
    gemm_h<<<gg, 512, G_SMEM>>>(hsx, wx + 2 * WSZ, bv, 1.0f, nullptr, (u32*)v, 1);

    meanv_kernel<<<BDIM * HDIM, 256>>>(mv);
    fill_invalid<<<MDIM, 256>>>(sl, mv, (u32*)ctx);

    dim3 ga(LDIM / 128, BDIM * HDIM);   // (16, 32)
    attn_mma<<<ga, 128, ATT_SMEM>>>(sl, (u32*)ctx);

    gemm_h<<<gg, 512, G_SMEM>>>(ctx, wx + 3 * WSZ, bo, 1.0f, out, nullptr, 0);
}

// round 10
// speedup vs baseline: 8.1544x; 1.0936x over previous
#include <cuda_runtime.h>
#include <cuda_fp16.h>
#include <cstdint>
#include <math.h>

typedef unsigned int u32;

#define BDIM 2
#define LDIM 2048
#define EDIM 1024
#define HDIM 16
#define DDIM 64
#define MDIM (BDIM * LDIM)   // 4096

// ---------------- scratch (device globals; allocation is forbidden) --------
__device__ __half g_q[BDIM * HDIM * LDIM * DDIM];   // [B,H,L,D]
__device__ __half g_k[BDIM * HDIM * LDIM * DDIM];
__device__ __half g_v[BDIM * HDIM * LDIM * DDIM];
__device__ __half g_hs[MDIM * EDIM];
__device__ __half g_ctx[MDIM * EDIM];               // [B,L,E]
__device__ __half g_w[4 * EDIM * EDIM];             // Wq,Wk,Wv,Wo
__device__ float g_meanv[BDIM * HDIM * DDIM];       // [B,H,D]

// ---------------------------------------------------------------------------
// helpers
// ---------------------------------------------------------------------------
__device__ __forceinline__ u32 packh(float lo, float hi) {
    u32 d;
    asm("cvt.rn.f16x2.f32 %0, %1, %2;" : "=r"(d) : "f"(hi), "f"(lo));
    return d;
}

__device__ __forceinline__ void cpasync16(u32 dst, const void* src) {
    asm volatile("cp.async.cg.shared.global [%0], [%1], 16;\n" :: "r"(dst), "l"(src));
}
__device__ __forceinline__ void cp_commit() { asm volatile("cp.async.commit_group;\n"); }
__device__ __forceinline__ void cp_wait1() { asm volatile("cp.async.wait_group 1;\n"); }
__device__ __forceinline__ void cp_wait0() { asm volatile("cp.async.wait_group 0;\n"); }

__device__ __forceinline__ void ldsm4(u32& r0, u32& r1, u32& r2, u32& r3, u32 addr) {
    asm volatile("ldmatrix.sync.aligned.m8n8.x4.shared.b16 {%0,%1,%2,%3}, [%4];"
        : "=r"(r0), "=r"(r1), "=r"(r2), "=r"(r3) : "r"(addr));
}
__device__ __forceinline__ void ldsm4t(u32& r0, u32& r1, u32& r2, u32& r3, u32 addr) {
    asm volatile("ldmatrix.sync.aligned.m8n8.x4.trans.shared.b16 {%0,%1,%2,%3}, [%4];"
        : "=r"(r0), "=r"(r1), "=r"(r2), "=r"(r3) : "r"(addr));
}
__device__ __forceinline__ void mma16816(float* acc, const u32* a, const u32* b) {
    asm volatile("mma.sync.aligned.m16n8k16.row.col.f32.f16.f16.f32 "
        "{%0,%1,%2,%3}, {%4,%5,%6,%7}, {%8,%9}, {%0,%1,%2,%3};"
        : "+f"(acc[0]), "+f"(acc[1]), "+f"(acc[2]), "+f"(acc[3])
        : "r"(a[0]), "r"(a[1]), "r"(a[2]), "r"(a[3]), "r"(b[0]), "r"(b[1]));
}

// ---------------------------------------------------------------------------
// Convert fp32 -> fp16
// ---------------------------------------------------------------------------
__global__ __launch_bounds__(256)
void conv_f32(const float* __restrict__ x, __half* __restrict__ o, int n4)
{
    int i = blockIdx.x * blockDim.x + threadIdx.x;
    if (i >= n4) return;
    float4 v = ((const float4*)x)[i];
    uint2 hv;
    hv.x = packh(v.x, v.y);
    hv.y = packh(v.z, v.w);
    ((uint2*)o)[i] = hv;
}

__global__ __launch_bounds__(256)
void conv_w4(const float* __restrict__ w0, const float* __restrict__ w1,
             const float* __restrict__ w2, const float* __restrict__ w3,
             __half* __restrict__ o)
{
    const int n4 = EDIM * EDIM / 4;
    int i = blockIdx.x * blockDim.x + threadIdx.x;
    const int m = i / n4;
    const int j = i - m * n4;
    const float* src = (m == 0) ? w0 : (m == 1) ? w1 : (m == 2) ? w2 : w3;
    float4 v = ((const float4*)src)[j];
    uint2 hv;
    hv.x = packh(v.x, v.y);
    hv.y = packh(v.z, v.w);
    ((uint2*)o)[i] = hv;
}

// ---------------------------------------------------------------------------
// mean(V) over all L rows per (b,h,d)  -> g_meanv
// ---------------------------------------------------------------------------
__global__ __launch_bounds__(256)
void meanv_kernel(float* __restrict__ mv)
{
    __shared__ float red[256];
    const int bh = blockIdx.x;
    const int tid = threadIdx.x;
    const int d = tid & 63;
    const int seg = tid >> 6;
    const __half* vb = g_v + (size_t)bh * LDIM * DDIM;
    float s = 0.f;
    for (int l = seg * 512; l < (seg + 1) * 512; l++)
        s += __half2float(vb[(size_t)l * DDIM + d]);
    red[tid] = s;
    __syncthreads();
    if (tid < 64)
        mv[bh * 64 + d] = (red[d] + red[64 + d] + red[128 + d] + red[192 + d])
                          * (1.0f / 2048.0f);
}

// ---------------------------------------------------------------------------
// Fill ctx rows for invalid queries (l >= seq_len[b]) with mean(V)
// ---------------------------------------------------------------------------
__global__ __launch_bounds__(256)
void fill_invalid(const int* __restrict__ seq_len, const float* __restrict__ mv,
                  u32* __restrict__ ctx)
{
    const int r = blockIdx.x;
    const int b = r >> 11;
    const int l = r & (LDIM - 1);
    if (l < seq_len[b]) return;
    const int tid = threadIdx.x;
#pragma unroll
    for (int it = 0; it < 2; it++) {
        const int idx = tid + it * 256;
        const int col = idx * 2;
        ctx[(size_t)r * 512 + idx] = packh(mv[b * 1024 + col], mv[b * 1024 + col + 1]);
    }
}

// ---------------------------------------------------------------------------
// fp16 tensor-core NT GEMM, fused-QKV capable.
// Tile 128(M) x 256(N), BK=64, 3-stage cp.async, 512 thr / 16 warps (4Mx4N),
// warp tile 32x64. QKV mode: grid (4,32,3), z selects projection.
// ---------------------------------------------------------------------------
#define SSTR 72                           // smem row stride in fp16 (144 B)
#define A_ARR (128 * SSTR * 2)            // 18432 B
#define B_ARR (256 * SSTR * 2)            // 36864 B
#define O_A 0
#define O_B A_ARR
#define STG (A_ARR + B_ARR)               // 55296 B
#define G_SMEM (3 * STG)                  // 165888 B
#define WSZ (EDIM * EDIM)

__device__ __forceinline__ void g_issue(
    u32 sbase, int s, int k0, int tid,
    const __half* A, const __half* B, int bm, int bn)
{
    const u32 st = sbase + (u32)(s % 3) * STG;
    // A: 1024 16B-chunks (128 rows x 8), two per thread
#pragma unroll
    for (int i = 0; i < 2; i++) {
        const int c = tid + i * 512;
        const int row = c >> 3, ch = c & 7;
        const u32 so = (u32)(row * (SSTR * 2) + ch * 16);
        cpasync16(st + O_A + so, A + (size_t)(bm + row) * EDIM + k0 + ch * 8);
    }
    // B: 2048 chunks (256 rows x 8), four per thread
#pragma unroll
    for (int i = 0; i < 4; i++) {
        const int c = tid + i * 512;
        const int row = c >> 3, ch = c & 7;
        const u32 so = (u32)(row * (SSTR * 2) + ch * 16);
        cpasync16(st + O_B + so, B + (size_t)(bn + row) * EDIM + k0 + ch * 8);
    }
    cp_commit();
}

extern "C" __global__ __launch_bounds__(512, 1)
void gemm_h(const __half* __restrict__ Ag, const __half* __restrict__ Wbase,
            const float* __restrict__ b0, const float* __restrict__ b2,
            float* __restrict__ out,
            u32* __restrict__ o0, u32* __restrict__ o1, u32* __restrict__ o2,
            int fused)
{
    extern __shared__ __align__(16) char dynsmem[];
    const u32 sbase = (u32)__cvta_generic_to_shared(dynsmem);
    const int bm = blockIdx.y * 128;
    const int bn = blockIdx.x * 256;
    const int z = blockIdx.z;
    const int tid = threadIdx.x;
    const int lane = tid & 31;
    const int wid = tid >> 5;
    const int wm = (wid & 3) * 32;
    const int wn = (wid >> 2) * 64;

    const __half* Bg = Wbase + (size_t)z * WSZ;
    const float* bias;
    float alpha;
    u32* outq;
    if (fused) {
        bias = (z == 0) ? b0 : ((z == 2) ? b2 : nullptr);
        alpha = (z == 0) ? 0.125f : 1.0f;
        outq = (z == 0) ? o0 : ((z == 1) ? o1 : o2);
    } else {
        bias = b0; alpha = 1.0f; outq = nullptr;
    }

    float acc[2][8][4];
#pragma unroll
    for (int i = 0; i < 2; i++)
#pragma unroll
        for (int j = 0; j < 8; j++)
#pragma unroll
            for (int c = 0; c < 4; c++) acc[i][j][c] = 0.f;

    const int lrA = wm + (lane & 15);
    const int lrB = wn + (lane & 15);
    const int lcol = (lane >> 4) * 8;

    const int NIT = EDIM / 64;            // 16
    g_issue(sbase, 0, 0, tid, Ag, Bg, bm, bn);
    g_issue(sbase, 1, 64, tid, Ag, Bg, bm, bn);

    for (int it = 0; it < NIT; it++) {
        if (it + 1 < NIT) cp_wait1(); else cp_wait0();
        __syncthreads();
        if (it + 2 < NIT)
            g_issue(sbase, it + 2, (it + 2) * 64, tid, Ag, Bg, bm, bn);

        const u32 st = sbase + (u32)(it % 3) * STG;
#pragma unroll
        for (int ks = 0; ks < 4; ks++) {
            const int kb = ks * 16;
            u32 ah[2][4];
#pragma unroll
            for (int mt = 0; mt < 2; mt++) {
                const u32 ad = st + O_A + (u32)((lrA + mt * 16) * SSTR + kb + lcol) * 2;
                ldsm4(ah[mt][0], ah[mt][1], ah[mt][2], ah[mt][3], ad);
            }
#pragma unroll
            for (int p = 0; p < 4; p++) {
                const u32 bd = st + O_B + (u32)((lrB + p * 16) * SSTR + kb + lcol) * 2;
                u32 t0, t1, t2, t3;
                u32 b0r[2], b1r[2];
                ldsm4(t0, t1, t2, t3, bd);
                b0r[0] = t0; b0r[1] = t2; b1r[0] = t1; b1r[1] = t3;
#pragma unroll
                for (int mt = 0; mt < 2; mt++) {
                    mma16816(acc[mt][2 * p], ah[mt], b0r);
                    mma16816(acc[mt][2 * p + 1], ah[mt], b1r);
                }
            }
        }
        __syncthreads();
    }

    // ----- epilogue -----
#pragma unroll
    for (int mt = 0; mt < 2; mt++) {
#pragma unroll
        for (int nt = 0; nt < 8; nt++) {
#pragma unroll
            for (int r = 0; r < 2; r++) {
                const int row = bm + wm + mt * 16 + (lane >> 2) + r * 8;
                const int col0 = bn + wn + nt * 8 + (lane & 3) * 2;
                float v0 = acc[mt][nt][r * 2 + 0];
                float v1 = acc[mt][nt][r * 2 + 1];
                if (bias) { v0 += bias[col0]; v1 += bias[col0 + 1]; }
                v0 *= alpha; v1 *= alpha;
                const int b = row >> 11;
                const int l = row & (LDIM - 1);
                if (fused) {
                    const int h = col0 >> 6;
                    const int d = col0 & (DDIM - 1);
                    const size_t e = (((size_t)(b * HDIM + h) * LDIM) + l) * DDIM + d;
                    outq[e >> 1] = packh(v0, v1);
                } else {
                    out[(size_t)row * EDIM + col0] = v0;
                    out[(size_t)row * EDIM + col0 + 1] = v1;
                }
            }
        }
    }
}

// ---------------------------------------------------------------------------
// fp16 tensor-core flash attention, valid rows only (round-9 validated).
// ---------------------------------------------------------------------------
#define STR 72
#define Q_OFF 0
#define ST_BASE (128 * STR * 2)           // 18432
#define KT_B (64 * STR * 2)               // 9216
#define K_O 0
#define V_O KT_B
#define ST_SZ (2 * KT_B)                  // 18432
#define ATT_SMEM (ST_BASE + 2 * ST_SZ)    // 55296

__device__ __forceinline__ void attn_issue_kv(u32 base, int kbase, int tid,
                                              const __half* kg, const __half* vg)
{
    const int row = tid >> 1;
    const int c0 = (tid & 1) * 4;
#pragma unroll
    for (int c = 0; c < 4; c++) {
        const int ch = c0 + c;
        const u32 off = (u32)((row * STR + ch * 8) * 2);
        const size_t src = (size_t)(kbase + row) * DDIM + ch * 8;
        cpasync16(base + K_O + off, kg + src);
        cpasync16(base + V_O + off, vg + src);
    }
}

__global__ __launch_bounds__(128)
void attn_mma(const int* __restrict__ seq_len, u32* __restrict__ ctx)
{
    extern __shared__ __align__(16) char sm[];
    const u32 sb = (u32)__cvta_generic_to_shared(sm);
    const int bh = blockIdx.y;
    const int b = bh >> 4;
    const int h = bh & (HDIM - 1);
    const int qt = (int)gridDim.x - 1 - (int)blockIdx.x;
    const int q0 = qt * 128;
    const int sl = seq_len[b];
    if (q0 >= sl) return;

    const int tid = threadIdx.x;
    const int lane = tid & 31;
    const int w = tid >> 5;
    const int wm = w * 32;
    const int g = lane >> 2;
    const int qd = lane & 3;

    const size_t hoff = (size_t)bh * LDIM * DDIM;
    const __half* qg = g_q + hoff;
    const __half* kg = g_k + hoff;
    const __half* vg = g_v + hoff;

    {
        const int row = tid;
        const size_t src = (size_t)(q0 + row) * DDIM;
#pragma unroll
        for (int c = 0; c < 8; c++)
            cpasync16(sb + Q_OFF + (u32)((row * STR + c * 8) * 2), qg + src + c * 8);
    }
    attn_issue_kv(sb + ST_BASE, 0, tid, kg, vg);
    cp_commit();

    const int qend = min(q0 + 127, sl - 1);
    const int ntiles = (qend >> 6) + 1;

    float o[2][8][4];
    float mrow[4], lrow[4];
#pragma unroll
    for (int i = 0; i < 2; i++)
#pragma unroll
        for (int j = 0; j < 8; j++)
#pragma unroll
            for (int c = 0; c < 4; c++) o[i][j][c] = 0.f;
#pragma unroll
    for (int i = 0; i < 4; i++) { mrow[i] = -1e30f; lrow[i] = 0.f; }

    for (int t = 0; t < ntiles; t++) {
        if (t + 1 < ntiles) {
            attn_issue_kv(sb + ST_BASE + (u32)((t + 1) & 1) * ST_SZ, (t + 1) << 6,
                          tid, kg, vg);
            cp_commit();
            cp_wait1();
        } else {
            cp_wait0();
        }
        __syncthreads();

        const u32 kb_ = sb + ST_BASE + (u32)(t & 1) * ST_SZ;

        float s[2][8][4];
#pragma unroll
        for (int i = 0; i < 2; i++)
#pragma unroll
            for (int j = 0; j < 8; j++)
#pragma unroll
                for (int c = 0; c < 4; c++) s[i][j][c] = 0.f;

#pragma unroll
        for (int kf = 0; kf < 4; kf++) {
            u32 aq[2][4];
#pragma unroll
            for (int mf = 0; mf < 2; mf++) {
                const u32 ad = sb + Q_OFF + (u32)(((wm + mf * 16 + (lane & 15)) * STR
                                      + kf * 16 + (lane >> 4) * 8) * 2);
                ldsm4(aq[mf][0], aq[mf][1], aq[mf][2], aq[mf][3], ad);
            }
#pragma unroll
            for (int p = 0; p < 4; p++) {
                const u32 kd = kb_ + K_O + (u32)(((p * 16 + (lane & 15)) * STR
                                      + kf * 16 + (lane >> 4) * 8) * 2);
                u32 t0, t1, t2, t3;
                u32 bk0[2], bk1[2];
                ldsm4(t0, t1, t2, t3, kd);
                bk0[0] = t0; bk0[1] = t2; bk1[0] = t1; bk1[1] = t3;
#pragma unroll
                for (int mf = 0; mf < 2; mf++) {
                    mma16816(s[mf][2 * p], aq[mf], bk0);
                    mma16816(s[mf][2 * p + 1], aq[mf], bk1);
                }
            }
        }

        const int kbase = t << 6;
#pragma unroll
        for (int mf = 0; mf < 2; mf++) {
#pragma unroll
            for (int hl = 0; hl < 2; hl++) {
                const int qi = q0 + wm + mf * 16 + g + hl * 8;
                const int idx = mf * 2 + hl;
                float mx = -1e30f;
#pragma unroll
                for (int nf = 0; nf < 8; nf++) {
                    const int c0 = kbase + nf * 8 + qd * 2;
                    float s0 = s[mf][nf][hl * 2];
                    float s1 = s[mf][nf][hl * 2 + 1];
                    if (c0 > qi) s0 = -1e30f;
                    if (c0 + 1 > qi) s1 = -1e30f;
                    s[mf][nf][hl * 2] = s0;
                    s[mf][nf][hl * 2 + 1] = s1;
                    mx = fmaxf(mx, fmaxf(s0, s1));
                }
                mx = fmaxf(mx, __shfl_xor_sync(0xffffffffu, mx, 1));
                mx = fmaxf(mx, __shfl_xor_sync(0xffffffffu, mx, 2));
                const float mnew = fmaxf(mrow[idx], mx);
                const float sc = __expf(mrow[idx] - mnew);
                mrow[idx] = mnew;
                float ps = 0.f;
#pragma unroll
                for (int nf = 0; nf < 8; nf++) {
                    float p0 = __expf(s[mf][nf][hl * 2] - mnew);
                    float p1 = __expf(s[mf][nf][hl * 2 + 1] - mnew);
                    s[mf][nf][hl * 2] = p0;
                    s[mf][nf][hl * 2 + 1] = p1;
                    ps += p0 + p1;
                    o[mf][nf][hl * 2] *= sc;
                    o[mf][nf][hl * 2 + 1] *= sc;
                }
                ps += __shfl_xor_sync(0xffffffffu, ps, 1);
                ps += __shfl_xor_sync(0xffffffffu, ps, 2);
                lrow[idx] = lrow[idx] * sc + ps;
            }
        }

#pragma unroll
        for (int kg2 = 0; kg2 < 4; kg2++) {
            u32 ap[2][4];
#pragma unroll
            for (int mf = 0; mf < 2; mf++) {
                ap[mf][0] = packh(s[mf][2 * kg2][0], s[mf][2 * kg2][1]);
                ap[mf][1] = packh(s[mf][2 * kg2][2], s[mf][2 * kg2][3]);
                ap[mf][2] = packh(s[mf][2 * kg2 + 1][0], s[mf][2 * kg2 + 1][1]);
                ap[mf][3] = packh(s[mf][2 * kg2 + 1][2], s[mf][2 * kg2 + 1][3]);
            }
#pragma unroll
            for (int dp = 0; dp < 4; dp++) {
                const u32 vrow = kb_ + V_O
                    + (u32)(((kg2 * 16 + (lane & 7) + ((lane >> 3) & 1) * 8) * STR
                             + dp * 16 + (lane >> 4) * 8) * 2);
                u32 t0, t1, t2, t3;
                u32 bv0[2], bv1[2];
                ldsm4t(t0, t1, t2, t3, vrow);
                bv0[0] = t0; bv0[1] = t1; bv1[0] = t2; bv1[1] = t3;
#pragma unroll
                for (int mf = 0; mf < 2; mf++) {
                    mma16816(o[mf][2 * dp], ap[mf], bv0);
                    mma16816(o[mf][2 * dp + 1], ap[mf], bv1);
                }
            }
        }
        __syncthreads();
    }

#pragma unroll
    for (int mf = 0; mf < 2; mf++) {
#pragma unroll
        for (int hl = 0; hl < 2; hl++) {
            const int idx = mf * 2 + hl;
            const int qi = q0 + wm + mf * 16 + g + hl * 8;
            if (qi >= sl) continue;
            const float inv = 1.f / lrow[idx];
#pragma unroll
            for (int nf = 0; nf < 8; nf++) {
                const float o0 = o[mf][nf][hl * 2] * inv;
                const float o1 = o[mf][nf][hl * 2 + 1] * inv;
                const size_t e = ((size_t)(b * LDIM + qi) * EDIM)
                               + h * DDIM + nf * 8 + qd * 2;
                ctx[e >> 1] = packh(o0, o1);
            }
        }
    }
}

// ---------------------------------------------------------------------------
extern "C" void kernel_launch(void* const* d_in, const int* in_sizes, int n_in,
                              void* d_out, int out_size)
{
    const float* hs = (const float*)d_in[0];
    const int* sl   = (const int*)d_in[1];
    const float* Wq = (const float*)d_in[2];
    const float* bq = (const float*)d_in[3];
    const float* Wk = (const float*)d_in[4];
    const float* Wv = (const float*)d_in[5];
    const float* bv = (const float*)d_in[6];
    const float* Wo = (const float*)d_in[7];
    const float* bo = (const float*)d_in[8];
    float* out = (float*)d_out;

    __half *q, *k, *v, *hsx, *ctx, *wx;
    float* mv;
    cudaGetSymbolAddress((void**)&q, g_q);
    cudaGetSymbolAddress((void**)&k, g_k);
    cudaGetSymbolAddress((void**)&v, g_v);
    cudaGetSymbolAddress((void**)&hsx, g_hs);
    cudaGetSymbolAddress((void**)&ctx, g_ctx);
    cudaGetSymbolAddress((void**)&wx, g_w);
    cudaGetSymbolAddress((void**)&mv, g_meanv);

    cudaFuncSetAttribute(gemm_h, cudaFuncAttributeMaxDynamicSharedMemorySize, G_SMEM);
    cudaFuncSetAttribute(attn_mma, cudaFuncAttributeMaxDynamicSharedMemorySize, ATT_SMEM);

    conv_f32<<<(MDIM * EDIM / 4 + 255) / 256, 256>>>(hs, hsx, MDIM * EDIM / 4);
    conv_w4<<<4 * WSZ / 4 / 256, 256>>>(Wq, Wk, Wv, Wo, wx);

    // fused QKV: grid (4, 32, 3)
    dim3 g3(EDIM / 256, MDIM / 128, 3);
    gemm_h<<<g3, 512, G_SMEM>>>(hsx, wx, bq, bv, nullptr,
                                (u32*)q, (u32*)k, (u32*)v, 1);

    meanv_kernel<<<BDIM * HDIM, 256>>>(mv);
    fill_invalid<<<MDIM, 256>>>(sl, mv, (u32*)ctx);

    dim3 ga(LDIM / 128, BDIM * HDIM);   // (16, 32)
    attn_mma<<<ga, 128, ATT_SMEM>>>(sl, (u32*)ctx);

    // O projection: grid (4, 32, 1), Wbase = Wo
    dim3 g1(EDIM / 256, MDIM / 128, 1);
    gemm_h<<<g1, 512, G_SMEM>>>(ctx, wx + 3 * (size_t)WSZ, bo, nullptr, out,
                                nullptr, nullptr, nullptr, 0);
}

// round 11
// speedup vs baseline: 8.3638x; 1.0257x over previous
#include <cuda_runtime.h>
#include <cuda_fp16.h>
#include <cstdint>
#include <math.h>

typedef unsigned int u32;

#define BDIM 2
#define LDIM 2048
#define EDIM 1024
#define HDIM 16
#define DDIM 64
#define MDIM (BDIM * LDIM)   // 4096
#define WSZ (EDIM * EDIM)

// ---------------- scratch (device globals; allocation is forbidden) --------
__device__ __half g_q[BDIM * HDIM * LDIM * DDIM];   // [B,H,L,D]
__device__ __half g_k[BDIM * HDIM * LDIM * DDIM];
__device__ __half g_v[BDIM * HDIM * LDIM * DDIM];
__device__ __half g_hs[MDIM * EDIM];
__device__ __half g_ctx[MDIM * EDIM];               // [B,L,E]
__device__ __half g_w[4 * EDIM * EDIM];             // Wq,Wk,Wv,Wo
__device__ float g_mvpart[BDIM * HDIM * 8 * DDIM];  // [B,H,seg,D]
__device__ float g_meanv[BDIM * HDIM * DDIM];       // [B,H,D]

// ---------------------------------------------------------------------------
// helpers
// ---------------------------------------------------------------------------
__device__ __forceinline__ u32 packh(float lo, float hi) {
    u32 d;
    asm("cvt.rn.f16x2.f32 %0, %1, %2;" : "=r"(d) : "f"(hi), "f"(lo));
    return d;
}

__device__ __forceinline__ void cpasync16(u32 dst, const void* src) {
    asm volatile("cp.async.cg.shared.global [%0], [%1], 16;\n" :: "r"(dst), "l"(src));
}
__device__ __forceinline__ void cp_commit() { asm volatile("cp.async.commit_group;\n"); }
__device__ __forceinline__ void cp_wait1() { asm volatile("cp.async.wait_group 1;\n"); }
__device__ __forceinline__ void cp_wait0() { asm volatile("cp.async.wait_group 0;\n"); }

__device__ __forceinline__ void ldsm4(u32& r0, u32& r1, u32& r2, u32& r3, u32 addr) {
    asm volatile("ldmatrix.sync.aligned.m8n8.x4.shared.b16 {%0,%1,%2,%3}, [%4];"
        : "=r"(r0), "=r"(r1), "=r"(r2), "=r"(r3) : "r"(addr));
}
__device__ __forceinline__ void ldsm4t(u32& r0, u32& r1, u32& r2, u32& r3, u32 addr) {
    asm volatile("ldmatrix.sync.aligned.m8n8.x4.trans.shared.b16 {%0,%1,%2,%3}, [%4];"
        : "=r"(r0), "=r"(r1), "=r"(r2), "=r"(r3) : "r"(addr));
}
__device__ __forceinline__ void mma16816(float* acc, const u32* a, const u32* b) {
    asm volatile("mma.sync.aligned.m16n8k16.row.col.f32.f16.f16.f32 "
        "{%0,%1,%2,%3}, {%4,%5,%6,%7}, {%8,%9}, {%0,%1,%2,%3};"
        : "+f"(acc[0]), "+f"(acc[1]), "+f"(acc[2]), "+f"(acc[3])
        : "r"(a[0]), "r"(a[1]), "r"(a[2]), "r"(a[3]), "r"(b[0]), "r"(b[1]));
}

// ---------------------------------------------------------------------------
// Fused fp32 -> fp16 convert for hidden_states + all 4 weight matrices
// ---------------------------------------------------------------------------
#define HS4 (MDIM * EDIM / 4)             // 1048576 float4 groups
#define W4 (WSZ / 4)                      // 262144 per matrix

__global__ __launch_bounds__(256)
void conv_all(const float* __restrict__ hs,
              const float* __restrict__ w0, const float* __restrict__ w1,
              const float* __restrict__ w2, const float* __restrict__ w3,
              __half* __restrict__ ohs, __half* __restrict__ ow)
{
    int i = blockIdx.x * blockDim.x + threadIdx.x;
    const float* src;
    uint2* dst;
    int j;
    if (i < HS4) {
        src = hs; j = i; dst = (uint2*)ohs + i;
    } else {
        const int t = i - HS4;
        const int m = t / W4;
        j = t - m * W4;
        src = (m == 0) ? w0 : (m == 1) ? w1 : (m == 2) ? w2 : w3;
        dst = (uint2*)ow + t;
    }
    float4 v = ((const float4*)src)[j];
    uint2 hv;
    hv.x = packh(v.x, v.y);
    hv.y = packh(v.z, v.w);
    *dst = hv;
}

// ---------------------------------------------------------------------------
// mean(V): two-phase deterministic reduction
// ---------------------------------------------------------------------------
__global__ __launch_bounds__(256)
void meanv_part(float* __restrict__ mvp)
{
    __shared__ float red[256];
    const int bh = blockIdx.x;            // 0..31
    const int seg = blockIdx.y;           // 0..7
    const int tid = threadIdx.x;
    const int d = tid & 63;
    const int sub = tid >> 6;             // 0..3
    const __half* vb = g_v + (size_t)bh * LDIM * DDIM;
    const int l0 = seg * 256 + sub * 64;
    float s = 0.f;
#pragma unroll 4
    for (int l = l0; l < l0 + 64; l++)
        s += __half2float(vb[(size_t)l * DDIM + d]);
    red[tid] = s;
    __syncthreads();
    if (tid < 64)
        mvp[(size_t)(bh * 8 + seg) * DDIM + d]
            = red[d] + red[64 + d] + red[128 + d] + red[192 + d];
}

__global__ __launch_bounds__(64)
void meanv_final(const float* __restrict__ mvp, float* __restrict__ mv)
{
    const int bh = blockIdx.x;
    const int d = threadIdx.x;
    float s = 0.f;
#pragma unroll
    for (int seg = 0; seg < 8; seg++)
        s += mvp[(size_t)(bh * 8 + seg) * DDIM + d];
    mv[bh * DDIM + d] = s * (1.0f / 2048.0f);
}

// ---------------------------------------------------------------------------
// Fill ctx rows for invalid queries (l >= seq_len[b]) with mean(V)
// ---------------------------------------------------------------------------
__global__ __launch_bounds__(256)
void fill_invalid(const int* __restrict__ seq_len, const float* __restrict__ mv,
                  u32* __restrict__ ctx)
{
    const int r = blockIdx.x;
    const int b = r >> 11;
    const int l = r & (LDIM - 1);
    if (l < seq_len[b]) return;
    const int tid = threadIdx.x;
#pragma unroll
    for (int it = 0; it < 2; it++) {
        const int idx = tid + it * 256;
        const int col = idx * 2;
        ctx[(size_t)r * 512 + idx] = packh(mv[b * 1024 + col], mv[b * 1024 + col + 1]);
    }
}

// ---------------------------------------------------------------------------
// fp16 tensor-core NT GEMM, fused-QKV capable (round-10 validated).
// Tile 128(M) x 256(N), BK=64, 3-stage cp.async, 512 thr / 16 warps (4Mx4N).
// ---------------------------------------------------------------------------
#define SSTR 72                           // smem row stride in fp16 (144 B)
#define A_ARR (128 * SSTR * 2)            // 18432 B
#define B_ARR (256 * SSTR * 2)            // 36864 B
#define O_A 0
#define O_B A_ARR
#define STG (A_ARR + B_ARR)               // 55296 B
#define G_SMEM (3 * STG)                  // 165888 B

__device__ __forceinline__ void g_issue(
    u32 sbase, int s, int k0, int tid,
    const __half* A, const __half* B, int bm, int bn)
{
    const u32 st = sbase + (u32)(s % 3) * STG;
#pragma unroll
    for (int i = 0; i < 2; i++) {
        const int c = tid + i * 512;
        const int row = c >> 3, ch = c & 7;
        const u32 so = (u32)(row * (SSTR * 2) + ch * 16);
        cpasync16(st + O_A + so, A + (size_t)(bm + row) * EDIM + k0 + ch * 8);
    }
#pragma unroll
    for (int i = 0; i < 4; i++) {
        const int c = tid + i * 512;
        const int row = c >> 3, ch = c & 7;
        const u32 so = (u32)(row * (SSTR * 2) + ch * 16);
        cpasync16(st + O_B + so, B + (size_t)(bn + row) * EDIM + k0 + ch * 8);
    }
    cp_commit();
}

extern "C" __global__ __launch_bounds__(512, 1)
void gemm_h(const __half* __restrict__ Ag, const __half* __restrict__ Wbase,
            const float* __restrict__ b0, const float* __restrict__ b2,
            float* __restrict__ out,
            u32* __restrict__ o0, u32* __restrict__ o1, u32* __restrict__ o2,
            int fused)
{
    extern __shared__ __align__(16) char dynsmem[];
    const u32 sbase = (u32)__cvta_generic_to_shared(dynsmem);
    const int bm = blockIdx.y * 128;
    const int bn = blockIdx.x * 256;
    const int z = blockIdx.z;
    const int tid = threadIdx.x;
    const int lane = tid & 31;
    const int wid = tid >> 5;
    const int wm = (wid & 3) * 32;
    const int wn = (wid >> 2) * 64;

    const __half* Bg = Wbase + (size_t)z * WSZ;
    const float* bias;
    float alpha;
    u32* outq;
    if (fused) {
        bias = (z == 0) ? b0 : ((z == 2) ? b2 : nullptr);
        alpha = (z == 0) ? 0.125f : 1.0f;
        outq = (z == 0) ? o0 : ((z == 1) ? o1 : o2);
    } else {
        bias = b0; alpha = 1.0f; outq = nullptr;
    }

    float acc[2][8][4];
#pragma unroll
    for (int i = 0; i < 2; i++)
#pragma unroll
        for (int j = 0; j < 8; j++)
#pragma unroll
            for (int c = 0; c < 4; c++) acc[i][j][c] = 0.f;

    const int lrA = wm + (lane & 15);
    const int lrB = wn + (lane & 15);
    const int lcol = (lane >> 4) * 8;

    const int NIT = EDIM / 64;            // 16
    g_issue(sbase, 0, 0, tid, Ag, Bg, bm, bn);
    g_issue(sbase, 1, 64, tid, Ag, Bg, bm, bn);

    for (int it = 0; it < NIT; it++) {
        if (it + 1 < NIT) cp_wait1(); else cp_wait0();
        __syncthreads();
        if (it + 2 < NIT)
            g_issue(sbase, it + 2, (it + 2) * 64, tid, Ag, Bg, bm, bn);

        const u32 st = sbase + (u32)(it % 3) * STG;
#pragma unroll
        for (int ks = 0; ks < 4; ks++) {
            const int kb = ks * 16;
            u32 ah[2][4];
#pragma unroll
            for (int mt = 0; mt < 2; mt++) {
                const u32 ad = st + O_A + (u32)((lrA + mt * 16) * SSTR + kb + lcol) * 2;
                ldsm4(ah[mt][0], ah[mt][1], ah[mt][2], ah[mt][3], ad);
            }
#pragma unroll
            for (int p = 0; p < 4; p++) {
                const u32 bd = st + O_B + (u32)((lrB + p * 16) * SSTR + kb + lcol) * 2;
                u32 t0, t1, t2, t3;
                u32 b0r[2], b1r[2];
                ldsm4(t0, t1, t2, t3, bd);
                b0r[0] = t0; b0r[1] = t2; b1r[0] = t1; b1r[1] = t3;
#pragma unroll
                for (int mt = 0; mt < 2; mt++) {
                    mma16816(acc[mt][2 * p], ah[mt], b0r);
                    mma16816(acc[mt][2 * p + 1], ah[mt], b1r);
                }
            }
        }
        __syncthreads();
    }

    // ----- epilogue -----
#pragma unroll
    for (int mt = 0; mt < 2; mt++) {
#pragma unroll
        for (int nt = 0; nt < 8; nt++) {
#pragma unroll
            for (int r = 0; r < 2; r++) {
                const int row = bm + wm + mt * 16 + (lane >> 2) + r * 8;
                const int col0 = bn + wn + nt * 8 + (lane & 3) * 2;
                float v0 = acc[mt][nt][r * 2 + 0];
                float v1 = acc[mt][nt][r * 2 + 1];
                if (bias) { v0 += bias[col0]; v1 += bias[col0 + 1]; }
                v0 *= alpha; v1 *= alpha;
                const int b = row >> 11;
                const int l = row & (LDIM - 1);
                if (fused) {
                    const int h = col0 >> 6;
                    const int d = col0 & (DDIM - 1);
                    const size_t e = (((size_t)(b * HDIM + h) * LDIM) + l) * DDIM + d;
                    outq[e >> 1] = packh(v0, v1);
                } else {
                    out[(size_t)row * EDIM + col0] = v0;
                    out[(size_t)row * EDIM + col0 + 1] = v1;
                }
            }
        }
    }
}

// ---------------------------------------------------------------------------
// fp16 tensor-core flash attention, valid rows only (round-9 validated).
// ---------------------------------------------------------------------------
#define STR 72
#define Q_OFF 0
#define ST_BASE (128 * STR * 2)           // 18432
#define KT_B (64 * STR * 2)               // 9216
#define K_O 0
#define V_O KT_B
#define ST_SZ (2 * KT_B)                  // 18432
#define ATT_SMEM (ST_BASE + 2 * ST_SZ)    // 55296

__device__ __forceinline__ void attn_issue_kv(u32 base, int kbase, int tid,
                                              const __half* kg, const __half* vg)
{
    const int row = tid >> 1;
    const int c0 = (tid & 1) * 4;
#pragma unroll
    for (int c = 0; c < 4; c++) {
        const int ch = c0 + c;
        const u32 off = (u32)((row * STR + ch * 8) * 2);
        const size_t src = (size_t)(kbase + row) * DDIM + ch * 8;
        cpasync16(base + K_O + off, kg + src);
        cpasync16(base + V_O + off, vg + src);
    }
}

__global__ __launch_bounds__(128)
void attn_mma(const int* __restrict__ seq_len, u32* __restrict__ ctx)
{
    extern __shared__ __align__(16) char sm[];
    const u32 sb = (u32)__cvta_generic_to_shared(sm);
    const int bh = blockIdx.y;
    const int b = bh >> 4;
    const int h = bh & (HDIM - 1);
    const int qt = (int)gridDim.x - 1 - (int)blockIdx.x;
    const int q0 = qt * 128;
    const int sl = seq_len[b];
    if (q0 >= sl) return;

    const int tid = threadIdx.x;
    const int lane = tid & 31;
    const int w = tid >> 5;
    const int wm = w * 32;
    const int g = lane >> 2;
    const int qd = lane & 3;

    const size_t hoff = (size_t)bh * LDIM * DDIM;
    const __half* qg = g_q + hoff;
    const __half* kg = g_k + hoff;
    const __half* vg = g_v + hoff;

    {
        const int row = tid;
        const size_t src = (size_t)(q0 + row) * DDIM;
#pragma unroll
        for (int c = 0; c < 8; c++)
            cpasync16(sb + Q_OFF + (u32)((row * STR + c * 8) * 2), qg + src + c * 8);
    }
    attn_issue_kv(sb + ST_BASE, 0, tid, kg, vg);
    cp_commit();

    const int qend = min(q0 + 127, sl - 1);
    const int ntiles = (qend >> 6) + 1;

    float o[2][8][4];
    float mrow[4], lrow[4];
#pragma unroll
    for (int i = 0; i < 2; i++)
#pragma unroll
        for (int j = 0; j < 8; j++)
#pragma unroll
            for (int c = 0; c < 4; c++) o[i][j][c] = 0.f;
#pragma unroll
    for (int i = 0; i < 4; i++) { mrow[i] = -1e30f; lrow[i] = 0.f; }

    for (int t = 0; t < ntiles; t++) {
        if (t + 1 < ntiles) {
            attn_issue_kv(sb + ST_BASE + (u32)((t + 1) & 1) * ST_SZ, (t + 1) << 6,
                          tid, kg, vg);
            cp_commit();
            cp_wait1();
        } else {
            cp_wait0();
        }
        __syncthreads();

        const u32 kb_ = sb + ST_BASE + (u32)(t & 1) * ST_SZ;

        float s[2][8][4];
#pragma unroll
        for (int i = 0; i < 2; i++)
#pragma unroll
            for (int j = 0; j < 8; j++)
#pragma unroll
                for (int c = 0; c < 4; c++) s[i][j][c] = 0.f;

#pragma unroll
        for (int kf = 0; kf < 4; kf++) {
            u32 aq[2][4];
#pragma unroll
            for (int mf = 0; mf < 2; mf++) {
                const u32 ad = sb + Q_OFF + (u32)(((wm + mf * 16 + (lane & 15)) * STR
                                      + kf * 16 + (lane >> 4) * 8) * 2);
                ldsm4(aq[mf][0], aq[mf][1], aq[mf][2], aq[mf][3], ad);
            }
#pragma unroll
            for (int p = 0; p < 4; p++) {
                const u32 kd = kb_ + K_O + (u32)(((p * 16 + (lane & 15)) * STR
                                      + kf * 16 + (lane >> 4) * 8) * 2);
                u32 t0, t1, t2, t3;
                u32 bk0[2], bk1[2];
                ldsm4(t0, t1, t2, t3, kd);
                bk0[0] = t0; bk0[1] = t2; bk1[0] = t1; bk1[1] = t3;
#pragma unroll
                for (int mf = 0; mf < 2; mf++) {
                    mma16816(s[mf][2 * p], aq[mf], bk0);
                    mma16816(s[mf][2 * p + 1], aq[mf], bk1);
                }
            }
        }

        const int kbase = t << 6;
#pragma unroll
        for (int mf = 0; mf < 2; mf++) {
#pragma unroll
            for (int hl = 0; hl < 2; hl++) {
                const int qi = q0 + wm + mf * 16 + g + hl * 8;
                const int idx = mf * 2 + hl;
                float mx = -1e30f;
#pragma unroll
                for (int nf = 0; nf < 8; nf++) {
                    const int c0 = kbase + nf * 8 + qd * 2;
                    float s0 = s[mf][nf][hl * 2];
                    float s1 = s[mf][nf][hl * 2 + 1];
                    if (c0 > qi) s0 = -1e30f;
                    if (c0 + 1 > qi) s1 = -1e30f;
                    s[mf][nf][hl * 2] = s0;
                    s[mf][nf][hl * 2 + 1] = s1;
                    mx = fmaxf(mx, fmaxf(s0, s1));
                }
                mx = fmaxf(mx, __shfl_xor_sync(0xffffffffu, mx, 1));
                mx = fmaxf(mx, __shfl_xor_sync(0xffffffffu, mx, 2));
                const float mnew = fmaxf(mrow[idx], mx);
                const float sc = __expf(mrow[idx] - mnew);
                mrow[idx] = mnew;
                float ps = 0.f;
#pragma unroll
                for (int nf = 0; nf < 8; nf++) {
                    float p0 = __expf(s[mf][nf][hl * 2] - mnew);
                    float p1 = __expf(s[mf][nf][hl * 2 + 1] - mnew);
                    s[mf][nf][hl * 2] = p0;
                    s[mf][nf][hl * 2 + 1] = p1;
                    ps += p0 + p1;
                    o[mf][nf][hl * 2] *= sc;
                    o[mf][nf][hl * 2 + 1] *= sc;
                }
                ps += __shfl_xor_sync(0xffffffffu, ps, 1);
                ps += __shfl_xor_sync(0xffffffffu, ps, 2);
                lrow[idx] = lrow[idx] * sc + ps;
            }
        }

#pragma unroll
        for (int kg2 = 0; kg2 < 4; kg2++) {
            u32 ap[2][4];
#pragma unroll
            for (int mf = 0; mf < 2; mf++) {
                ap[mf][0] = packh(s[mf][2 * kg2][0], s[mf][2 * kg2][1]);
                ap[mf][1] = packh(s[mf][2 * kg2][2], s[mf][2 * kg2][3]);
                ap[mf][2] = packh(s[mf][2 * kg2 + 1][0], s[mf][2 * kg2 + 1][1]);
                ap[mf][3] = packh(s[mf][2 * kg2 + 1][2], s[mf][2 * kg2 + 1][3]);
            }
#pragma unroll
            for (int dp = 0; dp < 4; dp++) {
                const u32 vrow = kb_ + V_O
                    + (u32)(((kg2 * 16 + (lane & 7) + ((lane >> 3) & 1) * 8) * STR
                             + dp * 16 + (lane >> 4) * 8) * 2);
                u32 t0, t1, t2, t3;
                u32 bv0[2], bv1[2];
                ldsm4t(t0, t1, t2, t3, vrow);
                bv0[0] = t0; bv0[1] = t1; bv1[0] = t2; bv1[1] = t3;
#pragma unroll
                for (int mf = 0; mf < 2; mf++) {
                    mma16816(o[mf][2 * dp], ap[mf], bv0);
                    mma16816(o[mf][2 * dp + 1], ap[mf], bv1);
                }
            }
        }
        __syncthreads();
    }

#pragma unroll
    for (int mf = 0; mf < 2; mf++) {
#pragma unroll
        for (int hl = 0; hl < 2; hl++) {
            const int idx = mf * 2 + hl;
            const int qi = q0 + wm + mf * 16 + g + hl * 8;
            if (qi >= sl) continue;
            const float inv = 1.f / lrow[idx];
#pragma unroll
            for (int nf = 0; nf < 8; nf++) {
                const float o0 = o[mf][nf][hl * 2] * inv;
                const float o1 = o[mf][nf][hl * 2 + 1] * inv;
                const size_t e = ((size_t)(b * LDIM + qi) * EDIM)
                               + h * DDIM + nf * 8 + qd * 2;
                ctx[e >> 1] = packh(o0, o1);
            }
        }
    }
}

// ---------------------------------------------------------------------------
extern "C" void kernel_launch(void* const* d_in, const int* in_sizes, int n_in,
                              void* d_out, int out_size)
{
    const float* hs = (const float*)d_in[0];
    const int* sl   = (const int*)d_in[1];
    const float* Wq = (const float*)d_in[2];
    const float* bq = (const float*)d_in[3];
    const float* Wk = (const float*)d_in[4];
    const float* Wv = (const float*)d_in[5];
    const float* bv = (const float*)d_in[6];
    const float* Wo = (const float*)d_in[7];
    const float* bo = (const float*)d_in[8];
    float* out = (float*)d_out;

    __half *q, *k, *v, *hsx, *ctx, *wx;
    float *mv, *mvp;
    cudaGetSymbolAddress((void**)&q, g_q);
    cudaGetSymbolAddress((void**)&k, g_k);
    cudaGetSymbolAddress((void**)&v, g_v);
    cudaGetSymbolAddress((void**)&hsx, g_hs);
    cudaGetSymbolAddress((void**)&ctx, g_ctx);
    cudaGetSymbolAddress((void**)&wx, g_w);
    cudaGetSymbolAddress((void**)&mv, g_meanv);
    cudaGetSymbolAddress((void**)&mvp, g_mvpart);

    cudaFuncSetAttribute(gemm_h, cudaFuncAttributeMaxDynamicSharedMemorySize, G_SMEM);
    cudaFuncSetAttribute(attn_mma, cudaFuncAttributeMaxDynamicSharedMemorySize, ATT_SMEM);

    // fused conversion: hs + 4 weight matrices, one launch
    conv_all<<<(HS4 + 4 * W4) / 256, 256>>>(hs, Wq, Wk, Wv, Wo, hsx, wx);

    // fused QKV: grid (4, 32, 3)
    dim3 g3(EDIM / 256, MDIM / 128, 3);
    gemm_h<<<g3, 512, G_SMEM>>>(hsx, wx, bq, bv, nullptr,
                                (u32*)q, (u32*)k, (u32*)v, 1);

    dim3 gmv(BDIM * HDIM, 8);
    meanv_part<<<gmv, 256>>>(mvp);
    meanv_final<<<BDIM * HDIM, 64>>>(mvp, mv);
    fill_invalid<<<MDIM, 256>>>(sl, mv, (u32*)ctx);

    dim3 ga(LDIM / 128, BDIM * HDIM);   // (16, 32)
    attn_mma<<<ga, 128, ATT_SMEM>>>(sl, (u32*)ctx);

    // O projection: grid (4, 32, 1), Wbase = Wo
    dim3 g1(EDIM / 256, MDIM / 128, 1);
    gemm_h<<<g1, 512, G_SMEM>>>(ctx, wx + 3 * (size_t)WSZ, bo, nullptr, out,
                                nullptr, nullptr, nullptr, 0);
}